// round 1
// baseline (speedup 1.0000x reference)
#include <cuda_runtime.h>
#include <cuda_bf16.h>
#include <math.h>

// Problem dims (fixed by reference)
#define NN   20000
#define EE   50000
#define FIN  16
#define DD   64
#define BB   128
#define GDIM 192          // 3*D  (GRU gates)
#define LG   256          // 4*D  (LSTM gates)
#define WE_COLS 4096      // D*D

// ---------------- scratch (device globals; no allocation allowed) ----------
__device__ float    g_x[NN * DD];          // node features: out == h
__device__ float    g_hidden[EE * 128];    // edge MLP hidden
__device__ float    g_We[(size_t)EE * WE_COLS];   // 819 MB edge weight matrices
__device__ float    g_agg[NN * DD];
__device__ float    g_m[NN * DD];
__device__ float    g_gi[NN * GDIM];
__device__ float    g_gh[NN * GDIM];
__device__ float    g_deg[NN];
__device__ float    g_e[NN];
__device__ float    g_a[NN];
__device__ unsigned g_emax[BB];
__device__ float    g_asum[BB];
__device__ float    g_r[BB * DD];
__device__ float    g_hh[BB * DD];
__device__ float    g_cc[BB * DD];
__device__ float    g_qstar[BB * 2 * DD];

// ---------------- helpers ----------------
__device__ __forceinline__ float sigmoidf_(float x) { return 1.0f / (1.0f + expf(-x)); }

// order-preserving float<->uint encoding for atomicMax on floats
__device__ __forceinline__ unsigned fenc(float f) {
    unsigned u = __float_as_uint(f);
    return (u & 0x80000000u) ? ~u : (u | 0x80000000u);
}
__device__ __forceinline__ float fdec(unsigned u) {
    return (u & 0x80000000u) ? __uint_as_float(u & 0x7fffffffu) : __uint_as_float(~u);
}

// ---------------- generic tiled GEMM: C[M,N] = A[M,K] @ B[N,K]^T + bias ----
template<bool RELU>
__global__ void gemm_abt(const float* __restrict__ A, const float* __restrict__ B,
                         const float* __restrict__ bias, float* __restrict__ C,
                         int M, int N, int K) {
    __shared__ float As[16][65];
    __shared__ float Bs[16][65];
    int tid = threadIdx.x;
    int tx = tid & 15, ty = tid >> 4;
    int rowBase = blockIdx.y * 64;
    int colBase = blockIdx.x * 64;
    float acc[4][4] = {};
    for (int k0 = 0; k0 < K; k0 += 16) {
#pragma unroll
        for (int i = 0; i < 4; i++) {
            int e = tid + i * 256;
            int m = e >> 4, kk = e & 15;
            int r = rowBase + m, k = k0 + kk;
            As[kk][m] = (r < M && k < K) ? A[(size_t)r * K + k] : 0.f;
        }
#pragma unroll
        for (int i = 0; i < 4; i++) {
            int e = tid + i * 256;
            int n = e >> 4, kk = e & 15;
            int c = colBase + n, k = k0 + kk;
            Bs[kk][n] = (c < N && k < K) ? B[(size_t)c * K + k] : 0.f;
        }
        __syncthreads();
#pragma unroll
        for (int kk = 0; kk < 16; kk++) {
            float ra[4], rb[4];
#pragma unroll
            for (int i = 0; i < 4; i++) ra[i] = As[kk][ty * 4 + i];
#pragma unroll
            for (int j = 0; j < 4; j++) rb[j] = Bs[kk][tx * 4 + j];
#pragma unroll
            for (int i = 0; i < 4; i++)
#pragma unroll
                for (int j = 0; j < 4; j++) acc[i][j] += ra[i] * rb[j];
        }
        __syncthreads();
    }
#pragma unroll
    for (int i = 0; i < 4; i++) {
        int r = rowBase + ty * 4 + i;
        if (r >= M) continue;
#pragma unroll
        for (int j = 0; j < 4; j++) {
            int c = colBase + tx * 4 + j;
            if (c >= N) continue;
            float v = acc[i][j] + bias[c];
            if (RELU) v = fmaxf(v, 0.f);
            C[(size_t)r * N + c] = v;
        }
    }
}

// ---------------- small kernels -------------------------------------------
__global__ void zero_f(float* p, int n) {
    int i = blockIdx.x * blockDim.x + threadIdx.x;
    if (i < n) p[i] = 0.f;
}

__global__ void mlp1_kernel(const float* __restrict__ ea, const float* __restrict__ w1,
                            const float* __restrict__ b1) {
    int idx = blockIdx.x * blockDim.x + threadIdx.x;
    if (idx >= EE * 128) return;
    int e = idx >> 7, h = idx & 127;
    float acc = b1[h];
    const float* row = ea + e * 5;
    const float* w = w1 + h * 5;
#pragma unroll
    for (int k = 0; k < 5; k++) acc += row[k] * w[k];
    g_hidden[idx] = fmaxf(acc, 0.f);
}

__global__ void deg_kernel(const int* __restrict__ ei) {
    int e = blockIdx.x * blockDim.x + threadIdx.x;
    if (e >= EE) return;
    atomicAdd(&g_deg[ei[EE + e]], 1.0f);
}

// one block (64 threads) per edge: msg = x[src] @ W_e, scatter-add to dst
__global__ void msg_kernel(const int* __restrict__ ei) {
    int e = blockIdx.x;
    int o = threadIdx.x;
    __shared__ float xs[DD];
    int src = ei[e];
    int dst = ei[EE + e];
    xs[o] = g_x[src * DD + o];
    __syncthreads();
    const float* w = g_We + (size_t)e * WE_COLS;
    float acc = 0.f;
#pragma unroll
    for (int d = 0; d < DD; d++) acc += xs[d] * w[d * DD + o];
    atomicAdd(&g_agg[dst * DD + o], acc);
}

__global__ void m_kernel(const float* __restrict__ conv_b) {
    int idx = blockIdx.x * blockDim.x + threadIdx.x;
    if (idx >= NN * DD) return;
    int n = idx >> 6, d = idx & 63;
    float dv = fmaxf(g_deg[n], 1.0f);
    g_m[idx] = fmaxf(g_agg[idx] / dv + conv_b[d], 0.f);
}

__global__ void gru_elem_kernel() {
    int idx = blockIdx.x * blockDim.x + threadIdx.x;
    if (idx >= NN * DD) return;
    int n = idx >> 6, j = idx & 63;
    const float* gi = g_gi + n * GDIM;
    const float* gh = g_gh + n * GDIM;
    float r = sigmoidf_(gi[j] + gh[j]);
    float z = sigmoidf_(gi[64 + j] + gh[64 + j]);
    float nn = tanhf(gi[128 + j] + r * gh[128 + j]);
    float h = g_x[idx];
    g_x[idx] = (1.f - z) * nn + z * h;
}

__global__ void s2s_init_kernel() {
    int i = blockIdx.x * blockDim.x + threadIdx.x;
    if (i < BB * 2 * DD) g_qstar[i] = 0.f;
    if (i < BB * DD) { g_hh[i] = 0.f; g_cc[i] = 0.f; }
}

__global__ void attn_init_kernel() {
    int i = blockIdx.x * blockDim.x + threadIdx.x;
    if (i < BB * DD) g_r[i] = 0.f;
    if (i < BB) { g_emax[i] = 0u; g_asum[i] = 0.f; }
}

// one block (256 threads) per graph: LSTM cell
__global__ void lstm_kernel(const float* __restrict__ w_ih, const float* __restrict__ w_hh,
                            const float* __restrict__ b_ih, const float* __restrict__ b_hh) {
    int b = blockIdx.x, j = threadIdx.x;
    __shared__ float qs[2 * DD];
    __shared__ float hs[DD];
    __shared__ float g[LG];
    if (j < 2 * DD) qs[j] = g_qstar[b * 2 * DD + j];
    else if (j < 2 * DD + DD) hs[j - 2 * DD] = g_hh[b * DD + (j - 2 * DD)];
    __syncthreads();
    float acc = b_ih[j] + b_hh[j];
    const float* wi = w_ih + j * 2 * DD;
#pragma unroll 8
    for (int k = 0; k < 2 * DD; k++) acc += qs[k] * wi[k];
    const float* wh = w_hh + j * DD;
#pragma unroll 8
    for (int k = 0; k < DD; k++) acc += hs[k] * wh[k];
    g[j] = acc;
    __syncthreads();
    if (j < DD) {
        float ig = sigmoidf_(g[j]);
        float fg = sigmoidf_(g[DD + j]);
        float gg = tanhf(g[2 * DD + j]);
        float og = sigmoidf_(g[3 * DD + j]);
        float cn = fg * g_cc[b * DD + j] + ig * gg;
        float hn = og * tanhf(cn);
        g_cc[b * DD + j] = cn;
        g_hh[b * DD + j] = hn;
    }
}

__global__ void e_kernel(const int* __restrict__ batch) {
    int n = blockIdx.x * blockDim.x + threadIdx.x;
    if (n >= NN) return;
    int b = batch[n];
    const float4* xr = (const float4*)(g_x + n * DD);
    const float4* qr = (const float4*)(g_hh + b * DD);
    float acc = 0.f;
#pragma unroll
    for (int i = 0; i < DD / 4; i++) {
        float4 a = xr[i], q = qr[i];
        acc += a.x * q.x + a.y * q.y + a.z * q.z + a.w * q.w;
    }
    g_e[n] = acc;
    atomicMax(&g_emax[b], fenc(acc));
}

__global__ void a_kernel(const int* __restrict__ batch) {
    int n = blockIdx.x * blockDim.x + threadIdx.x;
    if (n >= NN) return;
    int b = batch[n];
    float a = expf(g_e[n] - fdec(g_emax[b]));
    g_a[n] = a;
    atomicAdd(&g_asum[b], a);
}

__global__ void r_kernel(const int* __restrict__ batch) {
    int idx = blockIdx.x * blockDim.x + threadIdx.x;
    if (idx >= NN * (DD / 4)) return;
    int n = idx >> 4, c = idx & 15;
    int b = batch[n];
    float coef = g_a[n] / g_asum[b];
    float4 v = ((const float4*)(g_x + n * DD))[c];
    float* rp = g_r + b * DD + c * 4;
    atomicAdd(rp + 0, coef * v.x);
    atomicAdd(rp + 1, coef * v.y);
    atomicAdd(rp + 2, coef * v.z);
    atomicAdd(rp + 3, coef * v.w);
}

__global__ void qstar_kernel() {
    int idx = blockIdx.x * blockDim.x + threadIdx.x;
    if (idx >= BB * DD) return;
    int b = idx >> 6, j = idx & 63;
    g_qstar[b * 2 * DD + j] = g_hh[idx];
    g_qstar[b * 2 * DD + DD + j] = g_r[idx];
}

__global__ void out_kernel(float* __restrict__ out) {
    int i = blockIdx.x * blockDim.x + threadIdx.x;
    if (i < BB * 2 * DD) out[i] = g_qstar[i];
}

// ---------------- launch --------------------------------------------------
extern "C" void kernel_launch(void* const* d_in, const int* in_sizes, int n_in,
                              void* d_out, int out_size) {
    const float* x       = (const float*)d_in[0];
    const int*   ei      = (const int*)  d_in[1];
    const float* ea      = (const float*)d_in[2];
    const int*   batch   = (const int*)  d_in[3];
    const float* lin0_w  = (const float*)d_in[4];
    const float* lin0_b  = (const float*)d_in[5];
    const float* mlp_w1  = (const float*)d_in[6];
    const float* mlp_b1  = (const float*)d_in[7];
    const float* mlp_w2  = (const float*)d_in[8];
    const float* mlp_b2  = (const float*)d_in[9];
    const float* conv_b  = (const float*)d_in[10];
    const float* gw_ih   = (const float*)d_in[11];
    const float* gw_hh   = (const float*)d_in[12];
    const float* gb_ih   = (const float*)d_in[13];
    const float* gb_hh   = (const float*)d_in[14];
    const float* lw_ih   = (const float*)d_in[15];
    const float* lw_hh   = (const float*)d_in[16];
    const float* lb_ih   = (const float*)d_in[17];
    const float* lb_hh   = (const float*)d_in[18];
    float* out = (float*)d_out;

    float *p_x, *p_hidden, *p_We, *p_agg, *p_m, *p_gi, *p_gh, *p_deg;
    cudaGetSymbolAddress((void**)&p_x, g_x);
    cudaGetSymbolAddress((void**)&p_hidden, g_hidden);
    cudaGetSymbolAddress((void**)&p_We, g_We);
    cudaGetSymbolAddress((void**)&p_agg, g_agg);
    cudaGetSymbolAddress((void**)&p_m, g_m);
    cudaGetSymbolAddress((void**)&p_gi, g_gi);
    cudaGetSymbolAddress((void**)&p_gh, g_gh);
    cudaGetSymbolAddress((void**)&p_deg, g_deg);

    const int T = 256;
    // lin0: x @ lin0_w^T + b, relu -> g_x   [20000, 64]
    gemm_abt<true><<<dim3(1, (NN + 63) / 64), T>>>(x, lin0_w, lin0_b, p_x, NN, DD, FIN);

    // edge MLP
    mlp1_kernel<<<(EE * 128 + T - 1) / T, T>>>(ea, mlp_w1, mlp_b1);
    gemm_abt<false><<<dim3(WE_COLS / 64, (EE + 63) / 64), T>>>(p_hidden, mlp_w2, mlp_b2,
                                                               p_We, EE, WE_COLS, 128);

    // degree counts
    zero_f<<<(NN + T - 1) / T, T>>>(p_deg, NN);
    deg_kernel<<<(EE + T - 1) / T, T>>>(ei);

    // 3 message-passing + GRU iterations
    for (int it = 0; it < 3; it++) {
        zero_f<<<(NN * DD + T - 1) / T, T>>>(p_agg, NN * DD);
        msg_kernel<<<EE, DD>>>(ei);
        m_kernel<<<(NN * DD + T - 1) / T, T>>>(conv_b);
        gemm_abt<false><<<dim3(GDIM / 64, (NN + 63) / 64), T>>>(p_m, gw_ih, gb_ih, p_gi, NN, GDIM, DD);
        gemm_abt<false><<<dim3(GDIM / 64, (NN + 63) / 64), T>>>(p_x, gw_hh, gb_hh, p_gh, NN, GDIM, DD);
        gru_elem_kernel<<<(NN * DD + T - 1) / T, T>>>();
    }

    // Set2Set
    s2s_init_kernel<<<(BB * 2 * DD + T - 1) / T, T>>>();
    for (int s = 0; s < 3; s++) {
        lstm_kernel<<<BB, LG>>>(lw_ih, lw_hh, lb_ih, lb_hh);
        attn_init_kernel<<<(BB * DD + T - 1) / T, T>>>();
        e_kernel<<<(NN + T - 1) / T, T>>>(batch);
        a_kernel<<<(NN + T - 1) / T, T>>>(batch);
        r_kernel<<<(NN * (DD / 4) + T - 1) / T, T>>>(batch);
        qstar_kernel<<<(BB * DD + T - 1) / T, T>>>();
    }
    out_kernel<<<(BB * 2 * DD + T - 1) / T, T>>>(out);
}

// round 4
// speedup vs baseline: 1.9716x; 1.9716x over previous
#include <cuda_runtime.h>
#include <cuda_bf16.h>
#include <math.h>
#include <stdint.h>

// Problem dims
#define NN   20000
#define EE   50000
#define EPAD 50048          // 391 * 128
#define FIN  16
#define DD   64
#define BB   128
#define GDIM 192
#define LG   256
#define WE_COLS 4096

// ---------------- device scratch ----------------
__device__ float         g_x[NN * DD];
__device__ __nv_bfloat16 g_Ahi[(size_t)EPAD * 128];
__device__ __nv_bfloat16 g_Alo[(size_t)EPAD * 128];
__device__ __nv_bfloat16 g_Bhi[WE_COLS * 128];
__device__ __nv_bfloat16 g_Blo[WE_COLS * 128];
__device__ float         g_We[(size_t)EPAD * WE_COLS];   // 820 MB
__device__ float         g_agg[NN * DD];
__device__ float         g_m[NN * DD];
__device__ float         g_gi[NN * GDIM];
__device__ float         g_gh[NN * GDIM];
__device__ float         g_deg[NN];
__device__ float         g_e[NN];
__device__ float         g_a[NN];
__device__ unsigned      g_emax[BB];
__device__ float         g_asum[BB];
__device__ float         g_r[BB * DD];
__device__ float         g_hh[BB * DD];
__device__ float         g_cc[BB * DD];
__device__ float         g_qstar[BB * 2 * DD];

__device__ __forceinline__ float sigmoidf_(float x) { return 1.0f / (1.0f + expf(-x)); }
__device__ __forceinline__ unsigned fenc(float f) {
    unsigned u = __float_as_uint(f);
    return (u & 0x80000000u) ? ~u : (u | 0x80000000u);
}
__device__ __forceinline__ float fdec(unsigned u) {
    return (u & 0x80000000u) ? __uint_as_float(u & 0x7fffffffu) : __uint_as_float(~u);
}

__device__ __forceinline__ void mma16816(float* c, const uint32_t* a, const uint32_t* b) {
    asm volatile(
        "mma.sync.aligned.m16n8k16.row.col.f32.bf16.bf16.f32 "
        "{%0,%1,%2,%3}, {%4,%5,%6,%7}, {%8,%9}, {%0,%1,%2,%3};\n"
        : "+f"(c[0]), "+f"(c[1]), "+f"(c[2]), "+f"(c[3])
        : "r"(a[0]), "r"(a[1]), "r"(a[2]), "r"(a[3]), "r"(b[0]), "r"(b[1]));
}

// ---------------- W_e GEMM: C[EPAD,4096] = A[EPAD,128] @ B[4096,128]^T + b2
// split bf16 3-pass (hi*hi + hi*lo + lo*hi), fp32 accumulate.
#define SSTRIDE 136                        // bf16 elems per smem row (272B, 16B-aligned)
#define SM_AHI_O 0
#define SM_ALO_O (128 * SSTRIDE * 2)
#define SM_BHI_O (2 * 128 * SSTRIDE * 2)
#define SM_BLO_O (3 * 128 * SSTRIDE * 2)
#define SM_GEMM_TOTAL (4 * 128 * SSTRIDE * 2)   // 139264 B

__global__ void __launch_bounds__(256, 1)
gemm_we(const float* __restrict__ b2) {
    extern __shared__ char smem[];
    const int tid = threadIdx.x;
    const int n0 = blockIdx.x * 128;
    const int m0 = blockIdx.y * 128;

    // stage A (rows m0..m0+127) and B (rows n0..n0+127), K=128, hi+lo
    for (int idx = tid; idx < 128 * 16; idx += 256) {
        int r = idx >> 4, p = idx & 15;              // p: uint4 (8 bf16) chunk
        size_t goffA = (size_t)(m0 + r) * 128 + p * 8;
        size_t goffB = (size_t)(n0 + r) * 128 + p * 8;
        int soff = (r * SSTRIDE + p * 8) * 2;
        *(uint4*)(smem + SM_AHI_O + soff) = *(const uint4*)(g_Ahi + goffA);
        *(uint4*)(smem + SM_ALO_O + soff) = *(const uint4*)(g_Alo + goffA);
        *(uint4*)(smem + SM_BHI_O + soff) = *(const uint4*)(g_Bhi + goffB);
        *(uint4*)(smem + SM_BLO_O + soff) = *(const uint4*)(g_Blo + goffB);
    }
    __syncthreads();

    const int wid = tid >> 5, lane = tid & 31;
    const int warp_m = wid & 3, warp_n = wid >> 2;   // 4 x 2 warp grid
    const int g = lane >> 2, t4 = lane & 3;

    float acc[2][8][4];
#pragma unroll
    for (int mt = 0; mt < 2; mt++)
#pragma unroll
        for (int nt = 0; nt < 8; nt++)
#pragma unroll
            for (int q = 0; q < 4; q++) acc[mt][nt][q] = 0.f;

#pragma unroll
    for (int ks = 0; ks < 8; ks++) {
        const int k0 = ks * 16;
        uint32_t ahi[2][4], alo[2][4];
#pragma unroll
        for (int mt = 0; mt < 2; mt++) {
            int r0 = warp_m * 32 + mt * 16 + g;
            int byt = (r0 * SSTRIDE + k0 + t4 * 2) * 2;
            int byt8 = byt + 8 * SSTRIDE * 2;
            ahi[mt][0] = *(const uint32_t*)(smem + SM_AHI_O + byt);
            ahi[mt][1] = *(const uint32_t*)(smem + SM_AHI_O + byt8);
            ahi[mt][2] = *(const uint32_t*)(smem + SM_AHI_O + byt + 16);
            ahi[mt][3] = *(const uint32_t*)(smem + SM_AHI_O + byt8 + 16);
            alo[mt][0] = *(const uint32_t*)(smem + SM_ALO_O + byt);
            alo[mt][1] = *(const uint32_t*)(smem + SM_ALO_O + byt8);
            alo[mt][2] = *(const uint32_t*)(smem + SM_ALO_O + byt + 16);
            alo[mt][3] = *(const uint32_t*)(smem + SM_ALO_O + byt8 + 16);
        }
#pragma unroll
        for (int nt = 0; nt < 8; nt++) {
            int nrow = warp_n * 64 + nt * 8 + g;
            int byt = (nrow * SSTRIDE + k0 + t4 * 2) * 2;
            uint32_t bhi[2], blo[2];
            bhi[0] = *(const uint32_t*)(smem + SM_BHI_O + byt);
            bhi[1] = *(const uint32_t*)(smem + SM_BHI_O + byt + 16);
            blo[0] = *(const uint32_t*)(smem + SM_BLO_O + byt);
            blo[1] = *(const uint32_t*)(smem + SM_BLO_O + byt + 16);
#pragma unroll
            for (int mt = 0; mt < 2; mt++) {
                mma16816(acc[mt][nt], ahi[mt], bhi);
                mma16816(acc[mt][nt], ahi[mt], blo);
                mma16816(acc[mt][nt], alo[mt], bhi);
            }
        }
    }

    // epilogue: C += bias, store fp32
#pragma unroll
    for (int mt = 0; mt < 2; mt++) {
        int r0 = m0 + warp_m * 32 + mt * 16 + g;
#pragma unroll
        for (int nt = 0; nt < 8; nt++) {
            int n = n0 + warp_n * 64 + nt * 8 + t4 * 2;
            float2 bb = *(const float2*)(b2 + n);
            float2 v0 = make_float2(acc[mt][nt][0] + bb.x, acc[mt][nt][1] + bb.y);
            float2 v1 = make_float2(acc[mt][nt][2] + bb.x, acc[mt][nt][3] + bb.y);
            *(float2*)(g_We + (size_t)r0 * WE_COLS + n) = v0;
            *(float2*)(g_We + (size_t)(r0 + 8) * WE_COLS + n) = v1;
        }
    }
}

// ---------------- SIMT GEMM (lin0, GRU gates) ------------------------------
template<bool RELU>
__global__ void gemm_abt(const float* __restrict__ A, const float* __restrict__ B,
                         const float* __restrict__ bias, float* __restrict__ C,
                         int M, int N, int K) {
    __shared__ float As[16][65];
    __shared__ float Bs[16][65];
    int tid = threadIdx.x;
    int tx = tid & 15, ty = tid >> 4;
    int rowBase = blockIdx.y * 64;
    int colBase = blockIdx.x * 64;
    float acc[4][4] = {};
    for (int k0 = 0; k0 < K; k0 += 16) {
#pragma unroll
        for (int i = 0; i < 4; i++) {
            int e = tid + i * 256;
            int m = e >> 4, kk = e & 15;
            int r = rowBase + m, k = k0 + kk;
            As[kk][m] = (r < M && k < K) ? A[(size_t)r * K + k] : 0.f;
        }
#pragma unroll
        for (int i = 0; i < 4; i++) {
            int e = tid + i * 256;
            int n = e >> 4, kk = e & 15;
            int c = colBase + n, k = k0 + kk;
            Bs[kk][n] = (c < N && k < K) ? B[(size_t)c * K + k] : 0.f;
        }
        __syncthreads();
#pragma unroll
        for (int kk = 0; kk < 16; kk++) {
            float ra[4], rb[4];
#pragma unroll
            for (int i = 0; i < 4; i++) ra[i] = As[kk][ty * 4 + i];
#pragma unroll
            for (int j = 0; j < 4; j++) rb[j] = Bs[kk][tx * 4 + j];
#pragma unroll
            for (int i = 0; i < 4; i++)
#pragma unroll
                for (int j = 0; j < 4; j++) acc[i][j] += ra[i] * rb[j];
        }
        __syncthreads();
    }
#pragma unroll
    for (int i = 0; i < 4; i++) {
        int r = rowBase + ty * 4 + i;
        if (r >= M) continue;
#pragma unroll
        for (int j = 0; j < 4; j++) {
            int c = colBase + tx * 4 + j;
            if (c >= N) continue;
            float v = acc[i][j] + bias[c];
            if (RELU) v = fmaxf(v, 0.f);
            C[(size_t)r * N + c] = v;
        }
    }
}

// ---------------- small kernels -------------------------------------------
__global__ void zero_f(float* p, int n) {
    int i = blockIdx.x * blockDim.x + threadIdx.x;
    if (i < n) p[i] = 0.f;
}

// edge MLP layer 1 -> split bf16 hi/lo (rows >= EE zero-padded)
__global__ void mlp1_kernel(const float* __restrict__ ea, const float* __restrict__ w1,
                            const float* __restrict__ b1) {
    int idx = blockIdx.x * blockDim.x + threadIdx.x;
    if (idx >= EPAD * 128) return;
    int e = idx >> 7, h = idx & 127;
    float acc = 0.f;
    if (e < EE) {
        acc = b1[h];
        const float* row = ea + e * 5;
        const float* w = w1 + h * 5;
#pragma unroll
        for (int k = 0; k < 5; k++) acc += row[k] * w[k];
        acc = fmaxf(acc, 0.f);
    }
    __nv_bfloat16 hi = __float2bfloat16(acc);
    g_Ahi[idx] = hi;
    g_Alo[idx] = __float2bfloat16(acc - __bfloat162float(hi));
}

__global__ void w2prep_kernel(const float* __restrict__ w2) {
    int idx = blockIdx.x * blockDim.x + threadIdx.x;
    if (idx >= WE_COLS * 128) return;
    float v = w2[idx];
    __nv_bfloat16 hi = __float2bfloat16(v);
    g_Bhi[idx] = hi;
    g_Blo[idx] = __float2bfloat16(v - __bfloat162float(hi));
}

__global__ void deg_kernel(const int* __restrict__ ei) {
    int e = blockIdx.x * blockDim.x + threadIdx.x;
    if (e >= EE) return;
    atomicAdd(&g_deg[ei[EE + e]], 1.0f);
}

// one block (64 threads) per edge: msg = x[src] @ W_e, scatter-add to dst
__global__ void msg_kernel(const int* __restrict__ ei) {
    int e = blockIdx.x;
    int o = threadIdx.x;
    __shared__ float xs[DD];
    int src = ei[e];
    int dst = ei[EE + e];
    xs[o] = g_x[src * DD + o];
    __syncthreads();
    const float* w = g_We + (size_t)e * WE_COLS;
    float acc = 0.f;
#pragma unroll
    for (int d = 0; d < DD; d++) acc += xs[d] * w[d * DD + o];
    atomicAdd(&g_agg[dst * DD + o], acc);
}

__global__ void m_kernel(const float* __restrict__ conv_b) {
    int idx = blockIdx.x * blockDim.x + threadIdx.x;
    if (idx >= NN * DD) return;
    int n = idx >> 6, d = idx & 63;
    float dv = fmaxf(g_deg[n], 1.0f);
    g_m[idx] = fmaxf(g_agg[idx] / dv + conv_b[d], 0.f);
}

__global__ void gru_elem_kernel() {
    int idx = blockIdx.x * blockDim.x + threadIdx.x;
    if (idx >= NN * DD) return;
    int n = idx >> 6, j = idx & 63;
    const float* gi = g_gi + n * GDIM;
    const float* gh = g_gh + n * GDIM;
    float r = sigmoidf_(gi[j] + gh[j]);
    float z = sigmoidf_(gi[64 + j] + gh[64 + j]);
    float nn = tanhf(gi[128 + j] + r * gh[128 + j]);
    float h = g_x[idx];
    g_x[idx] = (1.f - z) * nn + z * h;
}

__global__ void s2s_init_kernel() {
    int i = blockIdx.x * blockDim.x + threadIdx.x;
    if (i < BB * 2 * DD) g_qstar[i] = 0.f;
    if (i < BB * DD) { g_hh[i] = 0.f; g_cc[i] = 0.f; }
}

__global__ void attn_init_kernel() {
    int i = blockIdx.x * blockDim.x + threadIdx.x;
    if (i < BB * DD) g_r[i] = 0.f;
    if (i < BB) { g_emax[i] = 0u; g_asum[i] = 0.f; }
}

__global__ void lstm_kernel(const float* __restrict__ w_ih, const float* __restrict__ w_hh,
                            const float* __restrict__ b_ih, const float* __restrict__ b_hh) {
    int b = blockIdx.x, j = threadIdx.x;
    __shared__ float qs[2 * DD];
    __shared__ float hs[DD];
    __shared__ float g[LG];
    if (j < 2 * DD) qs[j] = g_qstar[b * 2 * DD + j];
    else if (j < 2 * DD + DD) hs[j - 2 * DD] = g_hh[b * DD + (j - 2 * DD)];
    __syncthreads();
    float acc = b_ih[j] + b_hh[j];
    const float* wi = w_ih + j * 2 * DD;
#pragma unroll 8
    for (int k = 0; k < 2 * DD; k++) acc += qs[k] * wi[k];
    const float* wh = w_hh + j * DD;
#pragma unroll 8
    for (int k = 0; k < DD; k++) acc += hs[k] * wh[k];
    g[j] = acc;
    __syncthreads();
    if (j < DD) {
        float ig = sigmoidf_(g[j]);
        float fg = sigmoidf_(g[DD + j]);
        float gg = tanhf(g[2 * DD + j]);
        float og = sigmoidf_(g[3 * DD + j]);
        float cn = fg * g_cc[b * DD + j] + ig * gg;
        float hn = og * tanhf(cn);
        g_cc[b * DD + j] = cn;
        g_hh[b * DD + j] = hn;
    }
}

__global__ void e_kernel(const int* __restrict__ batch) {
    int n = blockIdx.x * blockDim.x + threadIdx.x;
    if (n >= NN) return;
    int b = batch[n];
    const float4* xr = (const float4*)(g_x + n * DD);
    const float4* qr = (const float4*)(g_hh + b * DD);
    float acc = 0.f;
#pragma unroll
    for (int i = 0; i < DD / 4; i++) {
        float4 a = xr[i], q = qr[i];
        acc += a.x * q.x + a.y * q.y + a.z * q.z + a.w * q.w;
    }
    g_e[n] = acc;
    atomicMax(&g_emax[b], fenc(acc));
}

__global__ void a_kernel(const int* __restrict__ batch) {
    int n = blockIdx.x * blockDim.x + threadIdx.x;
    if (n >= NN) return;
    int b = batch[n];
    float a = expf(g_e[n] - fdec(g_emax[b]));
    g_a[n] = a;
    atomicAdd(&g_asum[b], a);
}

__global__ void r_kernel(const int* __restrict__ batch) {
    int idx = blockIdx.x * blockDim.x + threadIdx.x;
    if (idx >= NN * (DD / 4)) return;
    int n = idx >> 4, c = idx & 15;
    int b = batch[n];
    float coef = g_a[n] / g_asum[b];
    float4 v = ((const float4*)(g_x + n * DD))[c];
    float* rp = g_r + b * DD + c * 4;
    atomicAdd(rp + 0, coef * v.x);
    atomicAdd(rp + 1, coef * v.y);
    atomicAdd(rp + 2, coef * v.z);
    atomicAdd(rp + 3, coef * v.w);
}

__global__ void qstar_kernel() {
    int idx = blockIdx.x * blockDim.x + threadIdx.x;
    if (idx >= BB * DD) return;
    int b = idx >> 6, j = idx & 63;
    g_qstar[b * 2 * DD + j] = g_hh[idx];
    g_qstar[b * 2 * DD + DD + j] = g_r[idx];
}

__global__ void out_kernel(float* __restrict__ out) {
    int i = blockIdx.x * blockDim.x + threadIdx.x;
    if (i < BB * 2 * DD) out[i] = g_qstar[i];
}

// ---------------- launch --------------------------------------------------
extern "C" void kernel_launch(void* const* d_in, const int* in_sizes, int n_in,
                              void* d_out, int out_size) {
    const float* x       = (const float*)d_in[0];
    const int*   ei      = (const int*)  d_in[1];
    const float* ea      = (const float*)d_in[2];
    const int*   batch   = (const int*)  d_in[3];
    const float* lin0_w  = (const float*)d_in[4];
    const float* lin0_b  = (const float*)d_in[5];
    const float* mlp_w1  = (const float*)d_in[6];
    const float* mlp_b1  = (const float*)d_in[7];
    const float* mlp_w2  = (const float*)d_in[8];
    const float* mlp_b2  = (const float*)d_in[9];
    const float* conv_b  = (const float*)d_in[10];
    const float* gw_ih   = (const float*)d_in[11];
    const float* gw_hh   = (const float*)d_in[12];
    const float* gb_ih   = (const float*)d_in[13];
    const float* gb_hh   = (const float*)d_in[14];
    const float* lw_ih   = (const float*)d_in[15];
    const float* lw_hh   = (const float*)d_in[16];
    const float* lb_ih   = (const float*)d_in[17];
    const float* lb_hh   = (const float*)d_in[18];
    float* out = (float*)d_out;

    float *p_x, *p_agg, *p_m, *p_gi, *p_gh, *p_deg;
    cudaGetSymbolAddress((void**)&p_x, g_x);
    cudaGetSymbolAddress((void**)&p_agg, g_agg);
    cudaGetSymbolAddress((void**)&p_m, g_m);
    cudaGetSymbolAddress((void**)&p_gi, g_gi);
    cudaGetSymbolAddress((void**)&p_gh, g_gh);
    cudaGetSymbolAddress((void**)&p_deg, g_deg);

    cudaFuncSetAttribute(gemm_we, cudaFuncAttributeMaxDynamicSharedMemorySize, SM_GEMM_TOTAL);

    const int T = 256;
    // lin0
    gemm_abt<true><<<dim3(1, (NN + 63) / 64), T>>>(x, lin0_w, lin0_b, p_x, NN, DD, FIN);
    // edge MLP layer 1 (-> split bf16), w2 split, then W_e GEMM (tensor cores)
    mlp1_kernel<<<(EPAD * 128 + T - 1) / T, T>>>(ea, mlp_w1, mlp_b1);
    w2prep_kernel<<<(WE_COLS * 128 + T - 1) / T, T>>>(mlp_w2);
    gemm_we<<<dim3(WE_COLS / 128, EPAD / 128), 256, SM_GEMM_TOTAL>>>(mlp_b2);
    // degree
    zero_f<<<(NN + T - 1) / T, T>>>(p_deg, NN);
    deg_kernel<<<(EE + T - 1) / T, T>>>(ei);

    for (int itr = 0; itr < 3; itr++) {
        zero_f<<<(NN * DD + T - 1) / T, T>>>(p_agg, NN * DD);
        msg_kernel<<<EE, DD>>>(ei);
        m_kernel<<<(NN * DD + T - 1) / T, T>>>(conv_b);
        gemm_abt<false><<<dim3(GDIM / 64, (NN + 63) / 64), T>>>(p_m, gw_ih, gb_ih, p_gi, NN, GDIM, DD);
        gemm_abt<false><<<dim3(GDIM / 64, (NN + 63) / 64), T>>>(p_x, gw_hh, gb_hh, p_gh, NN, GDIM, DD);
        gru_elem_kernel<<<(NN * DD + T - 1) / T, T>>>();
    }

    s2s_init_kernel<<<(BB * 2 * DD + T - 1) / T, T>>>();
    for (int s = 0; s < 3; s++) {
        lstm_kernel<<<BB, LG>>>(lw_ih, lw_hh, lb_ih, lb_hh);
        attn_init_kernel<<<(BB * DD + T - 1) / T, T>>>();
        e_kernel<<<(NN + T - 1) / T, T>>>(batch);
        a_kernel<<<(NN + T - 1) / T, T>>>(batch);
        r_kernel<<<(NN * (DD / 4) + T - 1) / T, T>>>(batch);
        qstar_kernel<<<(BB * DD + T - 1) / T, T>>>();
    }
    out_kernel<<<(BB * 2 * DD + T - 1) / T, T>>>(out);
}

// round 6
// speedup vs baseline: 2.0726x; 1.0513x over previous
#include <cuda_runtime.h>
#include <cuda_bf16.h>
#include <math.h>
#include <stdint.h>

// Problem dims
#define NN   20000
#define EE   50000
#define EPAD 50048          // 782 * 64
#define FIN  16
#define DD   64
#define BB   128
#define GDIM 192
#define LG   256
#define WE_COLS 4096

// ---------------- device scratch ----------------
__device__ float         g_x[NN * DD];
__device__ __nv_bfloat16 g_Ahi[(size_t)EPAD * 128];
__device__ __nv_bfloat16 g_Alo[(size_t)EPAD * 128];
__device__ __nv_bfloat16 g_Bhi[WE_COLS * 128];
__device__ __nv_bfloat16 g_Blo[WE_COLS * 128];
__device__ float         g_We[(size_t)EPAD * WE_COLS];   // 820 MB
__device__ float         g_agg[NN * DD];
__device__ float         g_m[NN * DD];
__device__ float         g_gi[NN * GDIM];
__device__ float         g_gh[NN * GDIM];
__device__ float         g_deg[NN];
__device__ float         g_e[NN];
__device__ float         g_a[NN];
__device__ unsigned      g_emax[BB];
__device__ float         g_asum[BB];
__device__ float         g_r[BB * DD];
__device__ float         g_hh[BB * DD];
__device__ float         g_cc[BB * DD];
__device__ float         g_qstar[BB * 2 * DD];

__device__ __forceinline__ float sigmoidf_(float x) { return 1.0f / (1.0f + expf(-x)); }
__device__ __forceinline__ unsigned fenc(float f) {
    unsigned u = __float_as_uint(f);
    return (u & 0x80000000u) ? ~u : (u | 0x80000000u);
}
__device__ __forceinline__ float fdec(unsigned u) {
    return (u & 0x80000000u) ? __uint_as_float(u & 0x7fffffffu) : __uint_as_float(~u);
}

__device__ __forceinline__ void mma16816(float* c, const uint32_t* a, const uint32_t* b) {
    asm volatile(
        "mma.sync.aligned.m16n8k16.row.col.f32.bf16.bf16.f32 "
        "{%0,%1,%2,%3}, {%4,%5,%6,%7}, {%8,%9}, {%0,%1,%2,%3};\n"
        : "+f"(c[0]), "+f"(c[1]), "+f"(c[2]), "+f"(c[3])
        : "r"(a[0]), "r"(a[1]), "r"(a[2]), "r"(a[3]), "r"(b[0]), "r"(b[1]));
}

// ---------------- W_e GEMM: C[EPAD,4096] = A[EPAD,128] @ B[4096,128]^T + b2
// split bf16 3-pass, fp32 accumulate. M-tile 64, N-tile 128, 2 CTAs/SM.
#define SSTRIDE 136
#define SM_AHI_O 0
#define SM_ALO_O (64 * SSTRIDE * 2)                  // 17408
#define SM_BHI_O (2 * 64 * SSTRIDE * 2)              // 34816
#define SM_BLO_O (SM_BHI_O + 128 * SSTRIDE * 2)      // 69632
#define SM_GEMM_TOTAL (SM_BLO_O + 128 * SSTRIDE * 2) // 104448

__global__ void __launch_bounds__(256, 2)
gemm_we(const float* __restrict__ b2) {
    extern __shared__ char smem[];
    const int tid = threadIdx.x;
    const int n0 = blockIdx.x * 128;
    const int m0 = blockIdx.y * 64;

    // stage A (64 rows) and B (128 rows), K=128, hi+lo
    for (int idx = tid; idx < 64 * 16; idx += 256) {
        int r = idx >> 4, p = idx & 15;
        size_t goffA = (size_t)(m0 + r) * 128 + p * 8;
        int soff = (r * SSTRIDE + p * 8) * 2;
        *(uint4*)(smem + SM_AHI_O + soff) = *(const uint4*)(g_Ahi + goffA);
        *(uint4*)(smem + SM_ALO_O + soff) = *(const uint4*)(g_Alo + goffA);
    }
    for (int idx = tid; idx < 128 * 16; idx += 256) {
        int r = idx >> 4, p = idx & 15;
        size_t goffB = (size_t)(n0 + r) * 128 + p * 8;
        int soff = (r * SSTRIDE + p * 8) * 2;
        *(uint4*)(smem + SM_BHI_O + soff) = *(const uint4*)(g_Bhi + goffB);
        *(uint4*)(smem + SM_BLO_O + soff) = *(const uint4*)(g_Blo + goffB);
    }
    __syncthreads();

    const int wid = tid >> 5, lane = tid & 31;
    const int warp_m = wid & 1, warp_n = wid >> 1;   // 2 x 4 warp grid
    const int g = lane >> 2, t4 = lane & 3;

    float acc[2][4][4];
#pragma unroll
    for (int mt = 0; mt < 2; mt++)
#pragma unroll
        for (int nt = 0; nt < 4; nt++)
#pragma unroll
            for (int q = 0; q < 4; q++) acc[mt][nt][q] = 0.f;

#pragma unroll
    for (int ks = 0; ks < 8; ks++) {
        const int k0 = ks * 16;
        uint32_t ahi[2][4], alo[2][4];
#pragma unroll
        for (int mt = 0; mt < 2; mt++) {
            int r0 = warp_m * 32 + mt * 16 + g;
            int byt = (r0 * SSTRIDE + k0 + t4 * 2) * 2;
            int byt8 = byt + 8 * SSTRIDE * 2;
            ahi[mt][0] = *(const uint32_t*)(smem + SM_AHI_O + byt);
            ahi[mt][1] = *(const uint32_t*)(smem + SM_AHI_O + byt8);
            ahi[mt][2] = *(const uint32_t*)(smem + SM_AHI_O + byt + 16);
            ahi[mt][3] = *(const uint32_t*)(smem + SM_AHI_O + byt8 + 16);
            alo[mt][0] = *(const uint32_t*)(smem + SM_ALO_O + byt);
            alo[mt][1] = *(const uint32_t*)(smem + SM_ALO_O + byt8);
            alo[mt][2] = *(const uint32_t*)(smem + SM_ALO_O + byt + 16);
            alo[mt][3] = *(const uint32_t*)(smem + SM_ALO_O + byt8 + 16);
        }
#pragma unroll
        for (int nt = 0; nt < 4; nt++) {
            int nrow = warp_n * 32 + nt * 8 + g;
            int byt = (nrow * SSTRIDE + k0 + t4 * 2) * 2;
            uint32_t bhi[2], blo[2];
            bhi[0] = *(const uint32_t*)(smem + SM_BHI_O + byt);
            bhi[1] = *(const uint32_t*)(smem + SM_BHI_O + byt + 16);
            blo[0] = *(const uint32_t*)(smem + SM_BLO_O + byt);
            blo[1] = *(const uint32_t*)(smem + SM_BLO_O + byt + 16);
#pragma unroll
            for (int mt = 0; mt < 2; mt++) {
                mma16816(acc[mt][nt], ahi[mt], bhi);
                mma16816(acc[mt][nt], ahi[mt], blo);
                mma16816(acc[mt][nt], alo[mt], bhi);
            }
        }
    }

    // epilogue: C += bias, store fp32
#pragma unroll
    for (int mt = 0; mt < 2; mt++) {
        int r0 = m0 + warp_m * 32 + mt * 16 + g;
#pragma unroll
        for (int nt = 0; nt < 4; nt++) {
            int n = n0 + warp_n * 32 + nt * 8 + t4 * 2;
            float2 bb = *(const float2*)(b2 + n);
            float2 v0 = make_float2(acc[mt][nt][0] + bb.x, acc[mt][nt][1] + bb.y);
            float2 v1 = make_float2(acc[mt][nt][2] + bb.x, acc[mt][nt][3] + bb.y);
            *(float2*)(g_We + (size_t)r0 * WE_COLS + n) = v0;
            *(float2*)(g_We + (size_t)(r0 + 8) * WE_COLS + n) = v1;
        }
    }
}

// ---------------- SIMT GEMM (lin0, GRU gates) ------------------------------
template<bool RELU>
__global__ void gemm_abt(const float* __restrict__ A, const float* __restrict__ B,
                         const float* __restrict__ bias, float* __restrict__ C,
                         int M, int N, int K) {
    __shared__ float As[16][65];
    __shared__ float Bs[16][65];
    int tid = threadIdx.x;
    int tx = tid & 15, ty = tid >> 4;
    int rowBase = blockIdx.y * 64;
    int colBase = blockIdx.x * 64;
    float acc[4][4] = {};
    for (int k0 = 0; k0 < K; k0 += 16) {
#pragma unroll
        for (int i = 0; i < 4; i++) {
            int e = tid + i * 256;
            int m = e >> 4, kk = e & 15;
            int r = rowBase + m, k = k0 + kk;
            As[kk][m] = (r < M && k < K) ? A[(size_t)r * K + k] : 0.f;
        }
#pragma unroll
        for (int i = 0; i < 4; i++) {
            int e = tid + i * 256;
            int n = e >> 4, kk = e & 15;
            int c = colBase + n, k = k0 + kk;
            Bs[kk][n] = (c < N && k < K) ? B[(size_t)c * K + k] : 0.f;
        }
        __syncthreads();
#pragma unroll
        for (int kk = 0; kk < 16; kk++) {
            float ra[4], rb[4];
#pragma unroll
            for (int i = 0; i < 4; i++) ra[i] = As[kk][ty * 4 + i];
#pragma unroll
            for (int j = 0; j < 4; j++) rb[j] = Bs[kk][tx * 4 + j];
#pragma unroll
            for (int i = 0; i < 4; i++)
#pragma unroll
                for (int j = 0; j < 4; j++) acc[i][j] += ra[i] * rb[j];
        }
        __syncthreads();
    }
#pragma unroll
    for (int i = 0; i < 4; i++) {
        int r = rowBase + ty * 4 + i;
        if (r >= M) continue;
#pragma unroll
        for (int j = 0; j < 4; j++) {
            int c = colBase + tx * 4 + j;
            if (c >= N) continue;
            float v = acc[i][j] + bias[c];
            if (RELU) v = fmaxf(v, 0.f);
            C[(size_t)r * N + c] = v;
        }
    }
}

// ---------------- small kernels -------------------------------------------
__global__ void zero_f(float* p, int n) {
    int i = blockIdx.x * blockDim.x + threadIdx.x;
    if (i < n) p[i] = 0.f;
}

__global__ void mlp1_kernel(const float* __restrict__ ea, const float* __restrict__ w1,
                            const float* __restrict__ b1) {
    int idx = blockIdx.x * blockDim.x + threadIdx.x;
    if (idx >= EPAD * 128) return;
    int e = idx >> 7, h = idx & 127;
    float acc = 0.f;
    if (e < EE) {
        acc = b1[h];
        const float* row = ea + e * 5;
        const float* w = w1 + h * 5;
#pragma unroll
        for (int k = 0; k < 5; k++) acc += row[k] * w[k];
        acc = fmaxf(acc, 0.f);
    }
    __nv_bfloat16 hi = __float2bfloat16(acc);
    g_Ahi[idx] = hi;
    g_Alo[idx] = __float2bfloat16(acc - __bfloat162float(hi));
}

__global__ void w2prep_kernel(const float* __restrict__ w2) {
    int idx = blockIdx.x * blockDim.x + threadIdx.x;
    if (idx >= WE_COLS * 128) return;
    float v = w2[idx];
    __nv_bfloat16 hi = __float2bfloat16(v);
    g_Bhi[idx] = hi;
    g_Blo[idx] = __float2bfloat16(v - __bfloat162float(hi));
}

__global__ void deg_kernel(const int* __restrict__ ei) {
    int e = blockIdx.x * blockDim.x + threadIdx.x;
    if (e >= EE) return;
    atomicAdd(&g_deg[ei[EE + e]], 1.0f);
}

// 8 edges per 256-thread block; one warp per edge; float4 loads, shfl reduce.
__global__ void __launch_bounds__(256)
msg_kernel(const int* __restrict__ ei) {
    __shared__ float xs[8][64];
    int w = threadIdx.x >> 5, lane = threadIdx.x & 31;
    int e = blockIdx.x * 8 + w;
    if (e >= EE) return;
    int src = ei[e];
    int dst = ei[EE + e];
    xs[w][lane] = g_x[src * DD + lane];
    xs[w][lane + 32] = g_x[src * DD + 32 + lane];
    __syncwarp();
    int h = lane >> 4, c4 = lane & 15;
    const float4* wp = (const float4*)(g_We + (size_t)e * WE_COLS);
    float ax = 0.f, ay = 0.f, az = 0.f, aw = 0.f;
#pragma unroll
    for (int s = 0; s < 32; s++) {
        int d = 2 * s + h;
        float xd = xs[w][d];
        float4 wv = wp[d * 16 + c4];
        ax = fmaf(xd, wv.x, ax);
        ay = fmaf(xd, wv.y, ay);
        az = fmaf(xd, wv.z, az);
        aw = fmaf(xd, wv.w, aw);
    }
    ax += __shfl_xor_sync(0xffffffffu, ax, 16);
    ay += __shfl_xor_sync(0xffffffffu, ay, 16);
    az += __shfl_xor_sync(0xffffffffu, az, 16);
    aw += __shfl_xor_sync(0xffffffffu, aw, 16);
    if (lane < 16) {
        float* rp = g_agg + (size_t)dst * DD + c4 * 4;
        atomicAdd(rp + 0, ax);
        atomicAdd(rp + 1, ay);
        atomicAdd(rp + 2, az);
        atomicAdd(rp + 3, aw);
    }
}

__global__ void m_kernel(const float* __restrict__ conv_b) {
    int idx = blockIdx.x * blockDim.x + threadIdx.x;
    if (idx >= NN * DD) return;
    int n = idx >> 6, d = idx & 63;
    float dv = fmaxf(g_deg[n], 1.0f);
    g_m[idx] = fmaxf(g_agg[idx] / dv + conv_b[d], 0.f);
}

__global__ void gru_elem_kernel() {
    int idx = blockIdx.x * blockDim.x + threadIdx.x;
    if (idx >= NN * DD) return;
    int n = idx >> 6, j = idx & 63;
    const float* gi = g_gi + n * GDIM;
    const float* gh = g_gh + n * GDIM;
    float r = sigmoidf_(gi[j] + gh[j]);
    float z = sigmoidf_(gi[64 + j] + gh[64 + j]);
    float nn = tanhf(gi[128 + j] + r * gh[128 + j]);
    float h = g_x[idx];
    g_x[idx] = (1.f - z) * nn + z * h;
}

__global__ void s2s_init_kernel() {
    int i = blockIdx.x * blockDim.x + threadIdx.x;
    if (i < BB * 2 * DD) g_qstar[i] = 0.f;
    if (i < BB * DD) { g_hh[i] = 0.f; g_cc[i] = 0.f; }
}

__global__ void attn_init_kernel() {
    int i = blockIdx.x * blockDim.x + threadIdx.x;
    if (i < BB * DD) g_r[i] = 0.f;
    if (i < BB) { g_emax[i] = 0u; g_asum[i] = 0.f; }
}

__global__ void lstm_kernel(const float* __restrict__ w_ih, const float* __restrict__ w_hh,
                            const float* __restrict__ b_ih, const float* __restrict__ b_hh) {
    int b = blockIdx.x, j = threadIdx.x;
    __shared__ float qs[2 * DD];
    __shared__ float hs[DD];
    __shared__ float g[LG];
    if (j < 2 * DD) qs[j] = g_qstar[b * 2 * DD + j];
    else if (j < 2 * DD + DD) hs[j - 2 * DD] = g_hh[b * DD + (j - 2 * DD)];
    __syncthreads();
    float acc = b_ih[j] + b_hh[j];
    const float* wi = w_ih + j * 2 * DD;
#pragma unroll 8
    for (int k = 0; k < 2 * DD; k++) acc += qs[k] * wi[k];
    const float* wh = w_hh + j * DD;
#pragma unroll 8
    for (int k = 0; k < DD; k++) acc += hs[k] * wh[k];
    g[j] = acc;
    __syncthreads();
    if (j < DD) {
        float ig = sigmoidf_(g[j]);
        float fg = sigmoidf_(g[DD + j]);
        float gg = tanhf(g[2 * DD + j]);
        float og = sigmoidf_(g[3 * DD + j]);
        float cn = fg * g_cc[b * DD + j] + ig * gg;
        float hn = og * tanhf(cn);
        g_cc[b * DD + j] = cn;
        g_hh[b * DD + j] = hn;
    }
}

__global__ void e_kernel(const int* __restrict__ batch) {
    int n = blockIdx.x * blockDim.x + threadIdx.x;
    if (n >= NN) return;
    int b = batch[n];
    const float4* xr = (const float4*)(g_x + n * DD);
    const float4* qr = (const float4*)(g_hh + b * DD);
    float acc = 0.f;
#pragma unroll
    for (int i = 0; i < DD / 4; i++) {
        float4 a = xr[i], q = qr[i];
        acc += a.x * q.x + a.y * q.y + a.z * q.z + a.w * q.w;
    }
    g_e[n] = acc;
    atomicMax(&g_emax[b], fenc(acc));
}

__global__ void a_kernel(const int* __restrict__ batch) {
    int n = blockIdx.x * blockDim.x + threadIdx.x;
    if (n >= NN) return;
    int b = batch[n];
    float a = expf(g_e[n] - fdec(g_emax[b]));
    g_a[n] = a;
    atomicAdd(&g_asum[b], a);
}

__global__ void r_kernel(const int* __restrict__ batch) {
    int idx = blockIdx.x * blockDim.x + threadIdx.x;
    if (idx >= NN * (DD / 4)) return;
    int n = idx >> 4, c = idx & 15;
    int b = batch[n];
    float coef = g_a[n] / g_asum[b];
    float4 v = ((const float4*)(g_x + n * DD))[c];
    float* rp = g_r + b * DD + c * 4;
    atomicAdd(rp + 0, coef * v.x);
    atomicAdd(rp + 1, coef * v.y);
    atomicAdd(rp + 2, coef * v.z);
    atomicAdd(rp + 3, coef * v.w);
}

__global__ void qstar_kernel() {
    int idx = blockIdx.x * blockDim.x + threadIdx.x;
    if (idx >= BB * DD) return;
    int b = idx >> 6, j = idx & 63;
    g_qstar[b * 2 * DD + j] = g_hh[idx];
    g_qstar[b * 2 * DD + DD + j] = g_r[idx];
}

__global__ void out_kernel(float* __restrict__ out) {
    int i = blockIdx.x * blockDim.x + threadIdx.x;
    if (i < BB * 2 * DD) out[i] = g_qstar[i];
}

// ---------------- launch --------------------------------------------------
extern "C" void kernel_launch(void* const* d_in, const int* in_sizes, int n_in,
                              void* d_out, int out_size) {
    const float* x       = (const float*)d_in[0];
    const int*   ei      = (const int*)  d_in[1];
    const float* ea      = (const float*)d_in[2];
    const int*   batch   = (const int*)  d_in[3];
    const float* lin0_w  = (const float*)d_in[4];
    const float* lin0_b  = (const float*)d_in[5];
    const float* mlp_w1  = (const float*)d_in[6];
    const float* mlp_b1  = (const float*)d_in[7];
    const float* mlp_w2  = (const float*)d_in[8];
    const float* mlp_b2  = (const float*)d_in[9];
    const float* conv_b  = (const float*)d_in[10];
    const float* gw_ih   = (const float*)d_in[11];
    const float* gw_hh   = (const float*)d_in[12];
    const float* gb_ih   = (const float*)d_in[13];
    const float* gb_hh   = (const float*)d_in[14];
    const float* lw_ih   = (const float*)d_in[15];
    const float* lw_hh   = (const float*)d_in[16];
    const float* lb_ih   = (const float*)d_in[17];
    const float* lb_hh   = (const float*)d_in[18];
    float* out = (float*)d_out;

    float *p_x, *p_agg, *p_m, *p_gi, *p_gh, *p_deg;
    cudaGetSymbolAddress((void**)&p_x, g_x);
    cudaGetSymbolAddress((void**)&p_agg, g_agg);
    cudaGetSymbolAddress((void**)&p_m, g_m);
    cudaGetSymbolAddress((void**)&p_gi, g_gi);
    cudaGetSymbolAddress((void**)&p_gh, g_gh);
    cudaGetSymbolAddress((void**)&p_deg, g_deg);

    cudaFuncSetAttribute(gemm_we, cudaFuncAttributeMaxDynamicSharedMemorySize, SM_GEMM_TOTAL);

    const int T = 256;
    // lin0
    gemm_abt<true><<<dim3(1, (NN + 63) / 64), T>>>(x, lin0_w, lin0_b, p_x, NN, DD, FIN);
    // edge MLP layer 1 (-> split bf16), w2 split, then W_e GEMM (tensor cores)
    mlp1_kernel<<<(EPAD * 128 + T - 1) / T, T>>>(ea, mlp_w1, mlp_b1);
    w2prep_kernel<<<(WE_COLS * 128 + T - 1) / T, T>>>(mlp_w2);
    gemm_we<<<dim3(WE_COLS / 128, EPAD / 64), 256, SM_GEMM_TOTAL>>>(mlp_b2);
    // degree
    zero_f<<<(NN + T - 1) / T, T>>>(p_deg, NN);
    deg_kernel<<<(EE + T - 1) / T, T>>>(ei);

    for (int itr = 0; itr < 3; itr++) {
        zero_f<<<(NN * DD + T - 1) / T, T>>>(p_agg, NN * DD);
        msg_kernel<<<(EE + 7) / 8, 256>>>(ei);
        m_kernel<<<(NN * DD + T - 1) / T, T>>>(conv_b);
        gemm_abt<false><<<dim3(GDIM / 64, (NN + 63) / 64), T>>>(p_m, gw_ih, gb_ih, p_gi, NN, GDIM, DD);
        gemm_abt<false><<<dim3(GDIM / 64, (NN + 63) / 64), T>>>(p_x, gw_hh, gb_hh, p_gh, NN, GDIM, DD);
        gru_elem_kernel<<<(NN * DD + T - 1) / T, T>>>();
    }

    s2s_init_kernel<<<(BB * 2 * DD + T - 1) / T, T>>>();
    for (int s = 0; s < 3; s++) {
        lstm_kernel<<<BB, LG>>>(lw_ih, lw_hh, lb_ih, lb_hh);
        attn_init_kernel<<<(BB * DD + T - 1) / T, T>>>();
        e_kernel<<<(NN + T - 1) / T, T>>>(batch);
        a_kernel<<<(NN + T - 1) / T, T>>>(batch);
        r_kernel<<<(NN * (DD / 4) + T - 1) / T, T>>>(batch);
        qstar_kernel<<<(BB * DD + T - 1) / T, T>>>();
    }
    out_kernel<<<(BB * 2 * DD + T - 1) / T, T>>>(out);
}

// round 7
// speedup vs baseline: 2.1494x; 1.0370x over previous
#include <cuda_runtime.h>
#include <cuda_bf16.h>
#include <math.h>
#include <stdint.h>

// Problem dims
#define NN   20000
#define EE   50000
#define EPAD 50048          // 782 * 64
#define FIN  16
#define DD   64
#define BB   128
#define GDIM 192
#define LG   256
#define WE_COLS 4096

// ---------------- device scratch ----------------
__device__ float         g_x[NN * DD];
__device__ __nv_bfloat16 g_Ahi[(size_t)EPAD * 128];
__device__ __nv_bfloat16 g_Alo[(size_t)EPAD * 128];
__device__ __nv_bfloat16 g_Bhi[WE_COLS * 128];
__device__ __nv_bfloat16 g_Blo[WE_COLS * 128];
__device__ float         g_We[(size_t)EPAD * WE_COLS];   // 820 MB
__device__ float         g_agg[NN * DD];
__device__ float         g_m[NN * DD];
__device__ float         g_gi[NN * GDIM];
__device__ float         g_gh[NN * GDIM];
__device__ float         g_deg[NN];
__device__ float         g_e[NN];
__device__ float         g_a[NN];
__device__ unsigned      g_emax[BB];
__device__ float         g_asum[BB];
__device__ float         g_r[BB * DD];
__device__ float         g_hh[BB * DD];
__device__ float         g_cc[BB * DD];
__device__ float         g_qstar[BB * 2 * DD];

__device__ __forceinline__ float sigmoidf_(float x) { return 1.0f / (1.0f + expf(-x)); }
__device__ __forceinline__ unsigned fenc(float f) {
    unsigned u = __float_as_uint(f);
    return (u & 0x80000000u) ? ~u : (u | 0x80000000u);
}
__device__ __forceinline__ float fdec(unsigned u) {
    return (u & 0x80000000u) ? __uint_as_float(u & 0x7fffffffu) : __uint_as_float(~u);
}

__device__ __forceinline__ uint32_t smem_u32(const void* p) {
    uint32_t a;
    asm("{ .reg .u64 t; cvta.to.shared.u64 t, %1; cvt.u32.u64 %0, t; }" : "=r"(a) : "l"(p));
    return a;
}

__device__ __forceinline__ void mma16816(float* c, const uint32_t* a, const uint32_t* b) {
    asm volatile(
        "mma.sync.aligned.m16n8k16.row.col.f32.bf16.bf16.f32 "
        "{%0,%1,%2,%3}, {%4,%5,%6,%7}, {%8,%9}, {%0,%1,%2,%3};\n"
        : "+f"(c[0]), "+f"(c[1]), "+f"(c[2]), "+f"(c[3])
        : "r"(a[0]), "r"(a[1]), "r"(a[2]), "r"(a[3]), "r"(b[0]), "r"(b[1]));
}

__device__ __forceinline__ void ldsm4(uint32_t* r, uint32_t addr) {
    asm volatile("ldmatrix.sync.aligned.m8n8.x4.shared.b16 {%0,%1,%2,%3}, [%4];"
                 : "=r"(r[0]), "=r"(r[1]), "=r"(r[2]), "=r"(r[3]) : "r"(addr));
}

// ---------------- W_e GEMM: C[EPAD,4096] = A[EPAD,128] @ B[4096,128]^T + b2
// split bf16 3-pass, fp32 accumulate. M-tile 64, N-tile 128, 2 CTAs/SM.
// Fragment loads via ldmatrix.x4 (conflict-free with 272B row stride).
#define SSTRIDE 136
#define SM_AHI_O 0
#define SM_ALO_O (64 * SSTRIDE * 2)                  // 17408
#define SM_BHI_O (2 * 64 * SSTRIDE * 2)              // 34816
#define SM_BLO_O (SM_BHI_O + 128 * SSTRIDE * 2)      // 69632
#define SM_GEMM_TOTAL (SM_BLO_O + 128 * SSTRIDE * 2) // 104448

__global__ void __launch_bounds__(256, 2)
gemm_we(const float* __restrict__ b2) {
    extern __shared__ char smem[];
    const int tid = threadIdx.x;
    const int n0 = blockIdx.x * 128;
    const int m0 = blockIdx.y * 64;

    // stage A (64 rows) and B (128 rows), K=128, hi+lo
    for (int idx = tid; idx < 64 * 16; idx += 256) {
        int r = idx >> 4, p = idx & 15;
        size_t goffA = (size_t)(m0 + r) * 128 + p * 8;
        int soff = (r * SSTRIDE + p * 8) * 2;
        *(uint4*)(smem + SM_AHI_O + soff) = *(const uint4*)(g_Ahi + goffA);
        *(uint4*)(smem + SM_ALO_O + soff) = *(const uint4*)(g_Alo + goffA);
    }
    for (int idx = tid; idx < 128 * 16; idx += 256) {
        int r = idx >> 4, p = idx & 15;
        size_t goffB = (size_t)(n0 + r) * 128 + p * 8;
        int soff = (r * SSTRIDE + p * 8) * 2;
        *(uint4*)(smem + SM_BHI_O + soff) = *(const uint4*)(g_Bhi + goffB);
        *(uint4*)(smem + SM_BLO_O + soff) = *(const uint4*)(g_Blo + goffB);
    }
    __syncthreads();

    const int wid = tid >> 5, lane = tid & 31;
    const int warp_m = wid & 1, warp_n = wid >> 1;   // 2 x 4 warp grid
    const int g = lane >> 2, t4 = lane & 3;
    const uint32_t sb = smem_u32(smem);

    // ldmatrix lane-address row components (element units, k added per step)
    // A (16x16, x4): rows r0+(lane&15), k offset +8 if lane>=16
    int arow0 = (warp_m * 32 + (lane & 15)) * SSTRIDE + ((lane >> 4) << 3);
    int arow1 = arow0 + 16 * SSTRIDE;
    // B (two 8-row n-blocks, x4): rows nb+(lane&7)+8*(lane>=16), k offset +8 if (lane&8)
    int brow = (warp_n * 32 + (lane & 7) + ((lane >> 4) << 3)) * SSTRIDE + (((lane >> 3) & 1) << 3);

    float acc[2][4][4];
#pragma unroll
    for (int mt = 0; mt < 2; mt++)
#pragma unroll
        for (int nt = 0; nt < 4; nt++)
#pragma unroll
            for (int q = 0; q < 4; q++) acc[mt][nt][q] = 0.f;

#pragma unroll
    for (int ks = 0; ks < 8; ks++) {
        const int k0 = ks * 16;
        uint32_t ahi[2][4], alo[2][4];
        ldsm4(ahi[0], sb + SM_AHI_O + (arow0 + k0) * 2);
        ldsm4(ahi[1], sb + SM_AHI_O + (arow1 + k0) * 2);
        ldsm4(alo[0], sb + SM_ALO_O + (arow0 + k0) * 2);
        ldsm4(alo[1], sb + SM_ALO_O + (arow1 + k0) * 2);

#pragma unroll
        for (int np = 0; np < 2; np++) {             // nt pairs {0,1}, {2,3}
            uint32_t bhi[4], blo[4];
            int boff = (brow + np * 16 * SSTRIDE + k0) * 2;
            ldsm4(bhi, sb + SM_BHI_O + boff);
            ldsm4(blo, sb + SM_BLO_O + boff);
#pragma unroll
            for (int h = 0; h < 2; h++) {            // nt = np*2 + h
                int nt = np * 2 + h;
#pragma unroll
                for (int mt = 0; mt < 2; mt++) {
                    mma16816(acc[mt][nt], ahi[mt], bhi + h * 2);
                    mma16816(acc[mt][nt], ahi[mt], blo + h * 2);
                    mma16816(acc[mt][nt], alo[mt], bhi + h * 2);
                }
            }
        }
    }

    // epilogue: C += bias, store fp32
#pragma unroll
    for (int mt = 0; mt < 2; mt++) {
        int r0 = m0 + warp_m * 32 + mt * 16 + g;
#pragma unroll
        for (int nt = 0; nt < 4; nt++) {
            int n = n0 + warp_n * 32 + nt * 8 + t4 * 2;
            float2 bb = *(const float2*)(b2 + n);
            float2 v0 = make_float2(acc[mt][nt][0] + bb.x, acc[mt][nt][1] + bb.y);
            float2 v1 = make_float2(acc[mt][nt][2] + bb.x, acc[mt][nt][3] + bb.y);
            *(float2*)(g_We + (size_t)r0 * WE_COLS + n) = v0;
            *(float2*)(g_We + (size_t)(r0 + 8) * WE_COLS + n) = v1;
        }
    }
}

// ---------------- SIMT GEMM (lin0, GRU gates) ------------------------------
template<bool RELU>
__global__ void gemm_abt(const float* __restrict__ A, const float* __restrict__ B,
                         const float* __restrict__ bias, float* __restrict__ C,
                         int M, int N, int K) {
    __shared__ float As[16][65];
    __shared__ float Bs[16][65];
    int tid = threadIdx.x;
    int tx = tid & 15, ty = tid >> 4;
    int rowBase = blockIdx.y * 64;
    int colBase = blockIdx.x * 64;
    float acc[4][4] = {};
    for (int k0 = 0; k0 < K; k0 += 16) {
#pragma unroll
        for (int i = 0; i < 4; i++) {
            int e = tid + i * 256;
            int m = e >> 4, kk = e & 15;
            int r = rowBase + m, k = k0 + kk;
            As[kk][m] = (r < M && k < K) ? A[(size_t)r * K + k] : 0.f;
        }
#pragma unroll
        for (int i = 0; i < 4; i++) {
            int e = tid + i * 256;
            int n = e >> 4, kk = e & 15;
            int c = colBase + n, k = k0 + kk;
            Bs[kk][n] = (c < N && k < K) ? B[(size_t)c * K + k] : 0.f;
        }
        __syncthreads();
#pragma unroll
        for (int kk = 0; kk < 16; kk++) {
            float ra[4], rb[4];
#pragma unroll
            for (int i = 0; i < 4; i++) ra[i] = As[kk][ty * 4 + i];
#pragma unroll
            for (int j = 0; j < 4; j++) rb[j] = Bs[kk][tx * 4 + j];
#pragma unroll
            for (int i = 0; i < 4; i++)
#pragma unroll
                for (int j = 0; j < 4; j++) acc[i][j] += ra[i] * rb[j];
        }
        __syncthreads();
    }
#pragma unroll
    for (int i = 0; i < 4; i++) {
        int r = rowBase + ty * 4 + i;
        if (r >= M) continue;
#pragma unroll
        for (int j = 0; j < 4; j++) {
            int c = colBase + tx * 4 + j;
            if (c >= N) continue;
            float v = acc[i][j] + bias[c];
            if (RELU) v = fmaxf(v, 0.f);
            C[(size_t)r * N + c] = v;
        }
    }
}

// ---------------- small kernels -------------------------------------------
__global__ void zero_f(float* p, int n) {
    int i = blockIdx.x * blockDim.x + threadIdx.x;
    if (i < n) p[i] = 0.f;
}

__global__ void mlp1_kernel(const float* __restrict__ ea, const float* __restrict__ w1,
                            const float* __restrict__ b1) {
    int idx = blockIdx.x * blockDim.x + threadIdx.x;
    if (idx >= EPAD * 128) return;
    int e = idx >> 7, h = idx & 127;
    float acc = 0.f;
    if (e < EE) {
        acc = b1[h];
        const float* row = ea + e * 5;
        const float* w = w1 + h * 5;
#pragma unroll
        for (int k = 0; k < 5; k++) acc += row[k] * w[k];
        acc = fmaxf(acc, 0.f);
    }
    __nv_bfloat16 hi = __float2bfloat16(acc);
    g_Ahi[idx] = hi;
    g_Alo[idx] = __float2bfloat16(acc - __bfloat162float(hi));
}

__global__ void w2prep_kernel(const float* __restrict__ w2) {
    int idx = blockIdx.x * blockDim.x + threadIdx.x;
    if (idx >= WE_COLS * 128) return;
    float v = w2[idx];
    __nv_bfloat16 hi = __float2bfloat16(v);
    g_Bhi[idx] = hi;
    g_Blo[idx] = __float2bfloat16(v - __bfloat162float(hi));
}

__global__ void deg_kernel(const int* __restrict__ ei) {
    int e = blockIdx.x * blockDim.x + threadIdx.x;
    if (e >= EE) return;
    atomicAdd(&g_deg[ei[EE + e]], 1.0f);
}

// 8 edges per 256-thread block; one warp per edge; float4 loads, shfl reduce.
__global__ void __launch_bounds__(256)
msg_kernel(const int* __restrict__ ei) {
    __shared__ float xs[8][64];
    int w = threadIdx.x >> 5, lane = threadIdx.x & 31;
    int e = blockIdx.x * 8 + w;
    if (e >= EE) return;
    int src = ei[e];
    int dst = ei[EE + e];
    xs[w][lane] = g_x[src * DD + lane];
    xs[w][lane + 32] = g_x[src * DD + 32 + lane];
    __syncwarp();
    int h = lane >> 4, c4 = lane & 15;
    const float4* wp = (const float4*)(g_We + (size_t)e * WE_COLS);
    float ax = 0.f, ay = 0.f, az = 0.f, aw = 0.f;
#pragma unroll
    for (int s = 0; s < 32; s++) {
        int d = 2 * s + h;
        float xd = xs[w][d];
        float4 wv = wp[d * 16 + c4];
        ax = fmaf(xd, wv.x, ax);
        ay = fmaf(xd, wv.y, ay);
        az = fmaf(xd, wv.z, az);
        aw = fmaf(xd, wv.w, aw);
    }
    ax += __shfl_xor_sync(0xffffffffu, ax, 16);
    ay += __shfl_xor_sync(0xffffffffu, ay, 16);
    az += __shfl_xor_sync(0xffffffffu, az, 16);
    aw += __shfl_xor_sync(0xffffffffu, aw, 16);
    if (lane < 16) {
        float* rp = g_agg + (size_t)dst * DD + c4 * 4;
        atomicAdd(rp + 0, ax);
        atomicAdd(rp + 1, ay);
        atomicAdd(rp + 2, az);
        atomicAdd(rp + 3, aw);
    }
}

__global__ void m_kernel(const float* __restrict__ conv_b) {
    int idx = blockIdx.x * blockDim.x + threadIdx.x;
    if (idx >= NN * DD) return;
    int n = idx >> 6, d = idx & 63;
    float dv = fmaxf(g_deg[n], 1.0f);
    g_m[idx] = fmaxf(g_agg[idx] / dv + conv_b[d], 0.f);
}

__global__ void gru_elem_kernel() {
    int idx = blockIdx.x * blockDim.x + threadIdx.x;
    if (idx >= NN * DD) return;
    int n = idx >> 6, j = idx & 63;
    const float* gi = g_gi + n * GDIM;
    const float* gh = g_gh + n * GDIM;
    float r = sigmoidf_(gi[j] + gh[j]);
    float z = sigmoidf_(gi[64 + j] + gh[64 + j]);
    float nn = tanhf(gi[128 + j] + r * gh[128 + j]);
    float h = g_x[idx];
    g_x[idx] = (1.f - z) * nn + z * h;
}

__global__ void s2s_init_kernel() {
    int i = blockIdx.x * blockDim.x + threadIdx.x;
    if (i < BB * 2 * DD) g_qstar[i] = 0.f;
    if (i < BB * DD) { g_hh[i] = 0.f; g_cc[i] = 0.f; }
}

__global__ void attn_init_kernel() {
    int i = blockIdx.x * blockDim.x + threadIdx.x;
    if (i < BB * DD) g_r[i] = 0.f;
    if (i < BB) { g_emax[i] = 0u; g_asum[i] = 0.f; }
}

__global__ void lstm_kernel(const float* __restrict__ w_ih, const float* __restrict__ w_hh,
                            const float* __restrict__ b_ih, const float* __restrict__ b_hh) {
    int b = blockIdx.x, j = threadIdx.x;
    __shared__ float qs[2 * DD];
    __shared__ float hs[DD];
    __shared__ float g[LG];
    if (j < 2 * DD) qs[j] = g_qstar[b * 2 * DD + j];
    else if (j < 2 * DD + DD) hs[j - 2 * DD] = g_hh[b * DD + (j - 2 * DD)];
    __syncthreads();
    float acc = b_ih[j] + b_hh[j];
    const float* wi = w_ih + j * 2 * DD;
#pragma unroll 8
    for (int k = 0; k < 2 * DD; k++) acc += qs[k] * wi[k];
    const float* wh = w_hh + j * DD;
#pragma unroll 8
    for (int k = 0; k < DD; k++) acc += hs[k] * wh[k];
    g[j] = acc;
    __syncthreads();
    if (j < DD) {
        float ig = sigmoidf_(g[j]);
        float fg = sigmoidf_(g[DD + j]);
        float gg = tanhf(g[2 * DD + j]);
        float og = sigmoidf_(g[3 * DD + j]);
        float cn = fg * g_cc[b * DD + j] + ig * gg;
        float hn = og * tanhf(cn);
        g_cc[b * DD + j] = cn;
        g_hh[b * DD + j] = hn;
    }
}

__global__ void e_kernel(const int* __restrict__ batch) {
    int n = blockIdx.x * blockDim.x + threadIdx.x;
    if (n >= NN) return;
    int b = batch[n];
    const float4* xr = (const float4*)(g_x + n * DD);
    const float4* qr = (const float4*)(g_hh + b * DD);
    float acc = 0.f;
#pragma unroll
    for (int i = 0; i < DD / 4; i++) {
        float4 a = xr[i], q = qr[i];
        acc += a.x * q.x + a.y * q.y + a.z * q.z + a.w * q.w;
    }
    g_e[n] = acc;
    atomicMax(&g_emax[b], fenc(acc));
}

__global__ void a_kernel(const int* __restrict__ batch) {
    int n = blockIdx.x * blockDim.x + threadIdx.x;
    if (n >= NN) return;
    int b = batch[n];
    float a = expf(g_e[n] - fdec(g_emax[b]));
    g_a[n] = a;
    atomicAdd(&g_asum[b], a);
}

__global__ void r_kernel(const int* __restrict__ batch) {
    int idx = blockIdx.x * blockDim.x + threadIdx.x;
    if (idx >= NN * (DD / 4)) return;
    int n = idx >> 4, c = idx & 15;
    int b = batch[n];
    float coef = g_a[n] / g_asum[b];
    float4 v = ((const float4*)(g_x + n * DD))[c];
    float* rp = g_r + b * DD + c * 4;
    atomicAdd(rp + 0, coef * v.x);
    atomicAdd(rp + 1, coef * v.y);
    atomicAdd(rp + 2, coef * v.z);
    atomicAdd(rp + 3, coef * v.w);
}

__global__ void qstar_kernel() {
    int idx = blockIdx.x * blockDim.x + threadIdx.x;
    if (idx >= BB * DD) return;
    int b = idx >> 6, j = idx & 63;
    g_qstar[b * 2 * DD + j] = g_hh[idx];
    g_qstar[b * 2 * DD + DD + j] = g_r[idx];
}

__global__ void out_kernel(float* __restrict__ out) {
    int i = blockIdx.x * blockDim.x + threadIdx.x;
    if (i < BB * 2 * DD) out[i] = g_qstar[i];
}

// ---------------- launch --------------------------------------------------
extern "C" void kernel_launch(void* const* d_in, const int* in_sizes, int n_in,
                              void* d_out, int out_size) {
    const float* x       = (const float*)d_in[0];
    const int*   ei      = (const int*)  d_in[1];
    const float* ea      = (const float*)d_in[2];
    const int*   batch   = (const int*)  d_in[3];
    const float* lin0_w  = (const float*)d_in[4];
    const float* lin0_b  = (const float*)d_in[5];
    const float* mlp_w1  = (const float*)d_in[6];
    const float* mlp_b1  = (const float*)d_in[7];
    const float* mlp_w2  = (const float*)d_in[8];
    const float* mlp_b2  = (const float*)d_in[9];
    const float* conv_b  = (const float*)d_in[10];
    const float* gw_ih   = (const float*)d_in[11];
    const float* gw_hh   = (const float*)d_in[12];
    const float* gb_ih   = (const float*)d_in[13];
    const float* gb_hh   = (const float*)d_in[14];
    const float* lw_ih   = (const float*)d_in[15];
    const float* lw_hh   = (const float*)d_in[16];
    const float* lb_ih   = (const float*)d_in[17];
    const float* lb_hh   = (const float*)d_in[18];
    float* out = (float*)d_out;

    float *p_x, *p_agg, *p_m, *p_gi, *p_gh, *p_deg;
    cudaGetSymbolAddress((void**)&p_x, g_x);
    cudaGetSymbolAddress((void**)&p_agg, g_agg);
    cudaGetSymbolAddress((void**)&p_m, g_m);
    cudaGetSymbolAddress((void**)&p_gi, g_gi);
    cudaGetSymbolAddress((void**)&p_gh, g_gh);
    cudaGetSymbolAddress((void**)&p_deg, g_deg);

    cudaFuncSetAttribute(gemm_we, cudaFuncAttributeMaxDynamicSharedMemorySize, SM_GEMM_TOTAL);

    const int T = 256;
    // lin0
    gemm_abt<true><<<dim3(1, (NN + 63) / 64), T>>>(x, lin0_w, lin0_b, p_x, NN, DD, FIN);
    // edge MLP layer 1 (-> split bf16), w2 split, then W_e GEMM (tensor cores)
    mlp1_kernel<<<(EPAD * 128 + T - 1) / T, T>>>(ea, mlp_w1, mlp_b1);
    w2prep_kernel<<<(WE_COLS * 128 + T - 1) / T, T>>>(mlp_w2);
    gemm_we<<<dim3(WE_COLS / 128, EPAD / 64), 256, SM_GEMM_TOTAL>>>(mlp_b2);
    // degree
    zero_f<<<(NN + T - 1) / T, T>>>(p_deg, NN);
    deg_kernel<<<(EE + T - 1) / T, T>>>(ei);

    for (int itr = 0; itr < 3; itr++) {
        zero_f<<<(NN * DD + T - 1) / T, T>>>(p_agg, NN * DD);
        msg_kernel<<<(EE + 7) / 8, 256>>>(ei);
        m_kernel<<<(NN * DD + T - 1) / T, T>>>(conv_b);
        gemm_abt<false><<<dim3(GDIM / 64, (NN + 63) / 64), T>>>(p_m, gw_ih, gb_ih, p_gi, NN, GDIM, DD);
        gemm_abt<false><<<dim3(GDIM / 64, (NN + 63) / 64), T>>>(p_x, gw_hh, gb_hh, p_gh, NN, GDIM, DD);
        gru_elem_kernel<<<(NN * DD + T - 1) / T, T>>>();
    }

    s2s_init_kernel<<<(BB * 2 * DD + T - 1) / T, T>>>();
    for (int s = 0; s < 3; s++) {
        lstm_kernel<<<BB, LG>>>(lw_ih, lw_hh, lb_ih, lb_hh);
        attn_init_kernel<<<(BB * DD + T - 1) / T, T>>>();
        e_kernel<<<(NN + T - 1) / T, T>>>(batch);
        a_kernel<<<(NN + T - 1) / T, T>>>(batch);
        r_kernel<<<(NN * (DD / 4) + T - 1) / T, T>>>(batch);
        qstar_kernel<<<(BB * DD + T - 1) / T, T>>>();
    }
    out_kernel<<<(BB * 2 * DD + T - 1) / T, T>>>(out);
}

// round 8
// speedup vs baseline: 3.0256x; 1.4076x over previous
#include <cuda_runtime.h>
#include <cuda_bf16.h>
#include <math.h>
#include <stdint.h>

// Problem dims
#define NN   20000
#define EE   50000
#define EPAD 50048          // 782 * 64
#define FIN  16
#define DD   64
#define BB   128
#define GDIM 192
#define LG   256
#define WE_COLS 4096

// ---------------- device scratch ----------------
__device__ float         g_x[NN * DD];
__device__ __nv_bfloat16 g_Ahi[(size_t)EPAD * 128];
__device__ __nv_bfloat16 g_Bhi[WE_COLS * 128];
__device__ __nv_bfloat16 g_We[(size_t)EPAD * WE_COLS];   // 410 MB bf16
__device__ float         g_agg[NN * DD];
__device__ float         g_m[NN * DD];
__device__ float         g_gi[NN * GDIM];
__device__ float         g_gh[NN * GDIM];
__device__ float         g_deg[NN];
__device__ float         g_e[NN];
__device__ float         g_a[NN];
__device__ unsigned      g_emax[BB];
__device__ float         g_asum[BB];
__device__ float         g_r[BB * DD];
__device__ float         g_hh[BB * DD];
__device__ float         g_cc[BB * DD];
__device__ float         g_qstar[BB * 2 * DD];

__device__ __forceinline__ float sigmoidf_(float x) { return 1.0f / (1.0f + expf(-x)); }
__device__ __forceinline__ unsigned fenc(float f) {
    unsigned u = __float_as_uint(f);
    return (u & 0x80000000u) ? ~u : (u | 0x80000000u);
}
__device__ __forceinline__ float fdec(unsigned u) {
    return (u & 0x80000000u) ? __uint_as_float(u & 0x7fffffffu) : __uint_as_float(~u);
}

__device__ __forceinline__ uint32_t smem_u32(const void* p) {
    uint32_t a;
    asm("{ .reg .u64 t; cvta.to.shared.u64 t, %1; cvt.u32.u64 %0, t; }" : "=r"(a) : "l"(p));
    return a;
}

__device__ __forceinline__ void mma16816(float* c, const uint32_t* a, const uint32_t* b) {
    asm volatile(
        "mma.sync.aligned.m16n8k16.row.col.f32.bf16.bf16.f32 "
        "{%0,%1,%2,%3}, {%4,%5,%6,%7}, {%8,%9}, {%0,%1,%2,%3};\n"
        : "+f"(c[0]), "+f"(c[1]), "+f"(c[2]), "+f"(c[3])
        : "r"(a[0]), "r"(a[1]), "r"(a[2]), "r"(a[3]), "r"(b[0]), "r"(b[1]));
}

__device__ __forceinline__ void ldsm4(uint32_t* r, uint32_t addr) {
    asm volatile("ldmatrix.sync.aligned.m8n8.x4.shared.b16 {%0,%1,%2,%3}, [%4];"
                 : "=r"(r[0]), "=r"(r[1]), "=r"(r[2]), "=r"(r[3]) : "r"(addr));
}

// ---------------- W_e GEMM: C[EPAD,4096] = A[EPAD,128] @ B[4096,128]^T + b2
// single-pass bf16, fp32 accumulate, bf16 store. M-tile 64, N-tile 128.
#define SSTRIDE 136
#define SM_A_O 0
#define SM_B_O (64 * SSTRIDE * 2)                    // 17408
#define SM_GEMM_TOTAL (SM_B_O + 128 * SSTRIDE * 2)   // 52224

__global__ void __launch_bounds__(256, 3)
gemm_we(const float* __restrict__ b2) {
    extern __shared__ char smem[];
    const int tid = threadIdx.x;
    const int n0 = blockIdx.x * 128;
    const int m0 = blockIdx.y * 64;

    for (int idx = tid; idx < 64 * 16; idx += 256) {
        int r = idx >> 4, p = idx & 15;
        *(uint4*)(smem + SM_A_O + (r * SSTRIDE + p * 8) * 2) =
            *(const uint4*)(g_Ahi + (size_t)(m0 + r) * 128 + p * 8);
    }
    for (int idx = tid; idx < 128 * 16; idx += 256) {
        int r = idx >> 4, p = idx & 15;
        *(uint4*)(smem + SM_B_O + (r * SSTRIDE + p * 8) * 2) =
            *(const uint4*)(g_Bhi + (size_t)(n0 + r) * 128 + p * 8);
    }
    __syncthreads();

    const int wid = tid >> 5, lane = tid & 31;
    const int warp_m = wid & 1, warp_n = wid >> 1;   // 2 x 4 warp grid
    const int g = lane >> 2, t4 = lane & 3;
    const uint32_t sb = smem_u32(smem);

    int arow0 = (warp_m * 32 + (lane & 15)) * SSTRIDE + ((lane >> 4) << 3);
    int arow1 = arow0 + 16 * SSTRIDE;
    int brow = (warp_n * 32 + (lane & 7) + ((lane >> 4) << 3)) * SSTRIDE + (((lane >> 3) & 1) << 3);

    float acc[2][4][4];
#pragma unroll
    for (int mt = 0; mt < 2; mt++)
#pragma unroll
        for (int nt = 0; nt < 4; nt++)
#pragma unroll
            for (int q = 0; q < 4; q++) acc[mt][nt][q] = 0.f;

#pragma unroll
    for (int ks = 0; ks < 8; ks++) {
        const int k0 = ks * 16;
        uint32_t a0[4], a1[4];
        ldsm4(a0, sb + SM_A_O + (arow0 + k0) * 2);
        ldsm4(a1, sb + SM_A_O + (arow1 + k0) * 2);
#pragma unroll
        for (int np = 0; np < 2; np++) {
            uint32_t bf[4];
            ldsm4(bf, sb + SM_B_O + (brow + np * 16 * SSTRIDE + k0) * 2);
#pragma unroll
            for (int h = 0; h < 2; h++) {
                int nt = np * 2 + h;
                mma16816(acc[0][nt], a0, bf + h * 2);
                mma16816(acc[1][nt], a1, bf + h * 2);
            }
        }
    }

    // epilogue: +bias, store bf16
#pragma unroll
    for (int mt = 0; mt < 2; mt++) {
        int r0 = m0 + warp_m * 32 + mt * 16 + g;
#pragma unroll
        for (int nt = 0; nt < 4; nt++) {
            int n = n0 + warp_n * 32 + nt * 8 + t4 * 2;
            float2 bb = *(const float2*)(b2 + n);
            __nv_bfloat162 v0 = __floats2bfloat162_rn(acc[mt][nt][0] + bb.x, acc[mt][nt][1] + bb.y);
            __nv_bfloat162 v1 = __floats2bfloat162_rn(acc[mt][nt][2] + bb.x, acc[mt][nt][3] + bb.y);
            *(__nv_bfloat162*)(g_We + (size_t)r0 * WE_COLS + n) = v0;
            *(__nv_bfloat162*)(g_We + (size_t)(r0 + 8) * WE_COLS + n) = v1;
        }
    }
}

// ---------------- SIMT GEMM (lin0, GRU gates) ------------------------------
template<bool RELU>
__global__ void gemm_abt(const float* __restrict__ A, const float* __restrict__ B,
                         const float* __restrict__ bias, float* __restrict__ C,
                         int M, int N, int K) {
    __shared__ float As[16][65];
    __shared__ float Bs[16][65];
    int tid = threadIdx.x;
    int tx = tid & 15, ty = tid >> 4;
    int rowBase = blockIdx.y * 64;
    int colBase = blockIdx.x * 64;
    float acc[4][4] = {};
    for (int k0 = 0; k0 < K; k0 += 16) {
#pragma unroll
        for (int i = 0; i < 4; i++) {
            int e = tid + i * 256;
            int m = e >> 4, kk = e & 15;
            int r = rowBase + m, k = k0 + kk;
            As[kk][m] = (r < M && k < K) ? A[(size_t)r * K + k] : 0.f;
        }
#pragma unroll
        for (int i = 0; i < 4; i++) {
            int e = tid + i * 256;
            int n = e >> 4, kk = e & 15;
            int c = colBase + n, k = k0 + kk;
            Bs[kk][n] = (c < N && k < K) ? B[(size_t)c * K + k] : 0.f;
        }
        __syncthreads();
#pragma unroll
        for (int kk = 0; kk < 16; kk++) {
            float ra[4], rb[4];
#pragma unroll
            for (int i = 0; i < 4; i++) ra[i] = As[kk][ty * 4 + i];
#pragma unroll
            for (int j = 0; j < 4; j++) rb[j] = Bs[kk][tx * 4 + j];
#pragma unroll
            for (int i = 0; i < 4; i++)
#pragma unroll
                for (int j = 0; j < 4; j++) acc[i][j] += ra[i] * rb[j];
        }
        __syncthreads();
    }
#pragma unroll
    for (int i = 0; i < 4; i++) {
        int r = rowBase + ty * 4 + i;
        if (r >= M) continue;
#pragma unroll
        for (int j = 0; j < 4; j++) {
            int c = colBase + tx * 4 + j;
            if (c >= N) continue;
            float v = acc[i][j] + bias[c];
            if (RELU) v = fmaxf(v, 0.f);
            C[(size_t)r * N + c] = v;
        }
    }
}

// ---------------- small kernels -------------------------------------------
__global__ void zero_f(float* p, int n) {
    int i = blockIdx.x * blockDim.x + threadIdx.x;
    if (i < n) p[i] = 0.f;
}

__global__ void mlp1_kernel(const float* __restrict__ ea, const float* __restrict__ w1,
                            const float* __restrict__ b1) {
    int idx = blockIdx.x * blockDim.x + threadIdx.x;
    if (idx >= EPAD * 128) return;
    int e = idx >> 7, h = idx & 127;
    float acc = 0.f;
    if (e < EE) {
        acc = b1[h];
        const float* row = ea + e * 5;
        const float* w = w1 + h * 5;
#pragma unroll
        for (int k = 0; k < 5; k++) acc += row[k] * w[k];
        acc = fmaxf(acc, 0.f);
    }
    g_Ahi[idx] = __float2bfloat16(acc);
}

__global__ void w2prep_kernel(const float* __restrict__ w2) {
    int idx = blockIdx.x * blockDim.x + threadIdx.x;
    if (idx >= WE_COLS * 128) return;
    g_Bhi[idx] = __float2bfloat16(w2[idx]);
}

__global__ void deg_kernel(const int* __restrict__ ei) {
    int e = blockIdx.x * blockDim.x + threadIdx.x;
    if (e >= EE) return;
    atomicAdd(&g_deg[ei[EE + e]], 1.0f);
}

// 8 edges per 256-thread block; one warp per edge; bf16 uint4 loads.
__global__ void __launch_bounds__(256)
msg_kernel(const int* __restrict__ ei) {
    __shared__ float xs[8][64];
    int w = threadIdx.x >> 5, lane = threadIdx.x & 31;
    int e = blockIdx.x * 8 + w;
    if (e >= EE) return;
    int src = ei[e];
    int dst = ei[EE + e];
    xs[w][lane] = g_x[src * DD + lane];
    xs[w][lane + 32] = g_x[src * DD + 32 + lane];
    __syncwarp();
    int oc = lane & 7, h = lane >> 3;               // o-octet, d-group
    const __nv_bfloat16* wp = g_We + (size_t)e * WE_COLS;
    float acc[8] = {0.f, 0.f, 0.f, 0.f, 0.f, 0.f, 0.f, 0.f};
#pragma unroll
    for (int s = 0; s < 16; s++) {
        int d = s * 4 + h;
        float xd = xs[w][d];
        uint4 v = *(const uint4*)(wp + d * 64 + oc * 8);
        float2 f0 = __bfloat1622float2(*(__nv_bfloat162*)&v.x);
        float2 f1 = __bfloat1622float2(*(__nv_bfloat162*)&v.y);
        float2 f2 = __bfloat1622float2(*(__nv_bfloat162*)&v.z);
        float2 f3 = __bfloat1622float2(*(__nv_bfloat162*)&v.w);
        acc[0] = fmaf(xd, f0.x, acc[0]);
        acc[1] = fmaf(xd, f0.y, acc[1]);
        acc[2] = fmaf(xd, f1.x, acc[2]);
        acc[3] = fmaf(xd, f1.y, acc[3]);
        acc[4] = fmaf(xd, f2.x, acc[4]);
        acc[5] = fmaf(xd, f2.y, acc[5]);
        acc[6] = fmaf(xd, f3.x, acc[6]);
        acc[7] = fmaf(xd, f3.y, acc[7]);
    }
#pragma unroll
    for (int i = 0; i < 8; i++) {
        acc[i] += __shfl_xor_sync(0xffffffffu, acc[i], 8);
        acc[i] += __shfl_xor_sync(0xffffffffu, acc[i], 16);
    }
    if (lane < 8) {
        float* rp = g_agg + (size_t)dst * DD + lane * 8;
#pragma unroll
        for (int i = 0; i < 8; i++) atomicAdd(rp + i, acc[i]);
    }
}

__global__ void m_kernel(const float* __restrict__ conv_b) {
    int idx = blockIdx.x * blockDim.x + threadIdx.x;
    if (idx >= NN * DD) return;
    int n = idx >> 6, d = idx & 63;
    float dv = fmaxf(g_deg[n], 1.0f);
    g_m[idx] = fmaxf(g_agg[idx] / dv + conv_b[d], 0.f);
}

__global__ void gru_elem_kernel() {
    int idx = blockIdx.x * blockDim.x + threadIdx.x;
    if (idx >= NN * DD) return;
    int n = idx >> 6, j = idx & 63;
    const float* gi = g_gi + n * GDIM;
    const float* gh = g_gh + n * GDIM;
    float r = sigmoidf_(gi[j] + gh[j]);
    float z = sigmoidf_(gi[64 + j] + gh[64 + j]);
    float nn = tanhf(gi[128 + j] + r * gh[128 + j]);
    float h = g_x[idx];
    g_x[idx] = (1.f - z) * nn + z * h;
}

__global__ void s2s_init_kernel() {
    int i = blockIdx.x * blockDim.x + threadIdx.x;
    if (i < BB * 2 * DD) g_qstar[i] = 0.f;
    if (i < BB * DD) { g_hh[i] = 0.f; g_cc[i] = 0.f; }
}

__global__ void attn_init_kernel() {
    int i = blockIdx.x * blockDim.x + threadIdx.x;
    if (i < BB * DD) g_r[i] = 0.f;
    if (i < BB) { g_emax[i] = 0u; g_asum[i] = 0.f; }
}

__global__ void lstm_kernel(const float* __restrict__ w_ih, const float* __restrict__ w_hh,
                            const float* __restrict__ b_ih, const float* __restrict__ b_hh) {
    int b = blockIdx.x, j = threadIdx.x;
    __shared__ float qs[2 * DD];
    __shared__ float hs[DD];
    __shared__ float g[LG];
    if (j < 2 * DD) qs[j] = g_qstar[b * 2 * DD + j];
    else if (j < 2 * DD + DD) hs[j - 2 * DD] = g_hh[b * DD + (j - 2 * DD)];
    __syncthreads();
    float acc = b_ih[j] + b_hh[j];
    const float* wi = w_ih + j * 2 * DD;
#pragma unroll 8
    for (int k = 0; k < 2 * DD; k++) acc += qs[k] * wi[k];
    const float* wh = w_hh + j * DD;
#pragma unroll 8
    for (int k = 0; k < DD; k++) acc += hs[k] * wh[k];
    g[j] = acc;
    __syncthreads();
    if (j < DD) {
        float ig = sigmoidf_(g[j]);
        float fg = sigmoidf_(g[DD + j]);
        float gg = tanhf(g[2 * DD + j]);
        float og = sigmoidf_(g[3 * DD + j]);
        float cn = fg * g_cc[b * DD + j] + ig * gg;
        float hn = og * tanhf(cn);
        g_cc[b * DD + j] = cn;
        g_hh[b * DD + j] = hn;
    }
}

__global__ void e_kernel(const int* __restrict__ batch) {
    int n = blockIdx.x * blockDim.x + threadIdx.x;
    if (n >= NN) return;
    int b = batch[n];
    const float4* xr = (const float4*)(g_x + n * DD);
    const float4* qr = (const float4*)(g_hh + b * DD);
    float acc = 0.f;
#pragma unroll
    for (int i = 0; i < DD / 4; i++) {
        float4 a = xr[i], q = qr[i];
        acc += a.x * q.x + a.y * q.y + a.z * q.z + a.w * q.w;
    }
    g_e[n] = acc;
    atomicMax(&g_emax[b], fenc(acc));
}

__global__ void a_kernel(const int* __restrict__ batch) {
    int n = blockIdx.x * blockDim.x + threadIdx.x;
    if (n >= NN) return;
    int b = batch[n];
    float a = expf(g_e[n] - fdec(g_emax[b]));
    g_a[n] = a;
    atomicAdd(&g_asum[b], a);
}

__global__ void r_kernel(const int* __restrict__ batch) {
    int idx = blockIdx.x * blockDim.x + threadIdx.x;
    if (idx >= NN * (DD / 4)) return;
    int n = idx >> 4, c = idx & 15;
    int b = batch[n];
    float coef = g_a[n] / g_asum[b];
    float4 v = ((const float4*)(g_x + n * DD))[c];
    float* rp = g_r + b * DD + c * 4;
    atomicAdd(rp + 0, coef * v.x);
    atomicAdd(rp + 1, coef * v.y);
    atomicAdd(rp + 2, coef * v.z);
    atomicAdd(rp + 3, coef * v.w);
}

__global__ void qstar_kernel() {
    int idx = blockIdx.x * blockDim.x + threadIdx.x;
    if (idx >= BB * DD) return;
    int b = idx >> 6, j = idx & 63;
    g_qstar[b * 2 * DD + j] = g_hh[idx];
    g_qstar[b * 2 * DD + DD + j] = g_r[idx];
}

__global__ void out_kernel(float* __restrict__ out) {
    int i = blockIdx.x * blockDim.x + threadIdx.x;
    if (i < BB * 2 * DD) out[i] = g_qstar[i];
}

// ---------------- launch --------------------------------------------------
extern "C" void kernel_launch(void* const* d_in, const int* in_sizes, int n_in,
                              void* d_out, int out_size) {
    const float* x       = (const float*)d_in[0];
    const int*   ei      = (const int*)  d_in[1];
    const float* ea      = (const float*)d_in[2];
    const int*   batch   = (const int*)  d_in[3];
    const float* lin0_w  = (const float*)d_in[4];
    const float* lin0_b  = (const float*)d_in[5];
    const float* mlp_w1  = (const float*)d_in[6];
    const float* mlp_b1  = (const float*)d_in[7];
    const float* mlp_w2  = (const float*)d_in[8];
    const float* mlp_b2  = (const float*)d_in[9];
    const float* conv_b  = (const float*)d_in[10];
    const float* gw_ih   = (const float*)d_in[11];
    const float* gw_hh   = (const float*)d_in[12];
    const float* gb_ih   = (const float*)d_in[13];
    const float* gb_hh   = (const float*)d_in[14];
    const float* lw_ih   = (const float*)d_in[15];
    const float* lw_hh   = (const float*)d_in[16];
    const float* lb_ih   = (const float*)d_in[17];
    const float* lb_hh   = (const float*)d_in[18];
    float* out = (float*)d_out;

    float *p_x, *p_agg, *p_m, *p_gi, *p_gh, *p_deg;
    cudaGetSymbolAddress((void**)&p_x, g_x);
    cudaGetSymbolAddress((void**)&p_agg, g_agg);
    cudaGetSymbolAddress((void**)&p_m, g_m);
    cudaGetSymbolAddress((void**)&p_gi, g_gi);
    cudaGetSymbolAddress((void**)&p_gh, g_gh);
    cudaGetSymbolAddress((void**)&p_deg, g_deg);

    cudaFuncSetAttribute(gemm_we, cudaFuncAttributeMaxDynamicSharedMemorySize, SM_GEMM_TOTAL);

    const int T = 256;
    // lin0
    gemm_abt<true><<<dim3(1, (NN + 63) / 64), T>>>(x, lin0_w, lin0_b, p_x, NN, DD, FIN);
    // edge MLP layer 1 (-> bf16), w2 bf16, then W_e GEMM (tensor cores)
    mlp1_kernel<<<(EPAD * 128 + T - 1) / T, T>>>(ea, mlp_w1, mlp_b1);
    w2prep_kernel<<<(WE_COLS * 128 + T - 1) / T, T>>>(mlp_w2);
    gemm_we<<<dim3(WE_COLS / 128, EPAD / 64), 256, SM_GEMM_TOTAL>>>(mlp_b2);
    // degree
    zero_f<<<(NN + T - 1) / T, T>>>(p_deg, NN);
    deg_kernel<<<(EE + T - 1) / T, T>>>(ei);

    for (int itr = 0; itr < 3; itr++) {
        zero_f<<<(NN * DD + T - 1) / T, T>>>(p_agg, NN * DD);
        msg_kernel<<<(EE + 7) / 8, 256>>>(ei);
        m_kernel<<<(NN * DD + T - 1) / T, T>>>(conv_b);
        gemm_abt<false><<<dim3(GDIM / 64, (NN + 63) / 64), T>>>(p_m, gw_ih, gb_ih, p_gi, NN, GDIM, DD);
        gemm_abt<false><<<dim3(GDIM / 64, (NN + 63) / 64), T>>>(p_x, gw_hh, gb_hh, p_gh, NN, GDIM, DD);
        gru_elem_kernel<<<(NN * DD + T - 1) / T, T>>>();
    }

    s2s_init_kernel<<<(BB * 2 * DD + T - 1) / T, T>>>();
    for (int s = 0; s < 3; s++) {
        lstm_kernel<<<BB, LG>>>(lw_ih, lw_hh, lb_ih, lb_hh);
        attn_init_kernel<<<(BB * DD + T - 1) / T, T>>>();
        e_kernel<<<(NN + T - 1) / T, T>>>(batch);
        a_kernel<<<(NN + T - 1) / T, T>>>(batch);
        r_kernel<<<(NN * (DD / 4) + T - 1) / T, T>>>(batch);
        qstar_kernel<<<(BB * DD + T - 1) / T, T>>>();
    }
    out_kernel<<<(BB * 2 * DD + T - 1) / T, T>>>(out);
}

// round 9
// speedup vs baseline: 3.5787x; 1.1828x over previous
#include <cuda_runtime.h>
#include <cuda_bf16.h>
#include <math.h>
#include <stdint.h>

// Problem dims
#define NN   20000
#define EE   50000
#define EPAD 50048          // 391 * 128
#define FIN  16
#define DD   64
#define BB   128
#define GDIM 192
#define LG   256
#define WE_COLS 4096

// ---------------- device scratch ----------------
__device__ float         g_x[NN * DD];
__device__ __nv_bfloat16 g_Ahi[(size_t)EPAD * 128];
__device__ __nv_bfloat16 g_Bhi[WE_COLS * 128];
__device__ __nv_bfloat16 g_We[(size_t)EPAD * WE_COLS];   // 410 MB bf16
__device__ float         g_agg[NN * DD];
__device__ float         g_m[NN * DD];
__device__ float         g_gi[NN * GDIM];
__device__ float         g_gh[NN * GDIM];
__device__ float         g_deg[NN];
__device__ float         g_e[NN];
__device__ float         g_a[NN];
__device__ unsigned      g_emax[BB];
__device__ float         g_asum[BB];
__device__ float         g_r[BB * DD];
__device__ float         g_hh[BB * DD];
__device__ float         g_cc[BB * DD];
__device__ float         g_qstar[BB * 2 * DD];

__device__ __forceinline__ float sigmoidf_(float x) { return 1.0f / (1.0f + expf(-x)); }
__device__ __forceinline__ unsigned fenc(float f) {
    unsigned u = __float_as_uint(f);
    return (u & 0x80000000u) ? ~u : (u | 0x80000000u);
}
__device__ __forceinline__ float fdec(unsigned u) {
    return (u & 0x80000000u) ? __uint_as_float(u & 0x7fffffffu) : __uint_as_float(~u);
}

__device__ __forceinline__ uint32_t smem_u32(const void* p) {
    uint32_t a;
    asm("{ .reg .u64 t; cvta.to.shared.u64 t, %1; cvt.u32.u64 %0, t; }" : "=r"(a) : "l"(p));
    return a;
}

__device__ __forceinline__ void mma16816(float* c, const uint32_t* a, const uint32_t* b) {
    asm volatile(
        "mma.sync.aligned.m16n8k16.row.col.f32.bf16.bf16.f32 "
        "{%0,%1,%2,%3}, {%4,%5,%6,%7}, {%8,%9}, {%0,%1,%2,%3};\n"
        : "+f"(c[0]), "+f"(c[1]), "+f"(c[2]), "+f"(c[3])
        : "r"(a[0]), "r"(a[1]), "r"(a[2]), "r"(a[3]), "r"(b[0]), "r"(b[1]));
}

__device__ __forceinline__ void ldsm4(uint32_t* r, uint32_t addr) {
    asm volatile("ldmatrix.sync.aligned.m8n8.x4.shared.b16 {%0,%1,%2,%3}, [%4];"
                 : "=r"(r[0]), "=r"(r[1]), "=r"(r[2]), "=r"(r[3]) : "r"(addr));
}

__device__ __forceinline__ void cpasync16(uint32_t saddr, const void* gaddr) {
    asm volatile("cp.async.cg.shared.global [%0], [%1], 16;" :: "r"(saddr), "l"(gaddr));
}

// ---------------- W_e GEMM: C[EPAD,4096] = A[EPAD,128] @ B[4096,128]^T + b2
// single-pass bf16, fp32 accumulate, bf16 store.
// CTA tile 128x128, warp grid 2x4 (warp tile 64x32), cp.async staging,
// smem-staged coalesced epilogue.
#define SSTRIDE 136
#define SM_A_O 0
#define SM_B_O (128 * SSTRIDE * 2)                   // 34816
#define SM_GEMM_TOTAL (SM_B_O + 128 * SSTRIDE * 2)   // 69632

__global__ void __launch_bounds__(256, 2)
gemm_we(const float* __restrict__ b2) {
    extern __shared__ char smem[];
    const int tid = threadIdx.x;
    const int n0 = blockIdx.x * 128;
    const int m0 = blockIdx.y * 128;
    const uint32_t sb = smem_u32(smem);

    // stage A and B via cp.async (128 rows x 256B each)
    for (int idx = tid; idx < 128 * 16; idx += 256) {
        int r = idx >> 4, p = idx & 15;
        uint32_t so = (uint32_t)(r * SSTRIDE + p * 8) * 2;
        cpasync16(sb + SM_A_O + so, g_Ahi + (size_t)(m0 + r) * 128 + p * 8);
        cpasync16(sb + SM_B_O + so, g_Bhi + (size_t)(n0 + r) * 128 + p * 8);
    }
    asm volatile("cp.async.commit_group;");
    asm volatile("cp.async.wait_group 0;");
    __syncthreads();

    const int wid = tid >> 5, lane = tid & 31;
    const int warp_m = wid & 1, warp_n = wid >> 1;   // 2 x 4 warp grid
    const int g = lane >> 2, t4 = lane & 3;

    // ldmatrix lane-address row components (element units)
    int arow = (warp_m * 64 + (lane & 15)) * SSTRIDE + ((lane >> 4) << 3);
    int brow = (warp_n * 32 + (lane & 7) + ((lane >> 4) << 3)) * SSTRIDE + (((lane >> 3) & 1) << 3);

    float acc[4][4][4];
#pragma unroll
    for (int mt = 0; mt < 4; mt++)
#pragma unroll
        for (int nt = 0; nt < 4; nt++)
#pragma unroll
            for (int q = 0; q < 4; q++) acc[mt][nt][q] = 0.f;

#pragma unroll
    for (int ks = 0; ks < 8; ks++) {
        const int k0 = ks * 16;
        uint32_t af[4][4];
#pragma unroll
        for (int mt = 0; mt < 4; mt++)
            ldsm4(af[mt], sb + SM_A_O + (arow + mt * 16 * SSTRIDE + k0) * 2);
#pragma unroll
        for (int np = 0; np < 2; np++) {
            uint32_t bf[4];
            ldsm4(bf, sb + SM_B_O + (brow + np * 16 * SSTRIDE + k0) * 2);
#pragma unroll
            for (int h = 0; h < 2; h++) {
                int nt = np * 2 + h;
#pragma unroll
                for (int mt = 0; mt < 4; mt++)
                    mma16816(acc[mt][nt], af[mt], bf + h * 2);
            }
        }
    }

    // epilogue: +bias -> bf16 into smem (reuse A region), then coalesced STG
    __syncthreads();
    __nv_bfloat16* cs = (__nv_bfloat16*)smem;
#pragma unroll
    for (int mt = 0; mt < 4; mt++) {
        int r0 = warp_m * 64 + mt * 16 + g;
#pragma unroll
        for (int nt = 0; nt < 4; nt++) {
            int c = warp_n * 32 + nt * 8 + t4 * 2;
            float2 bb = *(const float2*)(b2 + n0 + c);
            *(__nv_bfloat162*)(cs + r0 * SSTRIDE + c) =
                __floats2bfloat162_rn(acc[mt][nt][0] + bb.x, acc[mt][nt][1] + bb.y);
            *(__nv_bfloat162*)(cs + (r0 + 8) * SSTRIDE + c) =
                __floats2bfloat162_rn(acc[mt][nt][2] + bb.x, acc[mt][nt][3] + bb.y);
        }
    }
    __syncthreads();
    for (int idx = tid; idx < 128 * 16; idx += 256) {
        int r = idx >> 4, ch = idx & 15;
        *(uint4*)(g_We + (size_t)(m0 + r) * WE_COLS + n0 + ch * 8) =
            *(const uint4*)(cs + r * SSTRIDE + ch * 8);
    }
}

// ---------------- SIMT GEMM (lin0, GRU gates) ------------------------------
template<bool RELU>
__global__ void gemm_abt(const float* __restrict__ A, const float* __restrict__ B,
                         const float* __restrict__ bias, float* __restrict__ C,
                         int M, int N, int K) {
    __shared__ float As[16][65];
    __shared__ float Bs[16][65];
    int tid = threadIdx.x;
    int tx = tid & 15, ty = tid >> 4;
    int rowBase = blockIdx.y * 64;
    int colBase = blockIdx.x * 64;
    float acc[4][4] = {};
    for (int k0 = 0; k0 < K; k0 += 16) {
#pragma unroll
        for (int i = 0; i < 4; i++) {
            int e = tid + i * 256;
            int m = e >> 4, kk = e & 15;
            int r = rowBase + m, k = k0 + kk;
            As[kk][m] = (r < M && k < K) ? A[(size_t)r * K + k] : 0.f;
        }
#pragma unroll
        for (int i = 0; i < 4; i++) {
            int e = tid + i * 256;
            int n = e >> 4, kk = e & 15;
            int c = colBase + n, k = k0 + kk;
            Bs[kk][n] = (c < N && k < K) ? B[(size_t)c * K + k] : 0.f;
        }
        __syncthreads();
#pragma unroll
        for (int kk = 0; kk < 16; kk++) {
            float ra[4], rb[4];
#pragma unroll
            for (int i = 0; i < 4; i++) ra[i] = As[kk][ty * 4 + i];
#pragma unroll
            for (int j = 0; j < 4; j++) rb[j] = Bs[kk][tx * 4 + j];
#pragma unroll
            for (int i = 0; i < 4; i++)
#pragma unroll
                for (int j = 0; j < 4; j++) acc[i][j] += ra[i] * rb[j];
        }
        __syncthreads();
    }
#pragma unroll
    for (int i = 0; i < 4; i++) {
        int r = rowBase + ty * 4 + i;
        if (r >= M) continue;
#pragma unroll
        for (int j = 0; j < 4; j++) {
            int c = colBase + tx * 4 + j;
            if (c >= N) continue;
            float v = acc[i][j] + bias[c];
            if (RELU) v = fmaxf(v, 0.f);
            C[(size_t)r * N + c] = v;
        }
    }
}

// ---------------- small kernels -------------------------------------------
__global__ void zero_f(float* p, int n) {
    int i = blockIdx.x * blockDim.x + threadIdx.x;
    if (i < n) p[i] = 0.f;
}

__global__ void mlp1_kernel(const float* __restrict__ ea, const float* __restrict__ w1,
                            const float* __restrict__ b1) {
    int idx = blockIdx.x * blockDim.x + threadIdx.x;
    if (idx >= EPAD * 128) return;
    int e = idx >> 7, h = idx & 127;
    float acc = 0.f;
    if (e < EE) {
        acc = b1[h];
        const float* row = ea + e * 5;
        const float* w = w1 + h * 5;
#pragma unroll
        for (int k = 0; k < 5; k++) acc += row[k] * w[k];
        acc = fmaxf(acc, 0.f);
    }
    g_Ahi[idx] = __float2bfloat16(acc);
}

__global__ void w2prep_kernel(const float* __restrict__ w2) {
    int idx = blockIdx.x * blockDim.x + threadIdx.x;
    if (idx >= WE_COLS * 128) return;
    g_Bhi[idx] = __float2bfloat16(w2[idx]);
}

__global__ void deg_kernel(const int* __restrict__ ei) {
    int e = blockIdx.x * blockDim.x + threadIdx.x;
    if (e >= EE) return;
    atomicAdd(&g_deg[ei[EE + e]], 1.0f);
}

// 8 edges per 256-thread block; one warp per edge; bf16 uint4 loads.
__global__ void __launch_bounds__(256)
msg_kernel(const int* __restrict__ ei) {
    __shared__ float xs[8][64];
    int w = threadIdx.x >> 5, lane = threadIdx.x & 31;
    int e = blockIdx.x * 8 + w;
    if (e >= EE) return;
    int src = ei[e];
    int dst = ei[EE + e];
    xs[w][lane] = g_x[src * DD + lane];
    xs[w][lane + 32] = g_x[src * DD + 32 + lane];
    __syncwarp();
    int oc = lane & 7, h = lane >> 3;               // o-octet, d-group
    const __nv_bfloat16* wp = g_We + (size_t)e * WE_COLS;
    float acc[8] = {0.f, 0.f, 0.f, 0.f, 0.f, 0.f, 0.f, 0.f};
#pragma unroll
    for (int s = 0; s < 16; s++) {
        int d = s * 4 + h;
        float xd = xs[w][d];
        uint4 v = *(const uint4*)(wp + d * 64 + oc * 8);
        float2 f0 = __bfloat1622float2(*(__nv_bfloat162*)&v.x);
        float2 f1 = __bfloat1622float2(*(__nv_bfloat162*)&v.y);
        float2 f2 = __bfloat1622float2(*(__nv_bfloat162*)&v.z);
        float2 f3 = __bfloat1622float2(*(__nv_bfloat162*)&v.w);
        acc[0] = fmaf(xd, f0.x, acc[0]);
        acc[1] = fmaf(xd, f0.y, acc[1]);
        acc[2] = fmaf(xd, f1.x, acc[2]);
        acc[3] = fmaf(xd, f1.y, acc[3]);
        acc[4] = fmaf(xd, f2.x, acc[4]);
        acc[5] = fmaf(xd, f2.y, acc[5]);
        acc[6] = fmaf(xd, f3.x, acc[6]);
        acc[7] = fmaf(xd, f3.y, acc[7]);
    }
#pragma unroll
    for (int i = 0; i < 8; i++) {
        acc[i] += __shfl_xor_sync(0xffffffffu, acc[i], 8);
        acc[i] += __shfl_xor_sync(0xffffffffu, acc[i], 16);
    }
    if (lane < 8) {
        float* rp = g_agg + (size_t)dst * DD + lane * 8;
#pragma unroll
        for (int i = 0; i < 8; i++) atomicAdd(rp + i, acc[i]);
    }
}

__global__ void m_kernel(const float* __restrict__ conv_b) {
    int idx = blockIdx.x * blockDim.x + threadIdx.x;
    if (idx >= NN * DD) return;
    int n = idx >> 6, d = idx & 63;
    float dv = fmaxf(g_deg[n], 1.0f);
    g_m[idx] = fmaxf(g_agg[idx] / dv + conv_b[d], 0.f);
}

__global__ void gru_elem_kernel() {
    int idx = blockIdx.x * blockDim.x + threadIdx.x;
    if (idx >= NN * DD) return;
    int n = idx >> 6, j = idx & 63;
    const float* gi = g_gi + n * GDIM;
    const float* gh = g_gh + n * GDIM;
    float r = sigmoidf_(gi[j] + gh[j]);
    float z = sigmoidf_(gi[64 + j] + gh[64 + j]);
    float nn = tanhf(gi[128 + j] + r * gh[128 + j]);
    float h = g_x[idx];
    g_x[idx] = (1.f - z) * nn + z * h;
}

__global__ void s2s_init_kernel() {
    int i = blockIdx.x * blockDim.x + threadIdx.x;
    if (i < BB * 2 * DD) g_qstar[i] = 0.f;
    if (i < BB * DD) { g_hh[i] = 0.f; g_cc[i] = 0.f; }
}

__global__ void attn_init_kernel() {
    int i = blockIdx.x * blockDim.x + threadIdx.x;
    if (i < BB * DD) g_r[i] = 0.f;
    if (i < BB) { g_emax[i] = 0u; g_asum[i] = 0.f; }
}

__global__ void lstm_kernel(const float* __restrict__ w_ih, const float* __restrict__ w_hh,
                            const float* __restrict__ b_ih, const float* __restrict__ b_hh) {
    int b = blockIdx.x, j = threadIdx.x;
    __shared__ float qs[2 * DD];
    __shared__ float hs[DD];
    __shared__ float g[LG];
    if (j < 2 * DD) qs[j] = g_qstar[b * 2 * DD + j];
    else if (j < 2 * DD + DD) hs[j - 2 * DD] = g_hh[b * DD + (j - 2 * DD)];
    __syncthreads();
    float acc = b_ih[j] + b_hh[j];
    const float* wi = w_ih + j * 2 * DD;
#pragma unroll 8
    for (int k = 0; k < 2 * DD; k++) acc += qs[k] * wi[k];
    const float* wh = w_hh + j * DD;
#pragma unroll 8
    for (int k = 0; k < DD; k++) acc += hs[k] * wh[k];
    g[j] = acc;
    __syncthreads();
    if (j < DD) {
        float ig = sigmoidf_(g[j]);
        float fg = sigmoidf_(g[DD + j]);
        float gg = tanhf(g[2 * DD + j]);
        float og = sigmoidf_(g[3 * DD + j]);
        float cn = fg * g_cc[b * DD + j] + ig * gg;
        float hn = og * tanhf(cn);
        g_cc[b * DD + j] = cn;
        g_hh[b * DD + j] = hn;
    }
}

__global__ void e_kernel(const int* __restrict__ batch) {
    int n = blockIdx.x * blockDim.x + threadIdx.x;
    if (n >= NN) return;
    int b = batch[n];
    const float4* xr = (const float4*)(g_x + n * DD);
    const float4* qr = (const float4*)(g_hh + b * DD);
    float acc = 0.f;
#pragma unroll
    for (int i = 0; i < DD / 4; i++) {
        float4 a = xr[i], q = qr[i];
        acc += a.x * q.x + a.y * q.y + a.z * q.z + a.w * q.w;
    }
    g_e[n] = acc;
    atomicMax(&g_emax[b], fenc(acc));
}

__global__ void a_kernel(const int* __restrict__ batch) {
    int n = blockIdx.x * blockDim.x + threadIdx.x;
    if (n >= NN) return;
    int b = batch[n];
    float a = expf(g_e[n] - fdec(g_emax[b]));
    g_a[n] = a;
    atomicAdd(&g_asum[b], a);
}

__global__ void r_kernel(const int* __restrict__ batch) {
    int idx = blockIdx.x * blockDim.x + threadIdx.x;
    if (idx >= NN * (DD / 4)) return;
    int n = idx >> 4, c = idx & 15;
    int b = batch[n];
    float coef = g_a[n] / g_asum[b];
    float4 v = ((const float4*)(g_x + n * DD))[c];
    float* rp = g_r + b * DD + c * 4;
    atomicAdd(rp + 0, coef * v.x);
    atomicAdd(rp + 1, coef * v.y);
    atomicAdd(rp + 2, coef * v.z);
    atomicAdd(rp + 3, coef * v.w);
}

__global__ void qstar_kernel() {
    int idx = blockIdx.x * blockDim.x + threadIdx.x;
    if (idx >= BB * DD) return;
    int b = idx >> 6, j = idx & 63;
    g_qstar[b * 2 * DD + j] = g_hh[idx];
    g_qstar[b * 2 * DD + DD + j] = g_r[idx];
}

__global__ void out_kernel(float* __restrict__ out) {
    int i = blockIdx.x * blockDim.x + threadIdx.x;
    if (i < BB * 2 * DD) out[i] = g_qstar[i];
}

// ---------------- launch --------------------------------------------------
extern "C" void kernel_launch(void* const* d_in, const int* in_sizes, int n_in,
                              void* d_out, int out_size) {
    const float* x       = (const float*)d_in[0];
    const int*   ei      = (const int*)  d_in[1];
    const float* ea      = (const float*)d_in[2];
    const int*   batch   = (const int*)  d_in[3];
    const float* lin0_w  = (const float*)d_in[4];
    const float* lin0_b  = (const float*)d_in[5];
    const float* mlp_w1  = (const float*)d_in[6];
    const float* mlp_b1  = (const float*)d_in[7];
    const float* mlp_w2  = (const float*)d_in[8];
    const float* mlp_b2  = (const float*)d_in[9];
    const float* conv_b  = (const float*)d_in[10];
    const float* gw_ih   = (const float*)d_in[11];
    const float* gw_hh   = (const float*)d_in[12];
    const float* gb_ih   = (const float*)d_in[13];
    const float* gb_hh   = (const float*)d_in[14];
    const float* lw_ih   = (const float*)d_in[15];
    const float* lw_hh   = (const float*)d_in[16];
    const float* lb_ih   = (const float*)d_in[17];
    const float* lb_hh   = (const float*)d_in[18];
    float* out = (float*)d_out;

    float *p_x, *p_agg, *p_m, *p_gi, *p_gh, *p_deg;
    cudaGetSymbolAddress((void**)&p_x, g_x);
    cudaGetSymbolAddress((void**)&p_agg, g_agg);
    cudaGetSymbolAddress((void**)&p_m, g_m);
    cudaGetSymbolAddress((void**)&p_gi, g_gi);
    cudaGetSymbolAddress((void**)&p_gh, g_gh);
    cudaGetSymbolAddress((void**)&p_deg, g_deg);

    cudaFuncSetAttribute(gemm_we, cudaFuncAttributeMaxDynamicSharedMemorySize, SM_GEMM_TOTAL);

    const int T = 256;
    // lin0
    gemm_abt<true><<<dim3(1, (NN + 63) / 64), T>>>(x, lin0_w, lin0_b, p_x, NN, DD, FIN);
    // edge MLP layer 1 (-> bf16), w2 bf16, then W_e GEMM (tensor cores)
    mlp1_kernel<<<(EPAD * 128 + T - 1) / T, T>>>(ea, mlp_w1, mlp_b1);
    w2prep_kernel<<<(WE_COLS * 128 + T - 1) / T, T>>>(mlp_w2);
    gemm_we<<<dim3(WE_COLS / 128, EPAD / 128), 256, SM_GEMM_TOTAL>>>(mlp_b2);
    // degree
    zero_f<<<(NN + T - 1) / T, T>>>(p_deg, NN);
    deg_kernel<<<(EE + T - 1) / T, T>>>(ei);

    for (int itr = 0; itr < 3; itr++) {
        zero_f<<<(NN * DD + T - 1) / T, T>>>(p_agg, NN * DD);
        msg_kernel<<<(EE + 7) / 8, 256>>>(ei);
        m_kernel<<<(NN * DD + T - 1) / T, T>>>(conv_b);
        gemm_abt<false><<<dim3(GDIM / 64, (NN + 63) / 64), T>>>(p_m, gw_ih, gb_ih, p_gi, NN, GDIM, DD);
        gemm_abt<false><<<dim3(GDIM / 64, (NN + 63) / 64), T>>>(p_x, gw_hh, gb_hh, p_gh, NN, GDIM, DD);
        gru_elem_kernel<<<(NN * DD + T - 1) / T, T>>>();
    }

    s2s_init_kernel<<<(BB * 2 * DD + T - 1) / T, T>>>();
    for (int s = 0; s < 3; s++) {
        lstm_kernel<<<BB, LG>>>(lw_ih, lw_hh, lb_ih, lb_hh);
        attn_init_kernel<<<(BB * DD + T - 1) / T, T>>>();
        e_kernel<<<(NN + T - 1) / T, T>>>(batch);
        a_kernel<<<(NN + T - 1) / T, T>>>(batch);
        r_kernel<<<(NN * (DD / 4) + T - 1) / T, T>>>(batch);
        qstar_kernel<<<(BB * DD + T - 1) / T, T>>>();
    }
    out_kernel<<<(BB * 2 * DD + T - 1) / T, T>>>(out);
}

// round 11
// speedup vs baseline: 4.1506x; 1.1598x over previous
#include <cuda_runtime.h>
#include <cuda_bf16.h>
#include <math.h>
#include <stdint.h>

// Problem dims
#define NN   20000
#define EE   50000
#define EPAD 50048          // 391 * 128
#define MPAD 20224          // 79 * 256
#define FIN  16
#define DD   64
#define BB   128
#define GDIM 192
#define LG   256
#define WE_COLS 4096

// ---------------- device scratch ----------------
__device__ float         g_x[NN * DD];
__device__ __nv_bfloat16 g_xhi[MPAD * DD];
__device__ __nv_bfloat16 g_xlo[MPAD * DD];
__device__ __nv_bfloat16 g_mhi[MPAD * DD];
__device__ __nv_bfloat16 g_mlo[MPAD * DD];
__device__ __nv_bfloat16 g_wih_hi[GDIM * DD];
__device__ __nv_bfloat16 g_wih_lo[GDIM * DD];
__device__ __nv_bfloat16 g_whh_hi[GDIM * DD];
__device__ __nv_bfloat16 g_whh_lo[GDIM * DD];
__device__ __nv_bfloat16 g_Ahi[(size_t)EPAD * 128];
__device__ __nv_bfloat16 g_Bhi[WE_COLS * 128];
__device__ __nv_bfloat16 g_We[(size_t)EPAD * WE_COLS];   // 410 MB bf16
__device__ float         g_agg[NN * DD];
__device__ float         g_gi[NN * GDIM];
__device__ float         g_gh[NN * GDIM];
__device__ float         g_deg[NN];
__device__ float         g_e[NN];
__device__ float         g_a[NN];
__device__ unsigned      g_emax[BB];
__device__ float         g_asum[BB];
__device__ float         g_hh[BB * DD];
__device__ float         g_cc[BB * DD];
__device__ float         g_qstar[BB * 2 * DD];

__device__ __forceinline__ float sigmoidf_(float x) { return 1.0f / (1.0f + expf(-x)); }
__device__ __forceinline__ unsigned fenc(float f) {
    unsigned u = __float_as_uint(f);
    return (u & 0x80000000u) ? ~u : (u | 0x80000000u);
}
__device__ __forceinline__ float fdec(unsigned u) {
    return (u & 0x80000000u) ? __uint_as_float(u & 0x7fffffffu) : __uint_as_float(~u);
}

__device__ __forceinline__ uint32_t smem_u32(const void* p) {
    uint32_t a;
    asm("{ .reg .u64 t; cvta.to.shared.u64 t, %1; cvt.u32.u64 %0, t; }" : "=r"(a) : "l"(p));
    return a;
}

__device__ __forceinline__ void mma16816(float* c, const uint32_t* a, const uint32_t* b) {
    asm volatile(
        "mma.sync.aligned.m16n8k16.row.col.f32.bf16.bf16.f32 "
        "{%0,%1,%2,%3}, {%4,%5,%6,%7}, {%8,%9}, {%0,%1,%2,%3};\n"
        : "+f"(c[0]), "+f"(c[1]), "+f"(c[2]), "+f"(c[3])
        : "r"(a[0]), "r"(a[1]), "r"(a[2]), "r"(a[3]), "r"(b[0]), "r"(b[1]));
}

__device__ __forceinline__ void ldsm4(uint32_t* r, uint32_t addr) {
    asm volatile("ldmatrix.sync.aligned.m8n8.x4.shared.b16 {%0,%1,%2,%3}, [%4];"
                 : "=r"(r[0]), "=r"(r[1]), "=r"(r[2]), "=r"(r[3]) : "r"(addr));
}

__device__ __forceinline__ void cpasync16(uint32_t saddr, const void* gaddr) {
    asm volatile("cp.async.cg.shared.global [%0], [%1], 16;" :: "r"(saddr), "l"(gaddr));
}

// ---------------- W_e GEMM (single-pass bf16, as round 9) ------------------
#define SSTRIDE 136
#define SM_A_O 0
#define SM_B_O (128 * SSTRIDE * 2)
#define SM_GEMM_TOTAL (SM_B_O + 128 * SSTRIDE * 2)   // 69632

__global__ void __launch_bounds__(256, 2)
gemm_we(const float* __restrict__ b2) {
    extern __shared__ char smem[];
    const int tid = threadIdx.x;
    const int n0 = blockIdx.x * 128;
    const int m0 = blockIdx.y * 128;
    const uint32_t sb = smem_u32(smem);

    for (int idx = tid; idx < 128 * 16; idx += 256) {
        int r = idx >> 4, p = idx & 15;
        uint32_t so = (uint32_t)(r * SSTRIDE + p * 8) * 2;
        cpasync16(sb + SM_A_O + so, g_Ahi + (size_t)(m0 + r) * 128 + p * 8);
        cpasync16(sb + SM_B_O + so, g_Bhi + (size_t)(n0 + r) * 128 + p * 8);
    }
    asm volatile("cp.async.commit_group;");
    asm volatile("cp.async.wait_group 0;");
    __syncthreads();

    const int wid = tid >> 5, lane = tid & 31;
    const int warp_m = wid & 1, warp_n = wid >> 1;
    const int g = lane >> 2, t4 = lane & 3;

    int arow = (warp_m * 64 + (lane & 15)) * SSTRIDE + ((lane >> 4) << 3);
    int brow = (warp_n * 32 + (lane & 7) + ((lane >> 4) << 3)) * SSTRIDE + (((lane >> 3) & 1) << 3);

    float acc[4][4][4];
#pragma unroll
    for (int mt = 0; mt < 4; mt++)
#pragma unroll
        for (int nt = 0; nt < 4; nt++)
#pragma unroll
            for (int q = 0; q < 4; q++) acc[mt][nt][q] = 0.f;

#pragma unroll
    for (int ks = 0; ks < 8; ks++) {
        const int k0 = ks * 16;
        uint32_t af[4][4];
#pragma unroll
        for (int mt = 0; mt < 4; mt++)
            ldsm4(af[mt], sb + SM_A_O + (arow + mt * 16 * SSTRIDE + k0) * 2);
#pragma unroll
        for (int np = 0; np < 2; np++) {
            uint32_t bf[4];
            ldsm4(bf, sb + SM_B_O + (brow + np * 16 * SSTRIDE + k0) * 2);
#pragma unroll
            for (int h = 0; h < 2; h++) {
                int nt = np * 2 + h;
#pragma unroll
                for (int mt = 0; mt < 4; mt++)
                    mma16816(acc[mt][nt], af[mt], bf + h * 2);
            }
        }
    }

    __syncthreads();
    __nv_bfloat16* cs = (__nv_bfloat16*)smem;
#pragma unroll
    for (int mt = 0; mt < 4; mt++) {
        int r0 = warp_m * 64 + mt * 16 + g;
#pragma unroll
        for (int nt = 0; nt < 4; nt++) {
            int c = warp_n * 32 + nt * 8 + t4 * 2;
            float2 bb = *(const float2*)(b2 + n0 + c);
            *(__nv_bfloat162*)(cs + r0 * SSTRIDE + c) =
                __floats2bfloat162_rn(acc[mt][nt][0] + bb.x, acc[mt][nt][1] + bb.y);
            *(__nv_bfloat162*)(cs + (r0 + 8) * SSTRIDE + c) =
                __floats2bfloat162_rn(acc[mt][nt][2] + bb.x, acc[mt][nt][3] + bb.y);
        }
    }
    __syncthreads();
    for (int idx = tid; idx < 128 * 16; idx += 256) {
        int r = idx >> 4, ch = idx & 15;
        *(uint4*)(g_We + (size_t)(m0 + r) * WE_COLS + n0 + ch * 8) =
            *(const uint4*)(cs + r * SSTRIDE + ch * 8);
    }
}

// ---------------- GRU gate GEMM: C[NN,192] = A[M,64] @ B[192,64]^T + bias
// 3-pass split bf16 (hi*hi + hi*lo + lo*hi), fp32 out.
// CTA tile 256x64, warp grid 4x2 (warp tile 64x32).
#define GSTRIDE 72
#define SG_AHI 0
#define SG_ALO (256 * GSTRIDE * 2)                   // 36864
#define SG_BHI (2 * 256 * GSTRIDE * 2)               // 73728
#define SG_BLO (SG_BHI + 64 * GSTRIDE * 2)           // 82944
#define SG_TOTAL (SG_BLO + 64 * GSTRIDE * 2)         // 92160

__global__ void __launch_bounds__(256, 2)
gemm_gates(const __nv_bfloat16* __restrict__ Ahi, const __nv_bfloat16* __restrict__ Alo,
           const __nv_bfloat16* __restrict__ Bhi, const __nv_bfloat16* __restrict__ Blo,
           const float* __restrict__ bias, float* __restrict__ C) {
    extern __shared__ char smem[];
    const int tid = threadIdx.x;
    const int n0 = blockIdx.x * 64;
    const int m0 = blockIdx.y * 256;
    const uint32_t sb = smem_u32(smem);

    for (int idx = tid; idx < 256 * 8; idx += 256) {
        int r = idx >> 3, p = idx & 7;
        uint32_t so = (uint32_t)(r * GSTRIDE + p * 8) * 2;
        cpasync16(sb + SG_AHI + so, Ahi + (size_t)(m0 + r) * 64 + p * 8);
        cpasync16(sb + SG_ALO + so, Alo + (size_t)(m0 + r) * 64 + p * 8);
    }
    for (int idx = tid; idx < 64 * 8; idx += 256) {
        int r = idx >> 3, p = idx & 7;
        uint32_t so = (uint32_t)(r * GSTRIDE + p * 8) * 2;
        cpasync16(sb + SG_BHI + so, Bhi + (size_t)(n0 + r) * 64 + p * 8);
        cpasync16(sb + SG_BLO + so, Blo + (size_t)(n0 + r) * 64 + p * 8);
    }
    asm volatile("cp.async.commit_group;");
    asm volatile("cp.async.wait_group 0;");
    __syncthreads();

    const int wid = tid >> 5, lane = tid & 31;
    const int warp_m = wid & 3, warp_n = wid >> 2;   // 4 x 2 warp grid
    const int g = lane >> 2, t4 = lane & 3;

    int arow = (warp_m * 64 + (lane & 15)) * GSTRIDE + ((lane >> 4) << 3);
    int brow = (warp_n * 32 + (lane & 7) + ((lane >> 4) << 3)) * GSTRIDE + (((lane >> 3) & 1) << 3);

    float acc[4][4][4];
#pragma unroll
    for (int mt = 0; mt < 4; mt++)
#pragma unroll
        for (int nt = 0; nt < 4; nt++)
#pragma unroll
            for (int q = 0; q < 4; q++) acc[mt][nt][q] = 0.f;

#pragma unroll
    for (int ks = 0; ks < 4; ks++) {
        const int k0 = ks * 16;
        uint32_t ahi[4][4], alo[4][4];
#pragma unroll
        for (int mt = 0; mt < 4; mt++) {
            ldsm4(ahi[mt], sb + SG_AHI + (arow + mt * 16 * GSTRIDE + k0) * 2);
            ldsm4(alo[mt], sb + SG_ALO + (arow + mt * 16 * GSTRIDE + k0) * 2);
        }
#pragma unroll
        for (int np = 0; np < 2; np++) {
            uint32_t bhi[4], blo[4];
            ldsm4(bhi, sb + SG_BHI + (brow + np * 16 * GSTRIDE + k0) * 2);
            ldsm4(blo, sb + SG_BLO + (brow + np * 16 * GSTRIDE + k0) * 2);
#pragma unroll
            for (int h = 0; h < 2; h++) {
                int nt = np * 2 + h;
#pragma unroll
                for (int mt = 0; mt < 4; mt++) {
                    mma16816(acc[mt][nt], ahi[mt], bhi + h * 2);
                    mma16816(acc[mt][nt], ahi[mt], blo + h * 2);
                    mma16816(acc[mt][nt], alo[mt], bhi + h * 2);
                }
            }
        }
    }

    // epilogue: +bias, fp32 store (guarded)
#pragma unroll
    for (int mt = 0; mt < 4; mt++) {
        int r0 = m0 + warp_m * 64 + mt * 16 + g;
#pragma unroll
        for (int nt = 0; nt < 4; nt++) {
            int n = n0 + warp_n * 32 + nt * 8 + t4 * 2;
            float2 bb = *(const float2*)(bias + n);
            if (r0 < NN)
                *(float2*)(C + (size_t)r0 * GDIM + n) =
                    make_float2(acc[mt][nt][0] + bb.x, acc[mt][nt][1] + bb.y);
            if (r0 + 8 < NN)
                *(float2*)(C + (size_t)(r0 + 8) * GDIM + n) =
                    make_float2(acc[mt][nt][2] + bb.x, acc[mt][nt][3] + bb.y);
        }
    }
}

// ---------------- SIMT GEMM (lin0 only) ------------------------------------
template<bool RELU>
__global__ void gemm_abt(const float* __restrict__ A, const float* __restrict__ B,
                         const float* __restrict__ bias, float* __restrict__ C,
                         int M, int N, int K) {
    __shared__ float As[16][65];
    __shared__ float Bs[16][65];
    int tid = threadIdx.x;
    int tx = tid & 15, ty = tid >> 4;
    int rowBase = blockIdx.y * 64;
    int colBase = blockIdx.x * 64;
    float acc[4][4] = {};
    for (int k0 = 0; k0 < K; k0 += 16) {
#pragma unroll
        for (int i = 0; i < 4; i++) {
            int e = tid + i * 256;
            int m = e >> 4, kk = e & 15;
            int r = rowBase + m, k = k0 + kk;
            As[kk][m] = (r < M && k < K) ? A[(size_t)r * K + k] : 0.f;
        }
#pragma unroll
        for (int i = 0; i < 4; i++) {
            int e = tid + i * 256;
            int n = e >> 4, kk = e & 15;
            int c = colBase + n, k = k0 + kk;
            Bs[kk][n] = (c < N && k < K) ? B[(size_t)c * K + k] : 0.f;
        }
        __syncthreads();
#pragma unroll
        for (int kk = 0; kk < 16; kk++) {
            float ra[4], rb[4];
#pragma unroll
            for (int i = 0; i < 4; i++) ra[i] = As[kk][ty * 4 + i];
#pragma unroll
            for (int j = 0; j < 4; j++) rb[j] = Bs[kk][tx * 4 + j];
#pragma unroll
            for (int i = 0; i < 4; i++)
#pragma unroll
                for (int j = 0; j < 4; j++) acc[i][j] += ra[i] * rb[j];
        }
        __syncthreads();
    }
#pragma unroll
    for (int i = 0; i < 4; i++) {
        int r = rowBase + ty * 4 + i;
        if (r >= M) continue;
#pragma unroll
        for (int j = 0; j < 4; j++) {
            int c = colBase + tx * 4 + j;
            if (c >= N) continue;
            float v = acc[i][j] + bias[c];
            if (RELU) v = fmaxf(v, 0.f);
            C[(size_t)r * N + c] = v;
        }
    }
}

// ---------------- small kernels -------------------------------------------
__global__ void init_kernel() {
    int i = blockIdx.x * blockDim.x + threadIdx.x;
    if (i < NN * DD) g_agg[i] = 0.f;
    if (i < (MPAD - NN) * DD) {
        int o = NN * DD + i;
        __nv_bfloat16 z = __float2bfloat16(0.f);
        g_mhi[o] = z; g_mlo[o] = z; g_xhi[o] = z; g_xlo[o] = z;
    }
}

__global__ void xcvt_kernel() {
    int i = blockIdx.x * blockDim.x + threadIdx.x;
    if (i >= NN * DD) return;
    float v = g_x[i];
    __nv_bfloat16 hi = __float2bfloat16(v);
    g_xhi[i] = hi;
    g_xlo[i] = __float2bfloat16(v - __bfloat162float(hi));
}

__global__ void wgru_prep(const float* __restrict__ wih, const float* __restrict__ whh) {
    int i = blockIdx.x * blockDim.x + threadIdx.x;
    if (i >= GDIM * DD) return;
    float a = wih[i];
    __nv_bfloat16 ah = __float2bfloat16(a);
    g_wih_hi[i] = ah;
    g_wih_lo[i] = __float2bfloat16(a - __bfloat162float(ah));
    float b = whh[i];
    __nv_bfloat16 bh = __float2bfloat16(b);
    g_whh_hi[i] = bh;
    g_whh_lo[i] = __float2bfloat16(b - __bfloat162float(bh));
}

__global__ void mlp1_kernel(const float* __restrict__ ea, const float* __restrict__ w1,
                            const float* __restrict__ b1) {
    int idx = blockIdx.x * blockDim.x + threadIdx.x;
    if (idx >= EPAD * 128) return;
    int e = idx >> 7, h = idx & 127;
    float acc = 0.f;
    if (e < EE) {
        acc = b1[h];
        const float* row = ea + e * 5;
        const float* w = w1 + h * 5;
#pragma unroll
        for (int k = 0; k < 5; k++) acc += row[k] * w[k];
        acc = fmaxf(acc, 0.f);
    }
    g_Ahi[idx] = __float2bfloat16(acc);
}

__global__ void w2prep_kernel(const float* __restrict__ w2) {
    int idx = blockIdx.x * blockDim.x + threadIdx.x;
    if (idx >= WE_COLS * 128) return;
    g_Bhi[idx] = __float2bfloat16(w2[idx]);
}

__global__ void deg_kernel(const int* __restrict__ ei) {
    int e = blockIdx.x * blockDim.x + threadIdx.x;
    if (e >= EE) return;
    atomicAdd(&g_deg[ei[EE + e]], 1.0f);
}

__global__ void zero_deg() {
    int i = blockIdx.x * blockDim.x + threadIdx.x;
    if (i < NN) g_deg[i] = 0.f;
}

// 8 edges per 256-thread block; one warp per edge; bf16 uint4 loads.
__global__ void __launch_bounds__(256)
msg_kernel(const int* __restrict__ ei) {
    __shared__ float xs[8][64];
    int w = threadIdx.x >> 5, lane = threadIdx.x & 31;
    int e = blockIdx.x * 8 + w;
    if (e >= EE) return;
    int src = ei[e];
    int dst = ei[EE + e];
    xs[w][lane] = g_x[src * DD + lane];
    xs[w][lane + 32] = g_x[src * DD + 32 + lane];
    __syncwarp();
    int oc = lane & 7, h = lane >> 3;
    const __nv_bfloat16* wp = g_We + (size_t)e * WE_COLS;
    float acc[8] = {0.f, 0.f, 0.f, 0.f, 0.f, 0.f, 0.f, 0.f};
#pragma unroll
    for (int s = 0; s < 16; s++) {
        int d = s * 4 + h;
        float xd = xs[w][d];
        uint4 v = *(const uint4*)(wp + d * 64 + oc * 8);
        float2 f0 = __bfloat1622float2(*(__nv_bfloat162*)&v.x);
        float2 f1 = __bfloat1622float2(*(__nv_bfloat162*)&v.y);
        float2 f2 = __bfloat1622float2(*(__nv_bfloat162*)&v.z);
        float2 f3 = __bfloat1622float2(*(__nv_bfloat162*)&v.w);
        acc[0] = fmaf(xd, f0.x, acc[0]);
        acc[1] = fmaf(xd, f0.y, acc[1]);
        acc[2] = fmaf(xd, f1.x, acc[2]);
        acc[3] = fmaf(xd, f1.y, acc[3]);
        acc[4] = fmaf(xd, f2.x, acc[4]);
        acc[5] = fmaf(xd, f2.y, acc[5]);
        acc[6] = fmaf(xd, f3.x, acc[6]);
        acc[7] = fmaf(xd, f3.y, acc[7]);
    }
#pragma unroll
    for (int i = 0; i < 8; i++) {
        acc[i] += __shfl_xor_sync(0xffffffffu, acc[i], 8);
        acc[i] += __shfl_xor_sync(0xffffffffu, acc[i], 16);
    }
    if (lane < 8) {
        float* rp = g_agg + (size_t)dst * DD + lane * 8;
#pragma unroll
        for (int i = 0; i < 8; i++) atomicAdd(rp + i, acc[i]);
    }
}

// m = relu(agg/deg + conv_b) -> bf16 hi/lo; reset agg for next iteration.
__global__ void m_kernel(const float* __restrict__ conv_b) {
    int idx = blockIdx.x * blockDim.x + threadIdx.x;
    if (idx >= NN * DD) return;
    int n = idx >> 6, d = idx & 63;
    float dv = fmaxf(g_deg[n], 1.0f);
    float m = fmaxf(g_agg[idx] / dv + conv_b[d], 0.f);
    g_agg[idx] = 0.f;
    __nv_bfloat16 hi = __float2bfloat16(m);
    g_mhi[idx] = hi;
    g_mlo[idx] = __float2bfloat16(m - __bfloat162float(hi));
}

__global__ void gru_elem_kernel() {
    int idx = blockIdx.x * blockDim.x + threadIdx.x;
    if (idx >= NN * DD) return;
    int n = idx >> 6, j = idx & 63;
    const float* gi = g_gi + (size_t)n * GDIM;
    const float* gh = g_gh + (size_t)n * GDIM;
    float r = sigmoidf_(gi[j] + gh[j]);
    float z = sigmoidf_(gi[64 + j] + gh[64 + j]);
    float nn = tanhf(gi[128 + j] + r * gh[128 + j]);
    float h = g_x[idx];
    float hnew = (1.f - z) * nn + z * h;
    g_x[idx] = hnew;
    __nv_bfloat16 hi = __float2bfloat16(hnew);
    g_xhi[idx] = hi;
    g_xlo[idx] = __float2bfloat16(hnew - __bfloat162float(hi));
}

__global__ void s2s_init_kernel() {
    int i = blockIdx.x * blockDim.x + threadIdx.x;
    if (i < BB * 2 * DD) g_qstar[i] = 0.f;
    if (i < BB * DD) { g_hh[i] = 0.f; g_cc[i] = 0.f; }
}

// LSTM cell + per-step attn init (zero emax/asum/qstar r-half)
__global__ void lstm_kernel(const float* __restrict__ w_ih, const float* __restrict__ w_hh,
                            const float* __restrict__ b_ih, const float* __restrict__ b_hh) {
    int b = blockIdx.x, j = threadIdx.x;
    __shared__ float qs[2 * DD];
    __shared__ float hs[DD];
    __shared__ float g[LG];
    if (j < 2 * DD) qs[j] = g_qstar[b * 2 * DD + j];
    else if (j < 2 * DD + DD) hs[j - 2 * DD] = g_hh[b * DD + (j - 2 * DD)];
    __syncthreads();
    float acc = b_ih[j] + b_hh[j];
    const float* wi = w_ih + j * 2 * DD;
#pragma unroll 8
    for (int k = 0; k < 2 * DD; k++) acc += qs[k] * wi[k];
    const float* wh = w_hh + j * DD;
#pragma unroll 8
    for (int k = 0; k < DD; k++) acc += hs[k] * wh[k];
    g[j] = acc;
    __syncthreads();
    if (j < DD) {
        float ig = sigmoidf_(g[j]);
        float fg = sigmoidf_(g[DD + j]);
        float gg = tanhf(g[2 * DD + j]);
        float og = sigmoidf_(g[3 * DD + j]);
        float cn = fg * g_cc[b * DD + j] + ig * gg;
        float hn = og * tanhf(cn);
        g_cc[b * DD + j] = cn;
        g_hh[b * DD + j] = hn;
        g_qstar[b * 2 * DD + j] = hn;          // q half
        g_qstar[b * 2 * DD + DD + j] = 0.f;    // r half (accumulated by r_kernel)
    } else if (j == DD) {
        g_emax[b] = 0u;
        g_asum[b] = 0.f;
    }
}

__global__ void e_kernel(const int* __restrict__ batch) {
    int n = blockIdx.x * blockDim.x + threadIdx.x;
    if (n >= NN) return;
    int b = batch[n];
    const float4* xr = (const float4*)(g_x + n * DD);
    const float4* qr = (const float4*)(g_hh + b * DD);
    float acc = 0.f;
#pragma unroll
    for (int i = 0; i < DD / 4; i++) {
        float4 a = xr[i], q = qr[i];
        acc += a.x * q.x + a.y * q.y + a.z * q.z + a.w * q.w;
    }
    g_e[n] = acc;
    atomicMax(&g_emax[b], fenc(acc));
}

__global__ void a_kernel(const int* __restrict__ batch) {
    int n = blockIdx.x * blockDim.x + threadIdx.x;
    if (n >= NN) return;
    int b = batch[n];
    float a = expf(g_e[n] - fdec(g_emax[b]));
    g_a[n] = a;
    atomicAdd(&g_asum[b], a);
}

__global__ void r_kernel(const int* __restrict__ batch) {
    int idx = blockIdx.x * blockDim.x + threadIdx.x;
    if (idx >= NN * (DD / 4)) return;
    int n = idx >> 4, c = idx & 15;
    int b = batch[n];
    float coef = g_a[n] / g_asum[b];
    float4 v = ((const float4*)(g_x + n * DD))[c];
    float* rp = g_qstar + b * 2 * DD + DD + c * 4;
    atomicAdd(rp + 0, coef * v.x);
    atomicAdd(rp + 1, coef * v.y);
    atomicAdd(rp + 2, coef * v.z);
    atomicAdd(rp + 3, coef * v.w);
}

__global__ void out_kernel(float* __restrict__ out) {
    int i = blockIdx.x * blockDim.x + threadIdx.x;
    if (i < BB * 2 * DD) out[i] = g_qstar[i];
}

// ---------------- launch --------------------------------------------------
extern "C" void kernel_launch(void* const* d_in, const int* in_sizes, int n_in,
                              void* d_out, int out_size) {
    const float* x       = (const float*)d_in[0];
    const int*   ei      = (const int*)  d_in[1];
    const float* ea      = (const float*)d_in[2];
    const int*   batch   = (const int*)  d_in[3];
    const float* lin0_w  = (const float*)d_in[4];
    const float* lin0_b  = (const float*)d_in[5];
    const float* mlp_w1  = (const float*)d_in[6];
    const float* mlp_b1  = (const float*)d_in[7];
    const float* mlp_w2  = (const float*)d_in[8];
    const float* mlp_b2  = (const float*)d_in[9];
    const float* conv_b  = (const float*)d_in[10];
    const float* gw_ih   = (const float*)d_in[11];
    const float* gw_hh   = (const float*)d_in[12];
    const float* gb_ih   = (const float*)d_in[13];
    const float* gb_hh   = (const float*)d_in[14];
    const float* lw_ih   = (const float*)d_in[15];
    const float* lw_hh   = (const float*)d_in[16];
    const float* lb_ih   = (const float*)d_in[17];
    const float* lb_hh   = (const float*)d_in[18];
    float* out = (float*)d_out;

    float *p_x, *p_gi, *p_gh;
    __nv_bfloat16 *p_xhi, *p_xlo, *p_mhi, *p_mlo, *p_wihh, *p_wihl, *p_whhh, *p_whhl;
    cudaGetSymbolAddress((void**)&p_x, g_x);
    cudaGetSymbolAddress((void**)&p_gi, g_gi);
    cudaGetSymbolAddress((void**)&p_gh, g_gh);
    cudaGetSymbolAddress((void**)&p_xhi, g_xhi);
    cudaGetSymbolAddress((void**)&p_xlo, g_xlo);
    cudaGetSymbolAddress((void**)&p_mhi, g_mhi);
    cudaGetSymbolAddress((void**)&p_mlo, g_mlo);
    cudaGetSymbolAddress((void**)&p_wihh, g_wih_hi);
    cudaGetSymbolAddress((void**)&p_wihl, g_wih_lo);
    cudaGetSymbolAddress((void**)&p_whhh, g_whh_hi);
    cudaGetSymbolAddress((void**)&p_whhl, g_whh_lo);

    cudaFuncSetAttribute(gemm_we, cudaFuncAttributeMaxDynamicSharedMemorySize, SM_GEMM_TOTAL);
    cudaFuncSetAttribute(gemm_gates, cudaFuncAttributeMaxDynamicSharedMemorySize, SG_TOTAL);

    const int T = 256;
    // lin0 + conversions + preps
    gemm_abt<true><<<dim3(1, (NN + 63) / 64), T>>>(x, lin0_w, lin0_b, p_x, NN, DD, FIN);
    xcvt_kernel<<<(NN * DD + T - 1) / T, T>>>();
    init_kernel<<<(NN * DD + T - 1) / T, T>>>();
    wgru_prep<<<(GDIM * DD + T - 1) / T, T>>>(gw_ih, gw_hh);
    mlp1_kernel<<<(EPAD * 128 + T - 1) / T, T>>>(ea, mlp_w1, mlp_b1);
    w2prep_kernel<<<(WE_COLS * 128 + T - 1) / T, T>>>(mlp_w2);
    gemm_we<<<dim3(WE_COLS / 128, EPAD / 128), 256, SM_GEMM_TOTAL>>>(mlp_b2);
    zero_deg<<<(NN + T - 1) / T, T>>>();
    deg_kernel<<<(EE + T - 1) / T, T>>>(ei);

    for (int itr = 0; itr < 3; itr++) {
        msg_kernel<<<(EE + 7) / 8, 256>>>(ei);
        m_kernel<<<(NN * DD + T - 1) / T, T>>>(conv_b);
        gemm_gates<<<dim3(GDIM / 64, MPAD / 256), 256, SG_TOTAL>>>(
            p_mhi, p_mlo, p_wihh, p_wihl, gb_ih, p_gi);
        gemm_gates<<<dim3(GDIM / 64, MPAD / 256), 256, SG_TOTAL>>>(
            p_xhi, p_xlo, p_whhh, p_whhl, gb_hh, p_gh);
        gru_elem_kernel<<<(NN * DD + T - 1) / T, T>>>();
    }

    s2s_init_kernel<<<(BB * 2 * DD + T - 1) / T, T>>>();
    for (int s = 0; s < 3; s++) {
        lstm_kernel<<<BB, LG>>>(lw_ih, lw_hh, lb_ih, lb_hh);
        e_kernel<<<(NN + T - 1) / T, T>>>(batch);
        a_kernel<<<(NN + T - 1) / T, T>>>(batch);
        r_kernel<<<(NN * (DD / 4) + T - 1) / T, T>>>(batch);
    }
    out_kernel<<<(BB * 2 * DD + T - 1) / T, T>>>(out);
}

// round 12
// speedup vs baseline: 5.0539x; 1.2177x over previous
#include <cuda_runtime.h>
#include <cuda_bf16.h>
#include <math.h>
#include <stdint.h>

// Problem dims
#define NN   20000
#define EE   50000
#define EPAD 50048          // 391 * 128
#define MPAD 20224          // 79 * 256
#define FIN  16
#define DD   64
#define BB   128
#define GDIM 192
#define LG   256
#define WE_COLS 4096

// ---------------- device scratch ----------------
__device__ float         g_x[NN * DD];
__device__ __nv_bfloat16 g_xhi[MPAD * DD];
__device__ __nv_bfloat16 g_xlo[MPAD * DD];
__device__ __nv_bfloat16 g_mhi[MPAD * DD];
__device__ __nv_bfloat16 g_mlo[MPAD * DD];
__device__ __nv_bfloat16 g_wih_hi[GDIM * DD];
__device__ __nv_bfloat16 g_wih_lo[GDIM * DD];
__device__ __nv_bfloat16 g_whh_hi[GDIM * DD];
__device__ __nv_bfloat16 g_whh_lo[GDIM * DD];
__device__ __nv_bfloat16 g_Ahi[(size_t)EPAD * 128];
__device__ __nv_bfloat16 g_Bhi[WE_COLS * 128];
__device__ __nv_bfloat16 g_We[(size_t)EPAD * WE_COLS];   // 410 MB bf16
__device__ float         g_agg[NN * DD];
__device__ float         g_gi[NN * GDIM];
__device__ float         g_gh[NN * GDIM];
__device__ float         g_deg[NN];
__device__ float         g_e[NN];
__device__ float         g_a[NN];
__device__ int           g_seg[BB + 1];
__device__ float         g_hh[BB * DD];
__device__ float         g_cc[BB * DD];
__device__ float         g_qstar[BB * 2 * DD];

__device__ __forceinline__ float sigmoidf_(float x) { return 1.0f / (1.0f + expf(-x)); }

__device__ __forceinline__ uint32_t smem_u32(const void* p) {
    uint32_t a;
    asm("{ .reg .u64 t; cvta.to.shared.u64 t, %1; cvt.u32.u64 %0, t; }" : "=r"(a) : "l"(p));
    return a;
}

__device__ __forceinline__ void mma16816(float* c, const uint32_t* a, const uint32_t* b) {
    asm volatile(
        "mma.sync.aligned.m16n8k16.row.col.f32.bf16.bf16.f32 "
        "{%0,%1,%2,%3}, {%4,%5,%6,%7}, {%8,%9}, {%0,%1,%2,%3};\n"
        : "+f"(c[0]), "+f"(c[1]), "+f"(c[2]), "+f"(c[3])
        : "r"(a[0]), "r"(a[1]), "r"(a[2]), "r"(a[3]), "r"(b[0]), "r"(b[1]));
}

__device__ __forceinline__ void ldsm4(uint32_t* r, uint32_t addr) {
    asm volatile("ldmatrix.sync.aligned.m8n8.x4.shared.b16 {%0,%1,%2,%3}, [%4];"
                 : "=r"(r[0]), "=r"(r[1]), "=r"(r[2]), "=r"(r[3]) : "r"(addr));
}

__device__ __forceinline__ void cpasync16(uint32_t saddr, const void* gaddr) {
    asm volatile("cp.async.cg.shared.global [%0], [%1], 16;" :: "r"(saddr), "l"(gaddr));
}

__device__ __forceinline__ uint4 ldcs16(const void* p) {
    uint4 v;
    asm volatile("ld.global.cs.v4.u32 {%0,%1,%2,%3}, [%4];"
                 : "=r"(v.x), "=r"(v.y), "=r"(v.z), "=r"(v.w) : "l"(p));
    return v;
}

// ---------------- W_e GEMM (single-pass bf16) ------------------------------
#define SSTRIDE 136
#define SM_A_O 0
#define SM_B_O (128 * SSTRIDE * 2)
#define SM_GEMM_TOTAL (SM_B_O + 128 * SSTRIDE * 2)   // 69632

__global__ void __launch_bounds__(256, 2)
gemm_we(const float* __restrict__ b2) {
    extern __shared__ char smem[];
    const int tid = threadIdx.x;
    const int n0 = blockIdx.x * 128;
    const int m0 = blockIdx.y * 128;
    const uint32_t sb = smem_u32(smem);

    for (int idx = tid; idx < 128 * 16; idx += 256) {
        int r = idx >> 4, p = idx & 15;
        uint32_t so = (uint32_t)(r * SSTRIDE + p * 8) * 2;
        cpasync16(sb + SM_A_O + so, g_Ahi + (size_t)(m0 + r) * 128 + p * 8);
        cpasync16(sb + SM_B_O + so, g_Bhi + (size_t)(n0 + r) * 128 + p * 8);
    }
    asm volatile("cp.async.commit_group;");
    asm volatile("cp.async.wait_group 0;");
    __syncthreads();

    const int wid = tid >> 5, lane = tid & 31;
    const int warp_m = wid & 1, warp_n = wid >> 1;
    const int g = lane >> 2, t4 = lane & 3;

    int arow = (warp_m * 64 + (lane & 15)) * SSTRIDE + ((lane >> 4) << 3);
    int brow = (warp_n * 32 + (lane & 7) + ((lane >> 4) << 3)) * SSTRIDE + (((lane >> 3) & 1) << 3);

    float acc[4][4][4];
#pragma unroll
    for (int mt = 0; mt < 4; mt++)
#pragma unroll
        for (int nt = 0; nt < 4; nt++)
#pragma unroll
            for (int q = 0; q < 4; q++) acc[mt][nt][q] = 0.f;

#pragma unroll
    for (int ks = 0; ks < 8; ks++) {
        const int k0 = ks * 16;
        uint32_t af[4][4];
#pragma unroll
        for (int mt = 0; mt < 4; mt++)
            ldsm4(af[mt], sb + SM_A_O + (arow + mt * 16 * SSTRIDE + k0) * 2);
#pragma unroll
        for (int np = 0; np < 2; np++) {
            uint32_t bf[4];
            ldsm4(bf, sb + SM_B_O + (brow + np * 16 * SSTRIDE + k0) * 2);
#pragma unroll
            for (int h = 0; h < 2; h++) {
                int nt = np * 2 + h;
#pragma unroll
                for (int mt = 0; mt < 4; mt++)
                    mma16816(acc[mt][nt], af[mt], bf + h * 2);
            }
        }
    }

    __syncthreads();
    __nv_bfloat16* cs = (__nv_bfloat16*)smem;
#pragma unroll
    for (int mt = 0; mt < 4; mt++) {
        int r0 = warp_m * 64 + mt * 16 + g;
#pragma unroll
        for (int nt = 0; nt < 4; nt++) {
            int c = warp_n * 32 + nt * 8 + t4 * 2;
            float2 bb = *(const float2*)(b2 + n0 + c);
            *(__nv_bfloat162*)(cs + r0 * SSTRIDE + c) =
                __floats2bfloat162_rn(acc[mt][nt][0] + bb.x, acc[mt][nt][1] + bb.y);
            *(__nv_bfloat162*)(cs + (r0 + 8) * SSTRIDE + c) =
                __floats2bfloat162_rn(acc[mt][nt][2] + bb.x, acc[mt][nt][3] + bb.y);
        }
    }
    __syncthreads();
    for (int idx = tid; idx < 128 * 16; idx += 256) {
        int r = idx >> 4, ch = idx & 15;
        *(uint4*)(g_We + (size_t)(m0 + r) * WE_COLS + n0 + ch * 8) =
            *(const uint4*)(cs + r * SSTRIDE + ch * 8);
    }
}

// ---------------- GRU gate GEMM (both gates in one launch, z selects) ------
#define GSTRIDE 72
#define SG_AHI 0
#define SG_ALO (256 * GSTRIDE * 2)
#define SG_BHI (2 * 256 * GSTRIDE * 2)
#define SG_BLO (SG_BHI + 64 * GSTRIDE * 2)
#define SG_TOTAL (SG_BLO + 64 * GSTRIDE * 2)         // 92160

__global__ void __launch_bounds__(256, 2)
gemm_gates(const float* __restrict__ gb_ih, const float* __restrict__ gb_hh) {
    extern __shared__ char smem[];
    const int tid = threadIdx.x;
    const int n0 = blockIdx.x * 64;
    const int m0 = blockIdx.y * 256;
    const int z = blockIdx.z;
    const uint32_t sb = smem_u32(smem);

    const __nv_bfloat16* Ahi = z ? g_xhi : g_mhi;
    const __nv_bfloat16* Alo = z ? g_xlo : g_mlo;
    const __nv_bfloat16* Bhi = z ? g_whh_hi : g_wih_hi;
    const __nv_bfloat16* Blo = z ? g_whh_lo : g_wih_lo;
    const float* bias = z ? gb_hh : gb_ih;
    float* C = z ? g_gh : g_gi;

    for (int idx = tid; idx < 256 * 8; idx += 256) {
        int r = idx >> 3, p = idx & 7;
        uint32_t so = (uint32_t)(r * GSTRIDE + p * 8) * 2;
        cpasync16(sb + SG_AHI + so, Ahi + (size_t)(m0 + r) * 64 + p * 8);
        cpasync16(sb + SG_ALO + so, Alo + (size_t)(m0 + r) * 64 + p * 8);
    }
    for (int idx = tid; idx < 64 * 8; idx += 256) {
        int r = idx >> 3, p = idx & 7;
        uint32_t so = (uint32_t)(r * GSTRIDE + p * 8) * 2;
        cpasync16(sb + SG_BHI + so, Bhi + (size_t)(n0 + r) * 64 + p * 8);
        cpasync16(sb + SG_BLO + so, Blo + (size_t)(n0 + r) * 64 + p * 8);
    }
    asm volatile("cp.async.commit_group;");
    asm volatile("cp.async.wait_group 0;");
    __syncthreads();

    const int wid = tid >> 5, lane = tid & 31;
    const int warp_m = wid & 3, warp_n = wid >> 2;
    const int g = lane >> 2, t4 = lane & 3;

    int arow = (warp_m * 64 + (lane & 15)) * GSTRIDE + ((lane >> 4) << 3);
    int brow = (warp_n * 32 + (lane & 7) + ((lane >> 4) << 3)) * GSTRIDE + (((lane >> 3) & 1) << 3);

    float acc[4][4][4];
#pragma unroll
    for (int mt = 0; mt < 4; mt++)
#pragma unroll
        for (int nt = 0; nt < 4; nt++)
#pragma unroll
            for (int q = 0; q < 4; q++) acc[mt][nt][q] = 0.f;

#pragma unroll
    for (int ks = 0; ks < 4; ks++) {
        const int k0 = ks * 16;
        uint32_t ahi[4][4], alo[4][4];
#pragma unroll
        for (int mt = 0; mt < 4; mt++) {
            ldsm4(ahi[mt], sb + SG_AHI + (arow + mt * 16 * GSTRIDE + k0) * 2);
            ldsm4(alo[mt], sb + SG_ALO + (arow + mt * 16 * GSTRIDE + k0) * 2);
        }
#pragma unroll
        for (int np = 0; np < 2; np++) {
            uint32_t bhi[4], blo[4];
            ldsm4(bhi, sb + SG_BHI + (brow + np * 16 * GSTRIDE + k0) * 2);
            ldsm4(blo, sb + SG_BLO + (brow + np * 16 * GSTRIDE + k0) * 2);
#pragma unroll
            for (int h = 0; h < 2; h++) {
                int nt = np * 2 + h;
#pragma unroll
                for (int mt = 0; mt < 4; mt++) {
                    mma16816(acc[mt][nt], ahi[mt], bhi + h * 2);
                    mma16816(acc[mt][nt], ahi[mt], blo + h * 2);
                    mma16816(acc[mt][nt], alo[mt], bhi + h * 2);
                }
            }
        }
    }

#pragma unroll
    for (int mt = 0; mt < 4; mt++) {
        int r0 = m0 + warp_m * 64 + mt * 16 + g;
#pragma unroll
        for (int nt = 0; nt < 4; nt++) {
            int n = n0 + warp_n * 32 + nt * 8 + t4 * 2;
            float2 bb = *(const float2*)(bias + n);
            if (r0 < NN)
                *(float2*)(C + (size_t)r0 * GDIM + n) =
                    make_float2(acc[mt][nt][0] + bb.x, acc[mt][nt][1] + bb.y);
            if (r0 + 8 < NN)
                *(float2*)(C + (size_t)(r0 + 8) * GDIM + n) =
                    make_float2(acc[mt][nt][2] + bb.x, acc[mt][nt][3] + bb.y);
        }
    }
}

// ---------------- SIMT GEMM (lin0 only) ------------------------------------
template<bool RELU>
__global__ void gemm_abt(const float* __restrict__ A, const float* __restrict__ B,
                         const float* __restrict__ bias, float* __restrict__ C,
                         int M, int N, int K) {
    __shared__ float As[16][65];
    __shared__ float Bs[16][65];
    int tid = threadIdx.x;
    int tx = tid & 15, ty = tid >> 4;
    int rowBase = blockIdx.y * 64;
    int colBase = blockIdx.x * 64;
    float acc[4][4] = {};
    for (int k0 = 0; k0 < K; k0 += 16) {
#pragma unroll
        for (int i = 0; i < 4; i++) {
            int e = tid + i * 256;
            int m = e >> 4, kk = e & 15;
            int r = rowBase + m, k = k0 + kk;
            As[kk][m] = (r < M && k < K) ? A[(size_t)r * K + k] : 0.f;
        }
#pragma unroll
        for (int i = 0; i < 4; i++) {
            int e = tid + i * 256;
            int n = e >> 4, kk = e & 15;
            int c = colBase + n, k = k0 + kk;
            Bs[kk][n] = (c < N && k < K) ? B[(size_t)c * K + k] : 0.f;
        }
        __syncthreads();
#pragma unroll
        for (int kk = 0; kk < 16; kk++) {
            float ra[4], rb[4];
#pragma unroll
            for (int i = 0; i < 4; i++) ra[i] = As[kk][ty * 4 + i];
#pragma unroll
            for (int j = 0; j < 4; j++) rb[j] = Bs[kk][tx * 4 + j];
#pragma unroll
            for (int i = 0; i < 4; i++)
#pragma unroll
                for (int j = 0; j < 4; j++) acc[i][j] += ra[i] * rb[j];
        }
        __syncthreads();
    }
#pragma unroll
    for (int i = 0; i < 4; i++) {
        int r = rowBase + ty * 4 + i;
        if (r >= M) continue;
#pragma unroll
        for (int j = 0; j < 4; j++) {
            int c = colBase + tx * 4 + j;
            if (c >= N) continue;
            float v = acc[i][j] + bias[c];
            if (RELU) v = fmaxf(v, 0.f);
            C[(size_t)r * N + c] = v;
        }
    }
}

// ---------------- small kernels -------------------------------------------
__global__ void init_kernel() {
    int i = blockIdx.x * blockDim.x + threadIdx.x;
    if (i < NN * DD) g_agg[i] = 0.f;
    if (i < (MPAD - NN) * DD) {
        int o = NN * DD + i;
        __nv_bfloat16 z = __float2bfloat16(0.f);
        g_mhi[o] = z; g_mlo[o] = z; g_xhi[o] = z; g_xlo[o] = z;
    }
}

__global__ void xcvt_kernel() {
    int i = blockIdx.x * blockDim.x + threadIdx.x;
    if (i >= NN * DD) return;
    float v = g_x[i];
    __nv_bfloat16 hi = __float2bfloat16(v);
    g_xhi[i] = hi;
    g_xlo[i] = __float2bfloat16(v - __bfloat162float(hi));
}

__global__ void wgru_prep(const float* __restrict__ wih, const float* __restrict__ whh) {
    int i = blockIdx.x * blockDim.x + threadIdx.x;
    if (i >= GDIM * DD) return;
    float a = wih[i];
    __nv_bfloat16 ah = __float2bfloat16(a);
    g_wih_hi[i] = ah;
    g_wih_lo[i] = __float2bfloat16(a - __bfloat162float(ah));
    float b = whh[i];
    __nv_bfloat16 bh = __float2bfloat16(b);
    g_whh_hi[i] = bh;
    g_whh_lo[i] = __float2bfloat16(b - __bfloat162float(bh));
}

__global__ void mlp1_kernel(const float* __restrict__ ea, const float* __restrict__ w1,
                            const float* __restrict__ b1) {
    int idx = blockIdx.x * blockDim.x + threadIdx.x;
    if (idx >= EPAD * 128) return;
    int e = idx >> 7, h = idx & 127;
    float acc = 0.f;
    if (e < EE) {
        acc = b1[h];
        const float* row = ea + e * 5;
        const float* w = w1 + h * 5;
#pragma unroll
        for (int k = 0; k < 5; k++) acc += row[k] * w[k];
        acc = fmaxf(acc, 0.f);
    }
    g_Ahi[idx] = __float2bfloat16(acc);
}

__global__ void w2prep_kernel(const float* __restrict__ w2) {
    int idx = blockIdx.x * blockDim.x + threadIdx.x;
    if (idx >= WE_COLS * 128) return;
    g_Bhi[idx] = __float2bfloat16(w2[idx]);
}

__global__ void deg_kernel(const int* __restrict__ ei) {
    int e = blockIdx.x * blockDim.x + threadIdx.x;
    if (e >= EE) return;
    atomicAdd(&g_deg[ei[EE + e]], 1.0f);
}

__global__ void zero_deg() {
    int i = blockIdx.x * blockDim.x + threadIdx.x;
    if (i < NN) g_deg[i] = 0.f;
}

// segment boundaries from sorted batch: g_seg[b] = first n with batch[n] >= b
__global__ void seg_kernel(const int* __restrict__ batch) {
    int b = blockIdx.x * blockDim.x + threadIdx.x;
    if (b > BB) return;
    int lo = 0, hi = NN;
    while (lo < hi) {
        int mid = (lo + hi) >> 1;
        if (batch[mid] < b) lo = mid + 1; else hi = mid;
    }
    g_seg[b] = lo;
}

// 8 edges per 256-thread block; one warp per edge; streaming (evict-first) loads.
__global__ void __launch_bounds__(256)
msg_kernel(const int* __restrict__ ei) {
    __shared__ float xs[8][64];
    int w = threadIdx.x >> 5, lane = threadIdx.x & 31;
    int e = blockIdx.x * 8 + w;
    if (e >= EE) return;
    int src = ei[e];
    int dst = ei[EE + e];
    xs[w][lane] = g_x[src * DD + lane];
    xs[w][lane + 32] = g_x[src * DD + 32 + lane];
    __syncwarp();
    int oc = lane & 7, h = lane >> 3;
    const __nv_bfloat16* wp = g_We + (size_t)e * WE_COLS;
    float acc[8] = {0.f, 0.f, 0.f, 0.f, 0.f, 0.f, 0.f, 0.f};
#pragma unroll
    for (int s = 0; s < 16; s++) {
        int d = s * 4 + h;
        float xd = xs[w][d];
        uint4 v = ldcs16(wp + d * 64 + oc * 8);
        float2 f0 = __bfloat1622float2(*(__nv_bfloat162*)&v.x);
        float2 f1 = __bfloat1622float2(*(__nv_bfloat162*)&v.y);
        float2 f2 = __bfloat1622float2(*(__nv_bfloat162*)&v.z);
        float2 f3 = __bfloat1622float2(*(__nv_bfloat162*)&v.w);
        acc[0] = fmaf(xd, f0.x, acc[0]);
        acc[1] = fmaf(xd, f0.y, acc[1]);
        acc[2] = fmaf(xd, f1.x, acc[2]);
        acc[3] = fmaf(xd, f1.y, acc[3]);
        acc[4] = fmaf(xd, f2.x, acc[4]);
        acc[5] = fmaf(xd, f2.y, acc[5]);
        acc[6] = fmaf(xd, f3.x, acc[6]);
        acc[7] = fmaf(xd, f3.y, acc[7]);
    }
#pragma unroll
    for (int i = 0; i < 8; i++) {
        acc[i] += __shfl_xor_sync(0xffffffffu, acc[i], 8);
        acc[i] += __shfl_xor_sync(0xffffffffu, acc[i], 16);
    }
    if (lane < 8) {
        float* rp = g_agg + (size_t)dst * DD + lane * 8;
#pragma unroll
        for (int i = 0; i < 8; i++) atomicAdd(rp + i, acc[i]);
    }
}

// m = relu(agg/deg + conv_b) -> bf16 hi/lo; reset agg for next iteration.
__global__ void m_kernel(const float* __restrict__ conv_b) {
    int idx = blockIdx.x * blockDim.x + threadIdx.x;
    if (idx >= NN * DD) return;
    int n = idx >> 6, d = idx & 63;
    float dv = fmaxf(g_deg[n], 1.0f);
    float m = fmaxf(g_agg[idx] / dv + conv_b[d], 0.f);
    g_agg[idx] = 0.f;
    __nv_bfloat16 hi = __float2bfloat16(m);
    g_mhi[idx] = hi;
    g_mlo[idx] = __float2bfloat16(m - __bfloat162float(hi));
}

__global__ void gru_elem_kernel() {
    int idx = blockIdx.x * blockDim.x + threadIdx.x;
    if (idx >= NN * DD) return;
    int n = idx >> 6, j = idx & 63;
    const float* gi = g_gi + (size_t)n * GDIM;
    const float* gh = g_gh + (size_t)n * GDIM;
    float r = sigmoidf_(gi[j] + gh[j]);
    float z = sigmoidf_(gi[64 + j] + gh[64 + j]);
    float nn = tanhf(gi[128 + j] + r * gh[128 + j]);
    float h = g_x[idx];
    float hnew = (1.f - z) * nn + z * h;
    g_x[idx] = hnew;
    __nv_bfloat16 hi = __float2bfloat16(hnew);
    g_xhi[idx] = hi;
    g_xlo[idx] = __float2bfloat16(hnew - __bfloat162float(hi));
}

__global__ void s2s_init_kernel() {
    int i = blockIdx.x * blockDim.x + threadIdx.x;
    if (i < BB * 2 * DD) g_qstar[i] = 0.f;
    if (i < BB * DD) { g_hh[i] = 0.f; g_cc[i] = 0.f; }
}

// One fused Set2Set step: LSTM cell + segmented softmax attention per graph.
__global__ void __launch_bounds__(256)
s2s_step(const float* __restrict__ w_ih, const float* __restrict__ w_hh,
         const float* __restrict__ b_ih, const float* __restrict__ b_hh) {
    int b = blockIdx.x, tid = threadIdx.x;
    int lane = tid & 31, wrp = tid >> 5;
    __shared__ float qs[2 * DD];
    __shared__ float hsold[DD];
    __shared__ float g[LG];
    __shared__ float qnew[DD];
    __shared__ float red[8];
    __shared__ float rpart[16][DD];

    if (tid < 2 * DD) qs[tid] = g_qstar[b * 2 * DD + tid];
    else if (tid < 2 * DD + DD) hsold[tid - 2 * DD] = g_hh[b * DD + (tid - 2 * DD)];
    __syncthreads();

    // LSTM gates
    {
        float acc = b_ih[tid] + b_hh[tid];
        const float* wi = w_ih + tid * 2 * DD;
#pragma unroll 8
        for (int k = 0; k < 2 * DD; k++) acc += qs[k] * wi[k];
        const float* wh = w_hh + tid * DD;
#pragma unroll 8
        for (int k = 0; k < DD; k++) acc += hsold[k] * wh[k];
        g[tid] = acc;
    }
    __syncthreads();
    if (tid < DD) {
        float ig = sigmoidf_(g[tid]);
        float fg = sigmoidf_(g[DD + tid]);
        float gg = tanhf(g[2 * DD + tid]);
        float og = sigmoidf_(g[3 * DD + tid]);
        float cn = fg * g_cc[b * DD + tid] + ig * gg;
        float hn = og * tanhf(cn);
        g_cc[b * DD + tid] = cn;
        g_hh[b * DD + tid] = hn;
        qnew[tid] = hn;
        g_qstar[b * 2 * DD + tid] = hn;
    }
    __syncthreads();

    int s0 = g_seg[b], s1 = g_seg[b + 1];

    // pass 1: e = x.q, block max
    float lmax = -3.4e38f;
    for (int n = s0 + tid; n < s1; n += 256) {
        const float4* xr = (const float4*)(g_x + (size_t)n * DD);
        const float4* qr = (const float4*)qnew;
        float acc = 0.f;
#pragma unroll
        for (int i = 0; i < DD / 4; i++) {
            float4 a = xr[i], q = qr[i];
            acc += a.x * q.x + a.y * q.y + a.z * q.z + a.w * q.w;
        }
        g_e[n] = acc;
        lmax = fmaxf(lmax, acc);
    }
#pragma unroll
    for (int o = 16; o > 0; o >>= 1) lmax = fmaxf(lmax, __shfl_xor_sync(0xffffffffu, lmax, o));
    if (lane == 0) red[wrp] = lmax;
    __syncthreads();
    float emax = fmaxf(fmaxf(fmaxf(red[0], red[1]), fmaxf(red[2], red[3])),
                       fmaxf(fmaxf(red[4], red[5]), fmaxf(red[6], red[7])));
    __syncthreads();

    // pass 2: a = exp(e - emax), block sum
    float lsum = 0.f;
    for (int n = s0 + tid; n < s1; n += 256) {
        float a = expf(g_e[n] - emax);
        g_a[n] = a;
        lsum += a;
    }
#pragma unroll
    for (int o = 16; o > 0; o >>= 1) lsum += __shfl_xor_sync(0xffffffffu, lsum, o);
    if (lane == 0) red[wrp] = lsum;
    __syncthreads();
    float asum = red[0] + red[1] + red[2] + red[3] + red[4] + red[5] + red[6] + red[7];
    __syncthreads();

    // pass 3: r = sum a/asum * x, 16 row-groups x 16 col-quads
    int rowg = tid >> 4, o4 = tid & 15;
    float4 racc = make_float4(0.f, 0.f, 0.f, 0.f);
    for (int n = s0 + rowg; n < s1; n += 16) {
        float c = g_a[n] / asum;
        float4 v = ((const float4*)(g_x + (size_t)n * DD))[o4];
        racc.x = fmaf(c, v.x, racc.x);
        racc.y = fmaf(c, v.y, racc.y);
        racc.z = fmaf(c, v.z, racc.z);
        racc.w = fmaf(c, v.w, racc.w);
    }
    *(float4*)(&rpart[rowg][o4 * 4]) = racc;
    __syncthreads();
    if (tid < DD) {
        float s = 0.f;
#pragma unroll
        for (int r = 0; r < 16; r++) s += rpart[r][tid];
        g_qstar[b * 2 * DD + DD + tid] = s;
    }
}

__global__ void out_kernel(float* __restrict__ out) {
    int i = blockIdx.x * blockDim.x + threadIdx.x;
    if (i < BB * 2 * DD) out[i] = g_qstar[i];
}

// ---------------- launch --------------------------------------------------
extern "C" void kernel_launch(void* const* d_in, const int* in_sizes, int n_in,
                              void* d_out, int out_size) {
    const float* x       = (const float*)d_in[0];
    const int*   ei      = (const int*)  d_in[1];
    const float* ea      = (const float*)d_in[2];
    const int*   batch   = (const int*)  d_in[3];
    const float* lin0_w  = (const float*)d_in[4];
    const float* lin0_b  = (const float*)d_in[5];
    const float* mlp_w1  = (const float*)d_in[6];
    const float* mlp_b1  = (const float*)d_in[7];
    const float* mlp_w2  = (const float*)d_in[8];
    const float* mlp_b2  = (const float*)d_in[9];
    const float* conv_b  = (const float*)d_in[10];
    const float* gw_ih   = (const float*)d_in[11];
    const float* gw_hh   = (const float*)d_in[12];
    const float* gb_ih   = (const float*)d_in[13];
    const float* gb_hh   = (const float*)d_in[14];
    const float* lw_ih   = (const float*)d_in[15];
    const float* lw_hh   = (const float*)d_in[16];
    const float* lb_ih   = (const float*)d_in[17];
    const float* lb_hh   = (const float*)d_in[18];
    float* out = (float*)d_out;

    float* p_x;
    cudaGetSymbolAddress((void**)&p_x, g_x);

    cudaFuncSetAttribute(gemm_we, cudaFuncAttributeMaxDynamicSharedMemorySize, SM_GEMM_TOTAL);
    cudaFuncSetAttribute(gemm_gates, cudaFuncAttributeMaxDynamicSharedMemorySize, SG_TOTAL);

    const int T = 256;
    gemm_abt<true><<<dim3(1, (NN + 63) / 64), T>>>(x, lin0_w, lin0_b, p_x, NN, DD, FIN);
    xcvt_kernel<<<(NN * DD + T - 1) / T, T>>>();
    init_kernel<<<(NN * DD + T - 1) / T, T>>>();
    wgru_prep<<<(GDIM * DD + T - 1) / T, T>>>(gw_ih, gw_hh);
    mlp1_kernel<<<(EPAD * 128 + T - 1) / T, T>>>(ea, mlp_w1, mlp_b1);
    w2prep_kernel<<<(WE_COLS * 128 + T - 1) / T, T>>>(mlp_w2);
    gemm_we<<<dim3(WE_COLS / 128, EPAD / 128), 256, SM_GEMM_TOTAL>>>(mlp_b2);
    zero_deg<<<(NN + T - 1) / T, T>>>();
    deg_kernel<<<(EE + T - 1) / T, T>>>(ei);
    seg_kernel<<<1, BB + 1>>>(batch);

    for (int itr = 0; itr < 3; itr++) {
        msg_kernel<<<(EE + 7) / 8, 256>>>(ei);
        m_kernel<<<(NN * DD + T - 1) / T, T>>>(conv_b);
        gemm_gates<<<dim3(GDIM / 64, MPAD / 256, 2), 256, SG_TOTAL>>>(gb_ih, gb_hh);
        gru_elem_kernel<<<(NN * DD + T - 1) / T, T>>>();
    }

    s2s_init_kernel<<<(BB * 2 * DD + T - 1) / T, T>>>();
    for (int s = 0; s < 3; s++)
        s2s_step<<<BB, LG>>>(lw_ih, lw_hh, lb_ih, lb_hh);
    out_kernel<<<(BB * 2 * DD + T - 1) / T, T>>>(out);
}

// round 13
// speedup vs baseline: 5.1952x; 1.0280x over previous
#include <cuda_runtime.h>
#include <cuda_bf16.h>
#include <math.h>
#include <stdint.h>

// Problem dims
#define NN   20000
#define EE   50000
#define EPAD 50048          // 391 * 128
#define MPAD 20224          // 79 * 256
#define FIN  16
#define DD   64
#define BB   128
#define GDIM 192
#define LG   256
#define WE_COLS 4096

// ---------------- device scratch ----------------
__device__ float         g_x[NN * DD];
__device__ __nv_bfloat16 g_xhi[MPAD * DD];
__device__ __nv_bfloat16 g_xlo[MPAD * DD];
__device__ __nv_bfloat16 g_mhi[MPAD * DD];
__device__ __nv_bfloat16 g_mlo[MPAD * DD];
__device__ __nv_bfloat16 g_wih_hi[GDIM * DD];
__device__ __nv_bfloat16 g_wih_lo[GDIM * DD];
__device__ __nv_bfloat16 g_whh_hi[GDIM * DD];
__device__ __nv_bfloat16 g_whh_lo[GDIM * DD];
__device__ __nv_bfloat16 g_Ahi[(size_t)EPAD * 128];
__device__ __nv_bfloat16 g_Bhi[WE_COLS * 128];
__device__ __nv_bfloat16 g_We[(size_t)EPAD * WE_COLS];   // 410 MB bf16
__device__ float         g_agg[NN * DD];
__device__ float         g_gi[NN * GDIM];
__device__ float         g_gh[NN * GDIM];
__device__ float         g_deg[NN];
__device__ float         g_e[NN];
__device__ float         g_a[NN];
__device__ int           g_seg[BB + 1];
__device__ float         g_hh[BB * DD];
__device__ float         g_cc[BB * DD];
__device__ float         g_qstar[BB * 2 * DD];

__device__ __forceinline__ float sigmoidf_(float x) { return 1.0f / (1.0f + expf(-x)); }

__device__ __forceinline__ uint32_t smem_u32(const void* p) {
    uint32_t a;
    asm("{ .reg .u64 t; cvta.to.shared.u64 t, %1; cvt.u32.u64 %0, t; }" : "=r"(a) : "l"(p));
    return a;
}

__device__ __forceinline__ void mma16816(float* c, const uint32_t* a, const uint32_t* b) {
    asm volatile(
        "mma.sync.aligned.m16n8k16.row.col.f32.bf16.bf16.f32 "
        "{%0,%1,%2,%3}, {%4,%5,%6,%7}, {%8,%9}, {%0,%1,%2,%3};\n"
        : "+f"(c[0]), "+f"(c[1]), "+f"(c[2]), "+f"(c[3])
        : "r"(a[0]), "r"(a[1]), "r"(a[2]), "r"(a[3]), "r"(b[0]), "r"(b[1]));
}

__device__ __forceinline__ void ldsm4(uint32_t* r, uint32_t addr) {
    asm volatile("ldmatrix.sync.aligned.m8n8.x4.shared.b16 {%0,%1,%2,%3}, [%4];"
                 : "=r"(r[0]), "=r"(r[1]), "=r"(r[2]), "=r"(r[3]) : "r"(addr));
}

__device__ __forceinline__ void cpasync16(uint32_t saddr, const void* gaddr) {
    asm volatile("cp.async.cg.shared.global [%0], [%1], 16;" :: "r"(saddr), "l"(gaddr));
}

__device__ __forceinline__ uint4 ldcs16(const void* p) {
    uint4 v;
    asm volatile("ld.global.cs.v4.u32 {%0,%1,%2,%3}, [%4];"
                 : "=r"(v.x), "=r"(v.y), "=r"(v.z), "=r"(v.w) : "l"(p));
    return v;
}

// ---------------- W_e GEMM (single-pass bf16) ------------------------------
// CTA tile 128x128, 4 warps, warp grid 2x2, warp tile 64x64 (fragment reuse).
#define SSTRIDE 136
#define SM_A_O 0
#define SM_B_O (128 * SSTRIDE * 2)
#define SM_GEMM_TOTAL (SM_B_O + 128 * SSTRIDE * 2)   // 69632

__global__ void __launch_bounds__(128, 2)
gemm_we(const float* __restrict__ b2) {
    extern __shared__ char smem[];
    const int tid = threadIdx.x;
    const int n0 = blockIdx.x * 128;
    const int m0 = blockIdx.y * 128;
    const uint32_t sb = smem_u32(smem);

    for (int idx = tid; idx < 128 * 16; idx += 128) {
        int r = idx >> 4, p = idx & 15;
        uint32_t so = (uint32_t)(r * SSTRIDE + p * 8) * 2;
        cpasync16(sb + SM_A_O + so, g_Ahi + (size_t)(m0 + r) * 128 + p * 8);
        cpasync16(sb + SM_B_O + so, g_Bhi + (size_t)(n0 + r) * 128 + p * 8);
    }
    asm volatile("cp.async.commit_group;");
    asm volatile("cp.async.wait_group 0;");
    __syncthreads();

    const int wid = tid >> 5, lane = tid & 31;
    const int warp_m = wid & 1, warp_n = wid >> 1;   // 2 x 2 warp grid
    const int g = lane >> 2, t4 = lane & 3;

    int arow = (warp_m * 64 + (lane & 15)) * SSTRIDE + ((lane >> 4) << 3);
    int brow = (warp_n * 64 + (lane & 7) + ((lane >> 4) << 3)) * SSTRIDE + (((lane >> 3) & 1) << 3);

    float acc[4][8][4];
#pragma unroll
    for (int mt = 0; mt < 4; mt++)
#pragma unroll
        for (int nt = 0; nt < 8; nt++)
#pragma unroll
            for (int q = 0; q < 4; q++) acc[mt][nt][q] = 0.f;

#pragma unroll
    for (int ks = 0; ks < 8; ks++) {
        const int k0 = ks * 16;
        uint32_t af[4][4];
#pragma unroll
        for (int mt = 0; mt < 4; mt++)
            ldsm4(af[mt], sb + SM_A_O + (arow + mt * 16 * SSTRIDE + k0) * 2);
#pragma unroll
        for (int np = 0; np < 4; np++) {
            uint32_t bf[4];
            ldsm4(bf, sb + SM_B_O + (brow + np * 16 * SSTRIDE + k0) * 2);
#pragma unroll
            for (int h = 0; h < 2; h++) {
                int nt = np * 2 + h;
#pragma unroll
                for (int mt = 0; mt < 4; mt++)
                    mma16816(acc[mt][nt], af[mt], bf + h * 2);
            }
        }
    }

    __syncthreads();
    __nv_bfloat16* cs = (__nv_bfloat16*)smem;
#pragma unroll
    for (int mt = 0; mt < 4; mt++) {
        int r0 = warp_m * 64 + mt * 16 + g;
#pragma unroll
        for (int nt = 0; nt < 8; nt++) {
            int c = warp_n * 64 + nt * 8 + t4 * 2;
            float2 bb = *(const float2*)(b2 + n0 + c);
            *(__nv_bfloat162*)(cs + r0 * SSTRIDE + c) =
                __floats2bfloat162_rn(acc[mt][nt][0] + bb.x, acc[mt][nt][1] + bb.y);
            *(__nv_bfloat162*)(cs + (r0 + 8) * SSTRIDE + c) =
                __floats2bfloat162_rn(acc[mt][nt][2] + bb.x, acc[mt][nt][3] + bb.y);
        }
    }
    __syncthreads();
    for (int idx = tid; idx < 128 * 16; idx += 128) {
        int r = idx >> 4, ch = idx & 15;
        *(uint4*)(g_We + (size_t)(m0 + r) * WE_COLS + n0 + ch * 8) =
            *(const uint4*)(cs + r * SSTRIDE + ch * 8);
    }
}

// ---------------- GRU gate GEMM (both gates in one launch, z selects) ------
#define GSTRIDE 72
#define SG_AHI 0
#define SG_ALO (256 * GSTRIDE * 2)
#define SG_BHI (2 * 256 * GSTRIDE * 2)
#define SG_BLO (SG_BHI + 64 * GSTRIDE * 2)
#define SG_TOTAL (SG_BLO + 64 * GSTRIDE * 2)         // 92160

__global__ void __launch_bounds__(256, 2)
gemm_gates(const float* __restrict__ gb_ih, const float* __restrict__ gb_hh) {
    extern __shared__ char smem[];
    const int tid = threadIdx.x;
    const int n0 = blockIdx.x * 64;
    const int m0 = blockIdx.y * 256;
    const int z = blockIdx.z;
    const uint32_t sb = smem_u32(smem);

    const __nv_bfloat16* Ahi = z ? g_xhi : g_mhi;
    const __nv_bfloat16* Alo = z ? g_xlo : g_mlo;
    const __nv_bfloat16* Bhi = z ? g_whh_hi : g_wih_hi;
    const __nv_bfloat16* Blo = z ? g_whh_lo : g_wih_lo;
    const float* bias = z ? gb_hh : gb_ih;
    float* C = z ? g_gh : g_gi;

    for (int idx = tid; idx < 256 * 8; idx += 256) {
        int r = idx >> 3, p = idx & 7;
        uint32_t so = (uint32_t)(r * GSTRIDE + p * 8) * 2;
        cpasync16(sb + SG_AHI + so, Ahi + (size_t)(m0 + r) * 64 + p * 8);
        cpasync16(sb + SG_ALO + so, Alo + (size_t)(m0 + r) * 64 + p * 8);
    }
    for (int idx = tid; idx < 64 * 8; idx += 256) {
        int r = idx >> 3, p = idx & 7;
        uint32_t so = (uint32_t)(r * GSTRIDE + p * 8) * 2;
        cpasync16(sb + SG_BHI + so, Bhi + (size_t)(n0 + r) * 64 + p * 8);
        cpasync16(sb + SG_BLO + so, Blo + (size_t)(n0 + r) * 64 + p * 8);
    }
    asm volatile("cp.async.commit_group;");
    asm volatile("cp.async.wait_group 0;");
    __syncthreads();

    const int wid = tid >> 5, lane = tid & 31;
    const int warp_m = wid & 3, warp_n = wid >> 2;
    const int g = lane >> 2, t4 = lane & 3;

    int arow = (warp_m * 64 + (lane & 15)) * GSTRIDE + ((lane >> 4) << 3);
    int brow = (warp_n * 32 + (lane & 7) + ((lane >> 4) << 3)) * GSTRIDE + (((lane >> 3) & 1) << 3);

    float acc[4][4][4];
#pragma unroll
    for (int mt = 0; mt < 4; mt++)
#pragma unroll
        for (int nt = 0; nt < 4; nt++)
#pragma unroll
            for (int q = 0; q < 4; q++) acc[mt][nt][q] = 0.f;

#pragma unroll
    for (int ks = 0; ks < 4; ks++) {
        const int k0 = ks * 16;
        uint32_t ahi[4][4], alo[4][4];
#pragma unroll
        for (int mt = 0; mt < 4; mt++) {
            ldsm4(ahi[mt], sb + SG_AHI + (arow + mt * 16 * GSTRIDE + k0) * 2);
            ldsm4(alo[mt], sb + SG_ALO + (arow + mt * 16 * GSTRIDE + k0) * 2);
        }
#pragma unroll
        for (int np = 0; np < 2; np++) {
            uint32_t bhi[4], blo[4];
            ldsm4(bhi, sb + SG_BHI + (brow + np * 16 * GSTRIDE + k0) * 2);
            ldsm4(blo, sb + SG_BLO + (brow + np * 16 * GSTRIDE + k0) * 2);
#pragma unroll
            for (int h = 0; h < 2; h++) {
                int nt = np * 2 + h;
#pragma unroll
                for (int mt = 0; mt < 4; mt++) {
                    mma16816(acc[mt][nt], ahi[mt], bhi + h * 2);
                    mma16816(acc[mt][nt], ahi[mt], blo + h * 2);
                    mma16816(acc[mt][nt], alo[mt], bhi + h * 2);
                }
            }
        }
    }

#pragma unroll
    for (int mt = 0; mt < 4; mt++) {
        int r0 = m0 + warp_m * 64 + mt * 16 + g;
#pragma unroll
        for (int nt = 0; nt < 4; nt++) {
            int n = n0 + warp_n * 32 + nt * 8 + t4 * 2;
            float2 bb = *(const float2*)(bias + n);
            if (r0 < NN)
                *(float2*)(C + (size_t)r0 * GDIM + n) =
                    make_float2(acc[mt][nt][0] + bb.x, acc[mt][nt][1] + bb.y);
            if (r0 + 8 < NN)
                *(float2*)(C + (size_t)(r0 + 8) * GDIM + n) =
                    make_float2(acc[mt][nt][2] + bb.x, acc[mt][nt][3] + bb.y);
        }
    }
}

// ---------------- lin0 GEMM (SIMT, fused relu + bf16 hi/lo conversion) -----
__global__ void lin0_kernel(const float* __restrict__ A, const float* __restrict__ B,
                            const float* __restrict__ bias) {
    __shared__ float As[16][65];
    __shared__ float Bs[16][65];
    int tid = threadIdx.x;
    int tx = tid & 15, ty = tid >> 4;
    int rowBase = blockIdx.y * 64;
    float acc[4][4] = {};
    for (int k0 = 0; k0 < FIN; k0 += 16) {
#pragma unroll
        for (int i = 0; i < 4; i++) {
            int e = tid + i * 256;
            int m = e >> 4, kk = e & 15;
            int r = rowBase + m, k = k0 + kk;
            As[kk][m] = (r < NN && k < FIN) ? A[(size_t)r * FIN + k] : 0.f;
        }
#pragma unroll
        for (int i = 0; i < 4; i++) {
            int e = tid + i * 256;
            int n = e >> 4, kk = e & 15;
            int k = k0 + kk;
            Bs[kk][n] = (k < FIN) ? B[(size_t)n * FIN + k] : 0.f;
        }
        __syncthreads();
#pragma unroll
        for (int kk = 0; kk < 16; kk++) {
            float ra[4], rb[4];
#pragma unroll
            for (int i = 0; i < 4; i++) ra[i] = As[kk][ty * 4 + i];
#pragma unroll
            for (int j = 0; j < 4; j++) rb[j] = Bs[kk][tx * 4 + j];
#pragma unroll
            for (int i = 0; i < 4; i++)
#pragma unroll
                for (int j = 0; j < 4; j++) acc[i][j] += ra[i] * rb[j];
        }
        __syncthreads();
    }
#pragma unroll
    for (int i = 0; i < 4; i++) {
        int r = rowBase + ty * 4 + i;
        if (r >= NN) continue;
#pragma unroll
        for (int j = 0; j < 4; j++) {
            int c = tx * 4 + j;
            float v = fmaxf(acc[i][j] + bias[c], 0.f);
            int idx = r * DD + c;
            g_x[idx] = v;
            __nv_bfloat16 hi = __float2bfloat16(v);
            g_xhi[idx] = hi;
            g_xlo[idx] = __float2bfloat16(v - __bfloat162float(hi));
        }
    }
}

// ---------------- setup: agg zero, bf16 padding, GRU weight split, deg, seg
__global__ void setup_kernel(const float* __restrict__ wih, const float* __restrict__ whh,
                             const int* __restrict__ batch) {
    int i = blockIdx.x * blockDim.x + threadIdx.x;
    if (i < NN * DD) g_agg[i] = 0.f;
    if (i < (MPAD - NN) * DD) {
        int o = NN * DD + i;
        __nv_bfloat16 z = __float2bfloat16(0.f);
        g_mhi[o] = z; g_mlo[o] = z; g_xhi[o] = z; g_xlo[o] = z;
    }
    if (i < GDIM * DD) {
        float a = wih[i];
        __nv_bfloat16 ah = __float2bfloat16(a);
        g_wih_hi[i] = ah;
        g_wih_lo[i] = __float2bfloat16(a - __bfloat162float(ah));
        float b = whh[i];
        __nv_bfloat16 bh = __float2bfloat16(b);
        g_whh_hi[i] = bh;
        g_whh_lo[i] = __float2bfloat16(b - __bfloat162float(bh));
    }
    if (i < NN) g_deg[i] = 0.f;
    if (i <= BB) {
        int lo = 0, hi = NN;
        while (lo < hi) {
            int mid = (lo + hi) >> 1;
            if (batch[mid] < i) lo = mid + 1; else hi = mid;
        }
        g_seg[i] = lo;
    }
}

__global__ void mlp1_kernel(const float* __restrict__ ea, const float* __restrict__ w1,
                            const float* __restrict__ b1) {
    int idx = blockIdx.x * blockDim.x + threadIdx.x;
    if (idx >= EPAD * 128) return;
    int e = idx >> 7, h = idx & 127;
    float acc = 0.f;
    if (e < EE) {
        acc = b1[h];
        const float* row = ea + e * 5;
        const float* w = w1 + h * 5;
#pragma unroll
        for (int k = 0; k < 5; k++) acc += row[k] * w[k];
        acc = fmaxf(acc, 0.f);
    }
    g_Ahi[idx] = __float2bfloat16(acc);
}

__global__ void w2prep_kernel(const float* __restrict__ w2) {
    int idx = blockIdx.x * blockDim.x + threadIdx.x;
    if (idx >= WE_COLS * 128) return;
    g_Bhi[idx] = __float2bfloat16(w2[idx]);
}

__global__ void deg_kernel(const int* __restrict__ ei) {
    int e = blockIdx.x * blockDim.x + threadIdx.x;
    if (e >= EE) return;
    atomicAdd(&g_deg[ei[EE + e]], 1.0f);
}

// 8 edges per 256-thread block; one warp per edge; streaming (evict-first) loads.
__global__ void __launch_bounds__(256)
msg_kernel(const int* __restrict__ ei) {
    __shared__ float xs[8][64];
    int w = threadIdx.x >> 5, lane = threadIdx.x & 31;
    int e = blockIdx.x * 8 + w;
    if (e >= EE) return;
    int src = ei[e];
    int dst = ei[EE + e];
    xs[w][lane] = g_x[src * DD + lane];
    xs[w][lane + 32] = g_x[src * DD + 32 + lane];
    __syncwarp();
    int oc = lane & 7, h = lane >> 3;
    const __nv_bfloat16* wp = g_We + (size_t)e * WE_COLS;
    float acc[8] = {0.f, 0.f, 0.f, 0.f, 0.f, 0.f, 0.f, 0.f};
#pragma unroll
    for (int s = 0; s < 16; s++) {
        int d = s * 4 + h;
        float xd = xs[w][d];
        uint4 v = ldcs16(wp + d * 64 + oc * 8);
        float2 f0 = __bfloat1622float2(*(__nv_bfloat162*)&v.x);
        float2 f1 = __bfloat1622float2(*(__nv_bfloat162*)&v.y);
        float2 f2 = __bfloat1622float2(*(__nv_bfloat162*)&v.z);
        float2 f3 = __bfloat1622float2(*(__nv_bfloat162*)&v.w);
        acc[0] = fmaf(xd, f0.x, acc[0]);
        acc[1] = fmaf(xd, f0.y, acc[1]);
        acc[2] = fmaf(xd, f1.x, acc[2]);
        acc[3] = fmaf(xd, f1.y, acc[3]);
        acc[4] = fmaf(xd, f2.x, acc[4]);
        acc[5] = fmaf(xd, f2.y, acc[5]);
        acc[6] = fmaf(xd, f3.x, acc[6]);
        acc[7] = fmaf(xd, f3.y, acc[7]);
    }
#pragma unroll
    for (int i = 0; i < 8; i++) {
        acc[i] += __shfl_xor_sync(0xffffffffu, acc[i], 8);
        acc[i] += __shfl_xor_sync(0xffffffffu, acc[i], 16);
    }
    if (lane < 8) {
        float* rp = g_agg + (size_t)dst * DD + lane * 8;
#pragma unroll
        for (int i = 0; i < 8; i++) atomicAdd(rp + i, acc[i]);
    }
}

// m = relu(agg/deg + conv_b) -> bf16 hi/lo; reset agg for next iteration.
__global__ void m_kernel(const float* __restrict__ conv_b) {
    int idx = blockIdx.x * blockDim.x + threadIdx.x;
    if (idx >= NN * DD) return;
    int n = idx >> 6, d = idx & 63;
    float dv = fmaxf(g_deg[n], 1.0f);
    float m = fmaxf(g_agg[idx] / dv + conv_b[d], 0.f);
    g_agg[idx] = 0.f;
    __nv_bfloat16 hi = __float2bfloat16(m);
    g_mhi[idx] = hi;
    g_mlo[idx] = __float2bfloat16(m - __bfloat162float(hi));
}

__global__ void gru_elem_kernel() {
    int idx = blockIdx.x * blockDim.x + threadIdx.x;
    if (idx >= NN * DD) return;
    int n = idx >> 6, j = idx & 63;
    const float* gi = g_gi + (size_t)n * GDIM;
    const float* gh = g_gh + (size_t)n * GDIM;
    float r = sigmoidf_(gi[j] + gh[j]);
    float z = sigmoidf_(gi[64 + j] + gh[64 + j]);
    float nn = tanhf(gi[128 + j] + r * gh[128 + j]);
    float h = g_x[idx];
    float hnew = (1.f - z) * nn + z * h;
    g_x[idx] = hnew;
    __nv_bfloat16 hi = __float2bfloat16(hnew);
    g_xhi[idx] = hi;
    g_xlo[idx] = __float2bfloat16(hnew - __bfloat162float(hi));
}

__global__ void s2s_init_kernel() {
    int i = blockIdx.x * blockDim.x + threadIdx.x;
    if (i < BB * 2 * DD) g_qstar[i] = 0.f;
    if (i < BB * DD) { g_hh[i] = 0.f; g_cc[i] = 0.f; }
}

// One fused Set2Set step: LSTM cell + segmented softmax attention per graph.
__global__ void __launch_bounds__(256)
s2s_step(const float* __restrict__ w_ih, const float* __restrict__ w_hh,
         const float* __restrict__ b_ih, const float* __restrict__ b_hh) {
    int b = blockIdx.x, tid = threadIdx.x;
    int lane = tid & 31, wrp = tid >> 5;
    __shared__ float qs[2 * DD];
    __shared__ float hsold[DD];
    __shared__ float g[LG];
    __shared__ float qnew[DD];
    __shared__ float red[8];
    __shared__ float rpart[16][DD];

    if (tid < 2 * DD) qs[tid] = g_qstar[b * 2 * DD + tid];
    else if (tid < 2 * DD + DD) hsold[tid - 2 * DD] = g_hh[b * DD + (tid - 2 * DD)];
    __syncthreads();

    {
        float acc = b_ih[tid] + b_hh[tid];
        const float* wi = w_ih + tid * 2 * DD;
#pragma unroll 8
        for (int k = 0; k < 2 * DD; k++) acc += qs[k] * wi[k];
        const float* wh = w_hh + tid * DD;
#pragma unroll 8
        for (int k = 0; k < DD; k++) acc += hsold[k] * wh[k];
        g[tid] = acc;
    }
    __syncthreads();
    if (tid < DD) {
        float ig = sigmoidf_(g[tid]);
        float fg = sigmoidf_(g[DD + tid]);
        float gg = tanhf(g[2 * DD + tid]);
        float og = sigmoidf_(g[3 * DD + tid]);
        float cn = fg * g_cc[b * DD + tid] + ig * gg;
        float hn = og * tanhf(cn);
        g_cc[b * DD + tid] = cn;
        g_hh[b * DD + tid] = hn;
        qnew[tid] = hn;
        g_qstar[b * 2 * DD + tid] = hn;
    }
    __syncthreads();

    int s0 = g_seg[b], s1 = g_seg[b + 1];

    float lmax = -3.4e38f;
    for (int n = s0 + tid; n < s1; n += 256) {
        const float4* xr = (const float4*)(g_x + (size_t)n * DD);
        const float4* qr = (const float4*)qnew;
        float acc = 0.f;
#pragma unroll
        for (int i = 0; i < DD / 4; i++) {
            float4 a = xr[i], q = qr[i];
            acc += a.x * q.x + a.y * q.y + a.z * q.z + a.w * q.w;
        }
        g_e[n] = acc;
        lmax = fmaxf(lmax, acc);
    }
#pragma unroll
    for (int o = 16; o > 0; o >>= 1) lmax = fmaxf(lmax, __shfl_xor_sync(0xffffffffu, lmax, o));
    if (lane == 0) red[wrp] = lmax;
    __syncthreads();
    float emax = fmaxf(fmaxf(fmaxf(red[0], red[1]), fmaxf(red[2], red[3])),
                       fmaxf(fmaxf(red[4], red[5]), fmaxf(red[6], red[7])));
    __syncthreads();

    float lsum = 0.f;
    for (int n = s0 + tid; n < s1; n += 256) {
        float a = expf(g_e[n] - emax);
        g_a[n] = a;
        lsum += a;
    }
#pragma unroll
    for (int o = 16; o > 0; o >>= 1) lsum += __shfl_xor_sync(0xffffffffu, lsum, o);
    if (lane == 0) red[wrp] = lsum;
    __syncthreads();
    float asum = red[0] + red[1] + red[2] + red[3] + red[4] + red[5] + red[6] + red[7];
    __syncthreads();

    int rowg = tid >> 4, o4 = tid & 15;
    float4 racc = make_float4(0.f, 0.f, 0.f, 0.f);
    for (int n = s0 + rowg; n < s1; n += 16) {
        float c = g_a[n] / asum;
        float4 v = ((const float4*)(g_x + (size_t)n * DD))[o4];
        racc.x = fmaf(c, v.x, racc.x);
        racc.y = fmaf(c, v.y, racc.y);
        racc.z = fmaf(c, v.z, racc.z);
        racc.w = fmaf(c, v.w, racc.w);
    }
    *(float4*)(&rpart[rowg][o4 * 4]) = racc;
    __syncthreads();
    if (tid < DD) {
        float s = 0.f;
#pragma unroll
        for (int r = 0; r < 16; r++) s += rpart[r][tid];
        g_qstar[b * 2 * DD + DD + tid] = s;
    }
}

__global__ void out_kernel(float* __restrict__ out) {
    int i = blockIdx.x * blockDim.x + threadIdx.x;
    if (i < BB * 2 * DD) out[i] = g_qstar[i];
}

// ---------------- launch --------------------------------------------------
extern "C" void kernel_launch(void* const* d_in, const int* in_sizes, int n_in,
                              void* d_out, int out_size) {
    const float* x       = (const float*)d_in[0];
    const int*   ei      = (const int*)  d_in[1];
    const float* ea      = (const float*)d_in[2];
    const int*   batch   = (const int*)  d_in[3];
    const float* lin0_w  = (const float*)d_in[4];
    const float* lin0_b  = (const float*)d_in[5];
    const float* mlp_w1  = (const float*)d_in[6];
    const float* mlp_b1  = (const float*)d_in[7];
    const float* mlp_w2  = (const float*)d_in[8];
    const float* mlp_b2  = (const float*)d_in[9];
    const float* conv_b  = (const float*)d_in[10];
    const float* gw_ih   = (const float*)d_in[11];
    const float* gw_hh   = (const float*)d_in[12];
    const float* gb_ih   = (const float*)d_in[13];
    const float* gb_hh   = (const float*)d_in[14];
    const float* lw_ih   = (const float*)d_in[15];
    const float* lw_hh   = (const float*)d_in[16];
    const float* lb_ih   = (const float*)d_in[17];
    const float* lb_hh   = (const float*)d_in[18];
    float* out = (float*)d_out;

    cudaFuncSetAttribute(gemm_we, cudaFuncAttributeMaxDynamicSharedMemorySize, SM_GEMM_TOTAL);
    cudaFuncSetAttribute(gemm_gates, cudaFuncAttributeMaxDynamicSharedMemorySize, SG_TOTAL);

    const int T = 256;
    lin0_kernel<<<dim3(1, (NN + 63) / 64), T>>>(x, lin0_w, lin0_b);
    setup_kernel<<<(NN * DD + T - 1) / T, T>>>(gw_ih, gw_hh, batch);
    mlp1_kernel<<<(EPAD * 128 + T - 1) / T, T>>>(ea, mlp_w1, mlp_b1);
    w2prep_kernel<<<(WE_COLS * 128 + T - 1) / T, T>>>(mlp_w2);
    gemm_we<<<dim3(WE_COLS / 128, EPAD / 128), 128, SM_GEMM_TOTAL>>>(mlp_b2);
    deg_kernel<<<(EE + T - 1) / T, T>>>(ei);

    for (int itr = 0; itr < 3; itr++) {
        msg_kernel<<<(EE + 7) / 8, 256>>>(ei);
        m_kernel<<<(NN * DD + T - 1) / T, T>>>(conv_b);
        gemm_gates<<<dim3(GDIM / 64, MPAD / 256, 2), 256, SG_TOTAL>>>(gb_ih, gb_hh);
        gru_elem_kernel<<<(NN * DD + T - 1) / T, T>>>();
    }

    s2s_init_kernel<<<(BB * 2 * DD + T - 1) / T, T>>>();
    for (int s = 0; s < 3; s++)
        s2s_step<<<BB, LG>>>(lw_ih, lw_hh, lb_ih, lb_hh);
    out_kernel<<<(BB * 2 * DD + T - 1) / T, T>>>(out);
}

// round 14
// speedup vs baseline: 5.2393x; 1.0085x over previous
#include <cuda_runtime.h>
#include <cuda_bf16.h>
#include <math.h>
#include <stdint.h>

// Problem dims
#define NN   20000
#define EE   50000
#define EPAD 50048          // 391 * 128
#define MPAD 20224          // 79 * 256
#define FIN  16
#define DD   64
#define BB   128
#define GDIM 192
#define LG   256
#define WE_COLS 4096

// ---------------- device scratch ----------------
__device__ float         g_x[NN * DD];
__device__ __nv_bfloat16 g_xhi[MPAD * DD];
__device__ __nv_bfloat16 g_xlo[MPAD * DD];
__device__ __nv_bfloat16 g_mhi[MPAD * DD];
__device__ __nv_bfloat16 g_mlo[MPAD * DD];
__device__ __nv_bfloat16 g_wih_hi[GDIM * DD];
__device__ __nv_bfloat16 g_wih_lo[GDIM * DD];
__device__ __nv_bfloat16 g_whh_hi[GDIM * DD];
__device__ __nv_bfloat16 g_whh_lo[GDIM * DD];
__device__ __nv_bfloat16 g_Ahi[(size_t)EPAD * 128];
__device__ __nv_bfloat16 g_Bhi[WE_COLS * 128];
__device__ __nv_bfloat16 g_We[(size_t)EPAD * WE_COLS];   // 410 MB bf16
__device__ float         g_agg[NN * DD];
__device__ float         g_gi[NN * GDIM];
__device__ float         g_gh[NN * GDIM];
__device__ float         g_deg[NN];
__device__ float         g_e[NN];
__device__ float         g_a[NN];
__device__ int           g_seg[BB + 1];
__device__ float         g_hh[BB * DD];
__device__ float         g_cc[BB * DD];
__device__ float         g_qstar[BB * 2 * DD];

__device__ __forceinline__ float sigmoidf_(float x) { return 1.0f / (1.0f + expf(-x)); }

__device__ __forceinline__ uint32_t smem_u32(const void* p) {
    uint32_t a;
    asm("{ .reg .u64 t; cvta.to.shared.u64 t, %1; cvt.u32.u64 %0, t; }" : "=r"(a) : "l"(p));
    return a;
}

__device__ __forceinline__ void mma16816(float* c, const uint32_t* a, const uint32_t* b) {
    asm volatile(
        "mma.sync.aligned.m16n8k16.row.col.f32.bf16.bf16.f32 "
        "{%0,%1,%2,%3}, {%4,%5,%6,%7}, {%8,%9}, {%0,%1,%2,%3};\n"
        : "+f"(c[0]), "+f"(c[1]), "+f"(c[2]), "+f"(c[3])
        : "r"(a[0]), "r"(a[1]), "r"(a[2]), "r"(a[3]), "r"(b[0]), "r"(b[1]));
}

__device__ __forceinline__ void ldsm4(uint32_t* r, uint32_t addr) {
    asm volatile("ldmatrix.sync.aligned.m8n8.x4.shared.b16 {%0,%1,%2,%3}, [%4];"
                 : "=r"(r[0]), "=r"(r[1]), "=r"(r[2]), "=r"(r[3]) : "r"(addr));
}

__device__ __forceinline__ void cpasync16(uint32_t saddr, const void* gaddr) {
    asm volatile("cp.async.cg.shared.global [%0], [%1], 16;" :: "r"(saddr), "l"(gaddr));
}

__device__ __forceinline__ uint4 ldcs16(const void* p) {
    uint4 v;
    asm volatile("ld.global.cs.v4.u32 {%0,%1,%2,%3}, [%4];"
                 : "=r"(v.x), "=r"(v.y), "=r"(v.z), "=r"(v.w) : "l"(p));
    return v;
}

// ---------------- W_e GEMM (single-pass bf16) ------------------------------
// CTA tile 128x128, 4 warps, warp grid 2x2, warp tile 64x64. 3 CTAs/SM.
#define SSTRIDE 136
#define SM_A_O 0
#define SM_B_O (128 * SSTRIDE * 2)
#define SM_GEMM_TOTAL (SM_B_O + 128 * SSTRIDE * 2)   // 69632

__global__ void __launch_bounds__(128, 3)
gemm_we(const float* __restrict__ b2) {
    extern __shared__ char smem[];
    const int tid = threadIdx.x;
    const int n0 = blockIdx.x * 128;
    const int m0 = blockIdx.y * 128;
    const uint32_t sb = smem_u32(smem);

    for (int idx = tid; idx < 128 * 16; idx += 128) {
        int r = idx >> 4, p = idx & 15;
        uint32_t so = (uint32_t)(r * SSTRIDE + p * 8) * 2;
        cpasync16(sb + SM_A_O + so, g_Ahi + (size_t)(m0 + r) * 128 + p * 8);
        cpasync16(sb + SM_B_O + so, g_Bhi + (size_t)(n0 + r) * 128 + p * 8);
    }
    asm volatile("cp.async.commit_group;");
    asm volatile("cp.async.wait_group 0;");
    __syncthreads();

    const int wid = tid >> 5, lane = tid & 31;
    const int warp_m = wid & 1, warp_n = wid >> 1;   // 2 x 2 warp grid
    const int g = lane >> 2, t4 = lane & 3;

    int arow = (warp_m * 64 + (lane & 15)) * SSTRIDE + ((lane >> 4) << 3);
    int brow = (warp_n * 64 + (lane & 7) + ((lane >> 4) << 3)) * SSTRIDE + (((lane >> 3) & 1) << 3);

    float acc[4][8][4];
#pragma unroll
    for (int mt = 0; mt < 4; mt++)
#pragma unroll
        for (int nt = 0; nt < 8; nt++)
#pragma unroll
            for (int q = 0; q < 4; q++) acc[mt][nt][q] = 0.f;

#pragma unroll
    for (int ks = 0; ks < 8; ks++) {
        const int k0 = ks * 16;
        uint32_t af[4][4];
#pragma unroll
        for (int mt = 0; mt < 4; mt++)
            ldsm4(af[mt], sb + SM_A_O + (arow + mt * 16 * SSTRIDE + k0) * 2);
#pragma unroll
        for (int np = 0; np < 4; np++) {
            uint32_t bf[4];
            ldsm4(bf, sb + SM_B_O + (brow + np * 16 * SSTRIDE + k0) * 2);
#pragma unroll
            for (int h = 0; h < 2; h++) {
                int nt = np * 2 + h;
#pragma unroll
                for (int mt = 0; mt < 4; mt++)
                    mma16816(acc[mt][nt], af[mt], bf + h * 2);
            }
        }
    }

    __syncthreads();
    __nv_bfloat16* cs = (__nv_bfloat16*)smem;
#pragma unroll
    for (int mt = 0; mt < 4; mt++) {
        int r0 = warp_m * 64 + mt * 16 + g;
#pragma unroll
        for (int nt = 0; nt < 8; nt++) {
            int c = warp_n * 64 + nt * 8 + t4 * 2;
            float2 bb = *(const float2*)(b2 + n0 + c);
            *(__nv_bfloat162*)(cs + r0 * SSTRIDE + c) =
                __floats2bfloat162_rn(acc[mt][nt][0] + bb.x, acc[mt][nt][1] + bb.y);
            *(__nv_bfloat162*)(cs + (r0 + 8) * SSTRIDE + c) =
                __floats2bfloat162_rn(acc[mt][nt][2] + bb.x, acc[mt][nt][3] + bb.y);
        }
    }
    __syncthreads();
    for (int idx = tid; idx < 128 * 16; idx += 128) {
        int r = idx >> 4, ch = idx & 15;
        *(uint4*)(g_We + (size_t)(m0 + r) * WE_COLS + n0 + ch * 8) =
            *(const uint4*)(cs + r * SSTRIDE + ch * 8);
    }
}

// ---------------- GRU gate GEMM (both gates in one launch, z selects) ------
#define GSTRIDE 72
#define SG_AHI 0
#define SG_ALO (256 * GSTRIDE * 2)
#define SG_BHI (2 * 256 * GSTRIDE * 2)
#define SG_BLO (SG_BHI + 64 * GSTRIDE * 2)
#define SG_TOTAL (SG_BLO + 64 * GSTRIDE * 2)         // 92160

__global__ void __launch_bounds__(256, 2)
gemm_gates(const float* __restrict__ gb_ih, const float* __restrict__ gb_hh) {
    extern __shared__ char smem[];
    const int tid = threadIdx.x;
    const int n0 = blockIdx.x * 64;
    const int m0 = blockIdx.y * 256;
    const int z = blockIdx.z;
    const uint32_t sb = smem_u32(smem);

    const __nv_bfloat16* Ahi = z ? g_xhi : g_mhi;
    const __nv_bfloat16* Alo = z ? g_xlo : g_mlo;
    const __nv_bfloat16* Bhi = z ? g_whh_hi : g_wih_hi;
    const __nv_bfloat16* Blo = z ? g_whh_lo : g_wih_lo;
    const float* bias = z ? gb_hh : gb_ih;
    float* C = z ? g_gh : g_gi;

    for (int idx = tid; idx < 256 * 8; idx += 256) {
        int r = idx >> 3, p = idx & 7;
        uint32_t so = (uint32_t)(r * GSTRIDE + p * 8) * 2;
        cpasync16(sb + SG_AHI + so, Ahi + (size_t)(m0 + r) * 64 + p * 8);
        cpasync16(sb + SG_ALO + so, Alo + (size_t)(m0 + r) * 64 + p * 8);
    }
    for (int idx = tid; idx < 64 * 8; idx += 256) {
        int r = idx >> 3, p = idx & 7;
        uint32_t so = (uint32_t)(r * GSTRIDE + p * 8) * 2;
        cpasync16(sb + SG_BHI + so, Bhi + (size_t)(n0 + r) * 64 + p * 8);
        cpasync16(sb + SG_BLO + so, Blo + (size_t)(n0 + r) * 64 + p * 8);
    }
    asm volatile("cp.async.commit_group;");
    asm volatile("cp.async.wait_group 0;");
    __syncthreads();

    const int wid = tid >> 5, lane = tid & 31;
    const int warp_m = wid & 3, warp_n = wid >> 2;
    const int g = lane >> 2, t4 = lane & 3;

    int arow = (warp_m * 64 + (lane & 15)) * GSTRIDE + ((lane >> 4) << 3);
    int brow = (warp_n * 32 + (lane & 7) + ((lane >> 4) << 3)) * GSTRIDE + (((lane >> 3) & 1) << 3);

    float acc[4][4][4];
#pragma unroll
    for (int mt = 0; mt < 4; mt++)
#pragma unroll
        for (int nt = 0; nt < 4; nt++)
#pragma unroll
            for (int q = 0; q < 4; q++) acc[mt][nt][q] = 0.f;

#pragma unroll
    for (int ks = 0; ks < 4; ks++) {
        const int k0 = ks * 16;
        uint32_t ahi[4][4], alo[4][4];
#pragma unroll
        for (int mt = 0; mt < 4; mt++) {
            ldsm4(ahi[mt], sb + SG_AHI + (arow + mt * 16 * GSTRIDE + k0) * 2);
            ldsm4(alo[mt], sb + SG_ALO + (arow + mt * 16 * GSTRIDE + k0) * 2);
        }
#pragma unroll
        for (int np = 0; np < 2; np++) {
            uint32_t bhi[4], blo[4];
            ldsm4(bhi, sb + SG_BHI + (brow + np * 16 * GSTRIDE + k0) * 2);
            ldsm4(blo, sb + SG_BLO + (brow + np * 16 * GSTRIDE + k0) * 2);
#pragma unroll
            for (int h = 0; h < 2; h++) {
                int nt = np * 2 + h;
#pragma unroll
                for (int mt = 0; mt < 4; mt++) {
                    mma16816(acc[mt][nt], ahi[mt], bhi + h * 2);
                    mma16816(acc[mt][nt], ahi[mt], blo + h * 2);
                    mma16816(acc[mt][nt], alo[mt], bhi + h * 2);
                }
            }
        }
    }

#pragma unroll
    for (int mt = 0; mt < 4; mt++) {
        int r0 = m0 + warp_m * 64 + mt * 16 + g;
#pragma unroll
        for (int nt = 0; nt < 4; nt++) {
            int n = n0 + warp_n * 32 + nt * 8 + t4 * 2;
            float2 bb = *(const float2*)(bias + n);
            if (r0 < NN)
                *(float2*)(C + (size_t)r0 * GDIM + n) =
                    make_float2(acc[mt][nt][0] + bb.x, acc[mt][nt][1] + bb.y);
            if (r0 + 8 < NN)
                *(float2*)(C + (size_t)(r0 + 8) * GDIM + n) =
                    make_float2(acc[mt][nt][2] + bb.x, acc[mt][nt][3] + bb.y);
        }
    }
}

// ---------------- lin0 GEMM (SIMT, fused relu + bf16 hi/lo conversion) -----
__global__ void lin0_kernel(const float* __restrict__ A, const float* __restrict__ B,
                            const float* __restrict__ bias) {
    __shared__ float As[16][65];
    __shared__ float Bs[16][65];
    int tid = threadIdx.x;
    int tx = tid & 15, ty = tid >> 4;
    int rowBase = blockIdx.y * 64;
    float acc[4][4] = {};
    for (int k0 = 0; k0 < FIN; k0 += 16) {
#pragma unroll
        for (int i = 0; i < 4; i++) {
            int e = tid + i * 256;
            int m = e >> 4, kk = e & 15;
            int r = rowBase + m, k = k0 + kk;
            As[kk][m] = (r < NN && k < FIN) ? A[(size_t)r * FIN + k] : 0.f;
        }
#pragma unroll
        for (int i = 0; i < 4; i++) {
            int e = tid + i * 256;
            int n = e >> 4, kk = e & 15;
            int k = k0 + kk;
            Bs[kk][n] = (k < FIN) ? B[(size_t)n * FIN + k] : 0.f;
        }
        __syncthreads();
#pragma unroll
        for (int kk = 0; kk < 16; kk++) {
            float ra[4], rb[4];
#pragma unroll
            for (int i = 0; i < 4; i++) ra[i] = As[kk][ty * 4 + i];
#pragma unroll
            for (int j = 0; j < 4; j++) rb[j] = Bs[kk][tx * 4 + j];
#pragma unroll
            for (int i = 0; i < 4; i++)
#pragma unroll
                for (int j = 0; j < 4; j++) acc[i][j] += ra[i] * rb[j];
        }
        __syncthreads();
    }
#pragma unroll
    for (int i = 0; i < 4; i++) {
        int r = rowBase + ty * 4 + i;
        if (r >= NN) continue;
#pragma unroll
        for (int j = 0; j < 4; j++) {
            int c = tx * 4 + j;
            float v = fmaxf(acc[i][j] + bias[c], 0.f);
            int idx = r * DD + c;
            g_x[idx] = v;
            __nv_bfloat16 hi = __float2bfloat16(v);
            g_xhi[idx] = hi;
            g_xlo[idx] = __float2bfloat16(v - __bfloat162float(hi));
        }
    }
}

// ---------------- setup: agg zero, bf16 padding, GRU weight split, deg, seg
__global__ void setup_kernel(const float* __restrict__ wih, const float* __restrict__ whh,
                             const int* __restrict__ batch) {
    int i = blockIdx.x * blockDim.x + threadIdx.x;
    if (i < NN * DD) g_agg[i] = 0.f;
    if (i < (MPAD - NN) * DD) {
        int o = NN * DD + i;
        __nv_bfloat16 z = __float2bfloat16(0.f);
        g_mhi[o] = z; g_mlo[o] = z; g_xhi[o] = z; g_xlo[o] = z;
    }
    if (i < GDIM * DD) {
        float a = wih[i];
        __nv_bfloat16 ah = __float2bfloat16(a);
        g_wih_hi[i] = ah;
        g_wih_lo[i] = __float2bfloat16(a - __bfloat162float(ah));
        float b = whh[i];
        __nv_bfloat16 bh = __float2bfloat16(b);
        g_whh_hi[i] = bh;
        g_whh_lo[i] = __float2bfloat16(b - __bfloat162float(bh));
    }
    if (i < NN) g_deg[i] = 0.f;
    if (i <= BB) {
        int lo = 0, hi = NN;
        while (lo < hi) {
            int mid = (lo + hi) >> 1;
            if (batch[mid] < i) lo = mid + 1; else hi = mid;
        }
        g_seg[i] = lo;
    }
}

__global__ void mlp1_kernel(const float* __restrict__ ea, const float* __restrict__ w1,
                            const float* __restrict__ b1) {
    int idx = blockIdx.x * blockDim.x + threadIdx.x;
    if (idx >= EPAD * 128) return;
    int e = idx >> 7, h = idx & 127;
    float acc = 0.f;
    if (e < EE) {
        acc = b1[h];
        const float* row = ea + e * 5;
        const float* w = w1 + h * 5;
#pragma unroll
        for (int k = 0; k < 5; k++) acc += row[k] * w[k];
        acc = fmaxf(acc, 0.f);
    }
    g_Ahi[idx] = __float2bfloat16(acc);
}

__global__ void w2prep_kernel(const float* __restrict__ w2) {
    int idx = blockIdx.x * blockDim.x + threadIdx.x;
    if (idx >= WE_COLS * 128) return;
    g_Bhi[idx] = __float2bfloat16(w2[idx]);
}

__global__ void deg_kernel(const int* __restrict__ ei) {
    int e = blockIdx.x * blockDim.x + threadIdx.x;
    if (e >= EE) return;
    atomicAdd(&g_deg[ei[EE + e]], 1.0f);
}

// 8 edges per 256-thread block; one warp per edge; dual-row streaming loads.
__global__ void __launch_bounds__(256)
msg_kernel(const int* __restrict__ ei) {
    __shared__ float xs[8][64];
    int w = threadIdx.x >> 5, lane = threadIdx.x & 31;
    int e = blockIdx.x * 8 + w;
    if (e >= EE) return;
    int src = ei[e];
    int dst = ei[EE + e];
    xs[w][lane] = g_x[src * DD + lane];
    xs[w][lane + 32] = g_x[src * DD + 32 + lane];
    __syncwarp();
    int oc = lane & 7, h = lane >> 3;
    const __nv_bfloat16* wp = g_We + (size_t)e * WE_COLS;
    float acc[8] = {0.f, 0.f, 0.f, 0.f, 0.f, 0.f, 0.f, 0.f};
#pragma unroll
    for (int s = 0; s < 8; s++) {
        int d0 = s * 4 + h;
        int d1 = d0 + 32;
        uint4 v0 = ldcs16(wp + d0 * 64 + oc * 8);
        uint4 v1 = ldcs16(wp + d1 * 64 + oc * 8);
        float xd0 = xs[w][d0], xd1 = xs[w][d1];
        float2 a0 = __bfloat1622float2(*(__nv_bfloat162*)&v0.x);
        float2 a1 = __bfloat1622float2(*(__nv_bfloat162*)&v0.y);
        float2 a2 = __bfloat1622float2(*(__nv_bfloat162*)&v0.z);
        float2 a3 = __bfloat1622float2(*(__nv_bfloat162*)&v0.w);
        float2 b0 = __bfloat1622float2(*(__nv_bfloat162*)&v1.x);
        float2 b1 = __bfloat1622float2(*(__nv_bfloat162*)&v1.y);
        float2 b2 = __bfloat1622float2(*(__nv_bfloat162*)&v1.z);
        float2 b3 = __bfloat1622float2(*(__nv_bfloat162*)&v1.w);
        acc[0] = fmaf(xd0, a0.x, fmaf(xd1, b0.x, acc[0]));
        acc[1] = fmaf(xd0, a0.y, fmaf(xd1, b0.y, acc[1]));
        acc[2] = fmaf(xd0, a1.x, fmaf(xd1, b1.x, acc[2]));
        acc[3] = fmaf(xd0, a1.y, fmaf(xd1, b1.y, acc[3]));
        acc[4] = fmaf(xd0, a2.x, fmaf(xd1, b2.x, acc[4]));
        acc[5] = fmaf(xd0, a2.y, fmaf(xd1, b2.y, acc[5]));
        acc[6] = fmaf(xd0, a3.x, fmaf(xd1, b3.x, acc[6]));
        acc[7] = fmaf(xd0, a3.y, fmaf(xd1, b3.y, acc[7]));
    }
#pragma unroll
    for (int i = 0; i < 8; i++) {
        acc[i] += __shfl_xor_sync(0xffffffffu, acc[i], 8);
        acc[i] += __shfl_xor_sync(0xffffffffu, acc[i], 16);
    }
    if (lane < 8) {
        float* rp = g_agg + (size_t)dst * DD + lane * 8;
#pragma unroll
        for (int i = 0; i < 8; i++) atomicAdd(rp + i, acc[i]);
    }
}

// m = relu(agg/deg + conv_b) -> bf16 hi/lo; reset agg for next iteration.
__global__ void m_kernel(const float* __restrict__ conv_b) {
    int idx = blockIdx.x * blockDim.x + threadIdx.x;
    if (idx >= NN * DD) return;
    int n = idx >> 6, d = idx & 63;
    float dv = fmaxf(g_deg[n], 1.0f);
    float m = fmaxf(g_agg[idx] / dv + conv_b[d], 0.f);
    g_agg[idx] = 0.f;
    __nv_bfloat16 hi = __float2bfloat16(m);
    g_mhi[idx] = hi;
    g_mlo[idx] = __float2bfloat16(m - __bfloat162float(hi));
}

__global__ void gru_elem_kernel() {
    int idx = blockIdx.x * blockDim.x + threadIdx.x;
    if (idx >= NN * DD) return;
    int n = idx >> 6, j = idx & 63;
    const float* gi = g_gi + (size_t)n * GDIM;
    const float* gh = g_gh + (size_t)n * GDIM;
    float r = sigmoidf_(gi[j] + gh[j]);
    float z = sigmoidf_(gi[64 + j] + gh[64 + j]);
    float nn = tanhf(gi[128 + j] + r * gh[128 + j]);
    float h = g_x[idx];
    float hnew = (1.f - z) * nn + z * h;
    g_x[idx] = hnew;
    __nv_bfloat16 hi = __float2bfloat16(hnew);
    g_xhi[idx] = hi;
    g_xlo[idx] = __float2bfloat16(hnew - __bfloat162float(hi));
}

__global__ void s2s_init_kernel() {
    int i = blockIdx.x * blockDim.x + threadIdx.x;
    if (i < BB * 2 * DD) g_qstar[i] = 0.f;
    if (i < BB * DD) { g_hh[i] = 0.f; g_cc[i] = 0.f; }
}

// One fused Set2Set step: LSTM cell + segmented softmax attention per graph.
__global__ void __launch_bounds__(256)
s2s_step(const float* __restrict__ w_ih, const float* __restrict__ w_hh,
         const float* __restrict__ b_ih, const float* __restrict__ b_hh) {
    int b = blockIdx.x, tid = threadIdx.x;
    int lane = tid & 31, wrp = tid >> 5;
    __shared__ float qs[2 * DD];
    __shared__ float hsold[DD];
    __shared__ float g[LG];
    __shared__ float qnew[DD];
    __shared__ float red[8];
    __shared__ float rpart[16][DD];

    if (tid < 2 * DD) qs[tid] = g_qstar[b * 2 * DD + tid];
    else if (tid < 2 * DD + DD) hsold[tid - 2 * DD] = g_hh[b * DD + (tid - 2 * DD)];
    __syncthreads();

    {
        float acc = b_ih[tid] + b_hh[tid];
        const float* wi = w_ih + tid * 2 * DD;
#pragma unroll 8
        for (int k = 0; k < 2 * DD; k++) acc += qs[k] * wi[k];
        const float* wh = w_hh + tid * DD;
#pragma unroll 8
        for (int k = 0; k < DD; k++) acc += hsold[k] * wh[k];
        g[tid] = acc;
    }
    __syncthreads();
    if (tid < DD) {
        float ig = sigmoidf_(g[tid]);
        float fg = sigmoidf_(g[DD + tid]);
        float gg = tanhf(g[2 * DD + tid]);
        float og = sigmoidf_(g[3 * DD + tid]);
        float cn = fg * g_cc[b * DD + tid] + ig * gg;
        float hn = og * tanhf(cn);
        g_cc[b * DD + tid] = cn;
        g_hh[b * DD + tid] = hn;
        qnew[tid] = hn;
        g_qstar[b * 2 * DD + tid] = hn;
    }
    __syncthreads();

    int s0 = g_seg[b], s1 = g_seg[b + 1];

    float lmax = -3.4e38f;
    for (int n = s0 + tid; n < s1; n += 256) {
        const float4* xr = (const float4*)(g_x + (size_t)n * DD);
        const float4* qr = (const float4*)qnew;
        float acc = 0.f;
#pragma unroll
        for (int i = 0; i < DD / 4; i++) {
            float4 a = xr[i], q = qr[i];
            acc += a.x * q.x + a.y * q.y + a.z * q.z + a.w * q.w;
        }
        g_e[n] = acc;
        lmax = fmaxf(lmax, acc);
    }
#pragma unroll
    for (int o = 16; o > 0; o >>= 1) lmax = fmaxf(lmax, __shfl_xor_sync(0xffffffffu, lmax, o));
    if (lane == 0) red[wrp] = lmax;
    __syncthreads();
    float emax = fmaxf(fmaxf(fmaxf(red[0], red[1]), fmaxf(red[2], red[3])),
                       fmaxf(fmaxf(red[4], red[5]), fmaxf(red[6], red[7])));
    __syncthreads();

    float lsum = 0.f;
    for (int n = s0 + tid; n < s1; n += 256) {
        float a = expf(g_e[n] - emax);
        g_a[n] = a;
        lsum += a;
    }
#pragma unroll
    for (int o = 16; o > 0; o >>= 1) lsum += __shfl_xor_sync(0xffffffffu, lsum, o);
    if (lane == 0) red[wrp] = lsum;
    __syncthreads();
    float asum = red[0] + red[1] + red[2] + red[3] + red[4] + red[5] + red[6] + red[7];
    __syncthreads();

    int rowg = tid >> 4, o4 = tid & 15;
    float4 racc = make_float4(0.f, 0.f, 0.f, 0.f);
    for (int n = s0 + rowg; n < s1; n += 16) {
        float c = g_a[n] / asum;
        float4 v = ((const float4*)(g_x + (size_t)n * DD))[o4];
        racc.x = fmaf(c, v.x, racc.x);
        racc.y = fmaf(c, v.y, racc.y);
        racc.z = fmaf(c, v.z, racc.z);
        racc.w = fmaf(c, v.w, racc.w);
    }
    *(float4*)(&rpart[rowg][o4 * 4]) = racc;
    __syncthreads();
    if (tid < DD) {
        float s = 0.f;
#pragma unroll
        for (int r = 0; r < 16; r++) s += rpart[r][tid];
        g_qstar[b * 2 * DD + DD + tid] = s;
    }
}

__global__ void out_kernel(float* __restrict__ out) {
    int i = blockIdx.x * blockDim.x + threadIdx.x;
    if (i < BB * 2 * DD) out[i] = g_qstar[i];
}

// ---------------- launch --------------------------------------------------
extern "C" void kernel_launch(void* const* d_in, const int* in_sizes, int n_in,
                              void* d_out, int out_size) {
    const float* x       = (const float*)d_in[0];
    const int*   ei      = (const int*)  d_in[1];
    const float* ea      = (const float*)d_in[2];
    const int*   batch   = (const int*)  d_in[3];
    const float* lin0_w  = (const float*)d_in[4];
    const float* lin0_b  = (const float*)d_in[5];
    const float* mlp_w1  = (const float*)d_in[6];
    const float* mlp_b1  = (const float*)d_in[7];
    const float* mlp_w2  = (const float*)d_in[8];
    const float* mlp_b2  = (const float*)d_in[9];
    const float* conv_b  = (const float*)d_in[10];
    const float* gw_ih   = (const float*)d_in[11];
    const float* gw_hh   = (const float*)d_in[12];
    const float* gb_ih   = (const float*)d_in[13];
    const float* gb_hh   = (const float*)d_in[14];
    const float* lw_ih   = (const float*)d_in[15];
    const float* lw_hh   = (const float*)d_in[16];
    const float* lb_ih   = (const float*)d_in[17];
    const float* lb_hh   = (const float*)d_in[18];
    float* out = (float*)d_out;

    cudaFuncSetAttribute(gemm_we, cudaFuncAttributeMaxDynamicSharedMemorySize, SM_GEMM_TOTAL);
    cudaFuncSetAttribute(gemm_gates, cudaFuncAttributeMaxDynamicSharedMemorySize, SG_TOTAL);

    const int T = 256;
    lin0_kernel<<<dim3(1, (NN + 63) / 64), T>>>(x, lin0_w, lin0_b);
    setup_kernel<<<(NN * DD + T - 1) / T, T>>>(gw_ih, gw_hh, batch);
    mlp1_kernel<<<(EPAD * 128 + T - 1) / T, T>>>(ea, mlp_w1, mlp_b1);
    w2prep_kernel<<<(WE_COLS * 128 + T - 1) / T, T>>>(mlp_w2);
    gemm_we<<<dim3(WE_COLS / 128, EPAD / 128), 128, SM_GEMM_TOTAL>>>(mlp_b2);
    deg_kernel<<<(EE + T - 1) / T, T>>>(ei);

    for (int itr = 0; itr < 3; itr++) {
        msg_kernel<<<(EE + 7) / 8, 256>>>(ei);
        m_kernel<<<(NN * DD + T - 1) / T, T>>>(conv_b);
        gemm_gates<<<dim3(GDIM / 64, MPAD / 256, 2), 256, SG_TOTAL>>>(gb_ih, gb_hh);
        gru_elem_kernel<<<(NN * DD + T - 1) / T, T>>>();
    }

    s2s_init_kernel<<<(BB * 2 * DD + T - 1) / T, T>>>();
    for (int s = 0; s < 3; s++)
        s2s_step<<<BB, LG>>>(lw_ih, lw_hh, lb_ih, lb_hh);
    out_kernel<<<(BB * 2 * DD + T - 1) / T, T>>>(out);
}